// round 9
// baseline (speedup 1.0000x reference)
#include <cuda_runtime.h>
#include <cuda_bf16.h>
#include <math.h>
#include <cstdint>

#define NNODE 40000
#define EEDGE 640000
#define DD    128
#define HHID  256
#define LNEPS 1e-5f

// ==================== device scratch (allocation-free) ====================
__device__ __align__(128) float g_A[(size_t)NNODE * HHID];   // sender_x @ ew1[0:128]
__device__ __align__(128) float g_B[(size_t)NNODE * HHID];   // receiver_x @ ew1[128:256] + eb1
__device__ __align__(128) float g_R[(size_t)NNODE * HHID];   // receiver_x @ nw1[0:128] + nb1
__device__ __align__(128) float g_agg[(size_t)NNODE * DD];   // scatter-sum of edge messages
__device__ int   g_cnt[NNODE];
__device__ int   g_is64;
// pre-swizzled bf16 hi/lo weight tile images: 4 chunks of [64 n][128 k] each
__device__ __align__(16) __nv_bfloat16 g_w1h[4 * 64 * 128];
__device__ __align__(16) __nv_bfloat16 g_w1l[4 * 64 * 128];
__device__ __align__(16) __nv_bfloat16 g_w2h[4 * 64 * 128];
__device__ __align__(16) __nv_bfloat16 g_w2l[4 * 64 * 128];

// ==================== helpers ====================
__device__ __forceinline__ uint32_t smem_to_u32(const void* p) {
    uint32_t a;
    asm("{ .reg .u64 t; cvta.to.shared.u64 t, %1; cvt.u32.u64 %0, t; }" : "=r"(a) : "l"(p));
    return a;
}
__device__ __forceinline__ int eidx(const void* ei, long long pos) {
    return g_is64 ? (int)((const long long*)ei)[pos] : ((const int*)ei)[pos];
}
__device__ __forceinline__ float siluf(float x) { return x * (1.0f / (1.0f + expf(-x))); }
__device__ __forceinline__ void split2(float v, unsigned short& h, unsigned short& l) {
    __nv_bfloat16 hb = __float2bfloat16(v);
    __nv_bfloat16 lb = __float2bfloat16(v - __bfloat162float(hb));
    h = __bfloat16_as_ushort(hb);
    l = __bfloat16_as_ushort(lb);
}

#define LDSM_X4(r, ad) \
    asm volatile("ldmatrix.sync.aligned.m8n8.x4.shared.b16 {%0,%1,%2,%3}, [%4];" \
        : "=r"((r)[0]), "=r"((r)[1]), "=r"((r)[2]), "=r"((r)[3]) : "r"(ad))
#define MMA_BF16(d, a, b) \
    asm volatile("mma.sync.aligned.m16n8k16.row.col.f32.bf16.bf16.f32 " \
        "{%0,%1,%2,%3}, {%4,%5,%6,%7}, {%8,%9}, {%0,%1,%2,%3};" \
        : "+f"((d)[0]), "+f"((d)[1]), "+f"((d)[2]), "+f"((d)[3]) \
        : "r"((a)[0]), "r"((a)[1]), "r"((a)[2]), "r"((a)[3]), "r"((b)[0]), "r"((b)[1]))

__device__ __forceinline__ void bulk_reduce_add_f32(float* gdst, uint32_t ssrc, uint32_t bytes) {
    asm volatile("cp.reduce.async.bulk.global.shared::cta.bulk_group.add.f32 [%0], [%1], %2;"
                 :: "l"(gdst), "r"(ssrc), "r"(bytes) : "memory");
}
#define FENCE_ASYNC() asm volatile("fence.proxy.async.shared::cta;" ::: "memory")
#define CP_ASYNC16(sdst, gsrc) \
    asm volatile("cp.async.cg.shared.global [%0], [%1], 16;" :: "r"(sdst), "l"(gsrc) : "memory")
#define CP_COMMIT() asm volatile("cp.async.commit_group;" ::: "memory")
#define CP_WAIT0()  asm volatile("cp.async.wait_group 0;" ::: "memory")

// swizzled tile: rows of 256B (128 bf16); 16B-chunk c at row r lives at (c ^ (r&7))
__device__ __forceinline__ uint32_t sw_off(int r, int chunk) {
    return (uint32_t)(r * 256 + ((chunk ^ (r & 7)) << 4));
}

// ==================== init ====================
__global__ void k_init(const void* __restrict__ ei) {
    int i = blockIdx.x * 256 + threadIdx.x;
    if (i == 0) {
        const long long* p = (const long long*)ei;
        int ok = 1;
        #pragma unroll
        for (int j = 0; j < 32; j++) {
            long long v = p[j];
            if (v < 0 || v >= NNODE) ok = 0;
        }
        g_is64 = ok;
    }
    g_agg[i] = 0.0f;
    if (i < NNODE) g_cnt[i] = 0;
}

// ==================== prep: weight swizzle (4x 64-row chunks) + degree count ====================
__global__ void k_prepcount(const float* __restrict__ ew1, const float* __restrict__ ew2,
                            const void* __restrict__ ei) {
    int i = blockIdx.x * 256 + threadIdx.x;
    int d = eidx(ei, (long long)EEDGE + i);
    atomicAdd(&g_cnt[d], 1);
    if (i < 32768) {
        // W1e^T: n in 0..255 (chunk = n>>6), k in 0..127; source ew1[(256+k)*256+n]
        {
            int n = i >> 7, k = i & 127;
            float v = ew1[(size_t)(256 + k) * HHID + n];
            unsigned short h, l; split2(v, h, l);
            int chunk = n >> 6, r = n & 63;
            uint32_t off = (uint32_t)chunk * 16384 + sw_off(r, k >> 3) + (k & 7) * 2;
            *(unsigned short*)((char*)g_w1h + off) = h;
            *(unsigned short*)((char*)g_w1l + off) = l;
        }
        // W2e^T: n in 0..127, k in 0..255; chunk = (n>>6)*2 + (k>>7); source ew2[k*128+n]
        {
            int n = i & 127, k = i >> 7;
            float v = ew2[(size_t)k * DD + n];
            unsigned short h, l; split2(v, h, l);
            int chunk = (n >> 6) * 2 + (k >> 7);
            int r = n & 63, ck = k & 127;
            uint32_t off = (uint32_t)chunk * 16384 + sw_off(r, ck >> 3) + (ck & 7) * 2;
            *(unsigned short*)((char*)g_w2h + off) = h;
            *(unsigned short*)((char*)g_w2l + off) = l;
        }
    }
}

// ==================== FFMA pregemm ====================
#define FMA44(A_, xv, wv)                                                              \
    A_[0][0] += xv.x * wv.x; A_[0][1] += xv.x * wv.y; A_[0][2] += xv.x * wv.z; A_[0][3] += xv.x * wv.w; \
    A_[1][0] += xv.y * wv.x; A_[1][1] += xv.y * wv.y; A_[1][2] += xv.y * wv.z; A_[1][3] += xv.y * wv.w; \
    A_[2][0] += xv.z * wv.x; A_[2][1] += xv.z * wv.y; A_[2][2] += xv.z * wv.z; A_[2][3] += xv.z * wv.w; \
    A_[3][0] += xv.w * wv.x; A_[3][1] += xv.w * wv.y; A_[3][2] += xv.w * wv.z; A_[3][3] += xv.w * wv.w;

#define FMAROW(yy, hx)                                                  \
    yy[0] += hx * w0.x; yy[1] += hx * w0.y; yy[2] += hx * w0.z; yy[3] += hx * w0.w; \
    yy[4] += hx * w1v.x; yy[5] += hx * w1v.y; yy[6] += hx * w1v.z; yy[7] += hx * w1v.w;

__device__ __forceinline__ void pregemm_body(
    const float* __restrict__ X, const float* __restrict__ W,
    const float* __restrict__ bias, float* __restrict__ O,
    float* sm, int tid, int row0, int h0)
{
    float* Xs = sm;
    float* Ws = sm + 128 * 68;
    for (int idx = tid; idx < 64 * 32; idx += 256) {
        int r = idx >> 5, k4 = idx & 31;
        float4 v = *(const float4*)&X[(size_t)(row0 + r) * 128 + k4 * 4];
        Xs[(k4 * 4 + 0) * 68 + r] = v.x;
        Xs[(k4 * 4 + 1) * 68 + r] = v.y;
        Xs[(k4 * 4 + 2) * 68 + r] = v.z;
        Xs[(k4 * 4 + 3) * 68 + r] = v.w;
    }
    for (int idx = tid; idx < 128 * 16; idx += 256) {
        int k = idx >> 4, c4 = idx & 15;
        *(float4*)&Ws[k * 68 + c4 * 4] = *(const float4*)&W[(size_t)k * HHID + h0 + c4 * 4];
    }
    __syncthreads();

    int tx = tid & 15, ty = tid >> 4;
    float acc[4][4] = {};
    #pragma unroll 4
    for (int k = 0; k < 128; k++) {
        float4 xv = *(const float4*)&Xs[k * 68 + ty * 4];
        float4 wv = *(const float4*)&Ws[k * 68 + tx * 4];
        FMA44(acc, xv, wv)
    }
    #pragma unroll
    for (int i = 0; i < 4; i++) {
        float4 o = make_float4(acc[i][0], acc[i][1], acc[i][2], acc[i][3]);
        if (bias) {
            o.x += bias[h0 + tx * 4 + 0];
            o.y += bias[h0 + tx * 4 + 1];
            o.z += bias[h0 + tx * 4 + 2];
            o.w += bias[h0 + tx * 4 + 3];
        }
        *(float4*)&O[(size_t)(row0 + ty * 4 + i) * HHID + h0 + tx * 4] = o;
    }
}

__global__ __launch_bounds__(256) void k_pregemmAB(
    const float* __restrict__ sx, const float* __restrict__ rx,
    const float* __restrict__ ew1, const float* __restrict__ eb1)
{
    extern __shared__ float sm[];
    if (blockIdx.z == 0)
        pregemm_body(sx, ew1, nullptr, g_A, sm, threadIdx.x, blockIdx.x * 64, blockIdx.y * 64);
    else
        pregemm_body(rx, ew1 + 128 * HHID, eb1, g_B, sm, threadIdx.x, blockIdx.x * 64, blockIdx.y * 64);
}

__global__ __launch_bounds__(256) void k_pregemmR(
    const float* __restrict__ rx, const float* __restrict__ nw1, const float* __restrict__ nb1)
{
    extern __shared__ float sm[];
    pregemm_body(rx, nw1, nb1, g_R, sm, threadIdx.x, blockIdx.x * 64, blockIdx.y * 64);
}

// ==================== FFMA fused node/sender (K=128 both) ====================
template <int MODE>   // 1: node (agg @ nw1[128:256] + g_R), 2: sender
__global__ __launch_bounds__(256) void k_fused(
    const float* __restrict__ Xin,
    const float* __restrict__ w1, const float* __restrict__ b1,
    const float* __restrict__ w2, const float* __restrict__ b2,
    const float* __restrict__ gam, const float* __restrict__ bet,
    float* __restrict__ out)
{
    extern __shared__ float sm[];
    float* Xs = sm;
    float* Ws = Xs + 128 * 68;
    float* Hs = Ws + 128 * 68;
    float* rc = Hs + 64 * 68;

    int tid = threadIdx.x;
    int row0 = blockIdx.x * 64;

    if (MODE == 2) {
        for (int idx = tid; idx < 64 * 32; idx += 256) {
            int r = idx >> 5, k4 = idx & 31;
            float4 v = *(const float4*)&Xin[(size_t)(row0 + r) * 128 + k4 * 4];
            Xs[(k4 * 4 + 0) * 68 + r] = v.x;
            Xs[(k4 * 4 + 1) * 68 + r] = v.y;
            Xs[(k4 * 4 + 2) * 68 + r] = v.z;
            Xs[(k4 * 4 + 3) * 68 + r] = v.w;
        }
    } else {
        if (tid < 64) {
            int c = g_cnt[row0 + tid];
            rc[tid] = 1.0f / (float)(c > 1 ? c : 1);
        }
        __syncthreads();
        for (int idx = tid; idx < 64 * 32; idx += 256) {
            int r = idx >> 5, k4 = idx & 31;
            float s = rc[r];
            float4 v = *(const float4*)&g_agg[(size_t)(row0 + r) * 128 + k4 * 4];
            Xs[(k4 * 4 + 0) * 68 + r] = v.x * s;
            Xs[(k4 * 4 + 1) * 68 + r] = v.y * s;
            Xs[(k4 * 4 + 2) * 68 + r] = v.z * s;
            Xs[(k4 * 4 + 3) * 68 + r] = v.w * s;
        }
    }
    __syncthreads();

    int tx = tid & 15, ty = tid >> 4;
    float y[4][8] = {};

    #pragma unroll 1
    for (int hc = 0; hc < 4; hc++) {
        int h0 = hc * 64;
        for (int idx = tid; idx < 128 * 16; idx += 256) {
            int k = idx >> 4, c4 = idx & 15;
            *(float4*)&Ws[k * 68 + c4 * 4] = *(const float4*)&w1[(size_t)k * HHID + h0 + c4 * 4];
        }
        __syncthreads();

        float h[4][4] = {};
        #pragma unroll 4
        for (int k = 0; k < 128; k++) {
            float4 xv = *(const float4*)&Xs[k * 68 + ty * 4];
            float4 wv = *(const float4*)&Ws[k * 68 + tx * 4];
            FMA44(h, xv, wv)
        }

        if (MODE == 1) {
            #pragma unroll
            for (int i = 0; i < 4; i++) {
                float4 av = *(const float4*)&g_R[(size_t)(row0 + ty * 4 + i) * HHID + h0 + tx * 4];
                h[i][0] += av.x; h[i][1] += av.y; h[i][2] += av.z; h[i][3] += av.w;
            }
        } else {
            float4 bv = *(const float4*)&b1[h0 + tx * 4];
            #pragma unroll
            for (int i = 0; i < 4; i++) {
                h[i][0] += bv.x; h[i][1] += bv.y; h[i][2] += bv.z; h[i][3] += bv.w;
            }
        }

        #pragma unroll
        for (int j = 0; j < 4; j++) {
            float4 hv;
            hv.x = siluf(h[0][j]);
            hv.y = siluf(h[1][j]);
            hv.z = siluf(h[2][j]);
            hv.w = siluf(h[3][j]);
            *(float4*)&Hs[(tx * 4 + j) * 68 + ty * 4] = hv;
        }
        __syncthreads();

        for (int idx = tid; idx < 64 * 32; idx += 256) {
            int k = idx >> 5, c4 = idx & 31;
            *(float4*)&Ws[k * 132 + c4 * 4] = *(const float4*)&w2[(size_t)(h0 + k) * 128 + c4 * 4];
        }
        __syncthreads();

        #pragma unroll 2
        for (int k = 0; k < 64; k++) {
            float4 hv = *(const float4*)&Hs[k * 68 + ty * 4];
            float4 w0 = *(const float4*)&Ws[k * 132 + tx * 8];
            float4 w1v = *(const float4*)&Ws[k * 132 + tx * 8 + 4];
            FMAROW(y[0], hv.x)
            FMAROW(y[1], hv.y)
            FMAROW(y[2], hv.z)
            FMAROW(y[3], hv.w)
        }
        __syncthreads();
    }

    float b2r[8], gr[8], br[8];
    #pragma unroll
    for (int c = 0; c < 8; c++) {
        b2r[c] = b2[tx * 8 + c];
        gr[c] = gam[tx * 8 + c];
        br[c] = bet[tx * 8 + c];
    }
    #pragma unroll
    for (int i = 0; i < 4; i++) {
        #pragma unroll
        for (int c = 0; c < 8; c++) y[i][c] += b2r[c];

        float s1 = 0.f, s2 = 0.f;
        #pragma unroll
        for (int c = 0; c < 8; c++) { float v = y[i][c]; s1 += v; s2 += v * v; }
        #pragma unroll
        for (int m = 8; m >= 1; m >>= 1) {
            s1 += __shfl_xor_sync(0xffffffffu, s1, m);
            s2 += __shfl_xor_sync(0xffffffffu, s2, m);
        }
        float mu = s1 * (1.0f / 128.0f);
        float rs = rsqrtf(s2 * (1.0f / 128.0f) - mu * mu + LNEPS);

        int r = ty * 4 + i;
        float o[8];
        if (MODE == 1) {
            float4 x0 = *(const float4*)&Xin[(size_t)(row0 + r) * 128 + tx * 8];
            float4 x1 = *(const float4*)&Xin[(size_t)(row0 + r) * 128 + tx * 8 + 4];
            float xr[8] = {x0.x, x0.y, x0.z, x0.w, x1.x, x1.y, x1.z, x1.w};
            #pragma unroll
            for (int c = 0; c < 8; c++)
                o[c] = (y[i][c] - mu) * rs * gr[c] + br[c] + xr[c];
        } else {
            #pragma unroll
            for (int c = 0; c < 8; c++)
                o[c] = (y[i][c] - mu) * rs * gr[c] + br[c] + Xs[(tx * 8 + c) * 68 + r];
        }
        size_t gout = (size_t)(row0 + r) * 128 + tx * 8;
        *(float4*)&out[gout]     = make_float4(o[0], o[1], o[2], o[3]);
        *(float4*)&out[gout + 4] = make_float4(o[4], o[5], o[6], o[7]);
    }
}

// ==================== HMMA edge kernel: 64-edge tiles, 256 thr, 2 CTAs/SM ====================
#define LOSEP      16384
#define OFF_SIDX   0
#define OFF_DIDX   256
#define OFF_P1     512
#define OFF_P2     1536
#define OFF_A_HI   3072     // A hi 16KB, A lo at +LOSEP; becomes H k-chunk1 after G1; then MSG
#define OFF_H0     35840    // H k-chunk0 hi 16KB, lo at +LOSEP
#define OFF_W      68608    // W chunk hi 16KB, lo at +LOSEP
#define OFF_MSG    OFF_A_HI // 32KB, reuses A region after G2c? no: after all GEMMs? A holds H1 until G2 kc=1 done
#define SM_EDGE    101376

// async-stage one 64-row W chunk (16KB hi + 16KB lo)
__device__ __forceinline__ void stage_w(uint32_t sb, const __nv_bfloat16* gh,
                                        const __nv_bfloat16* gl, int tid) {
    const char* ph = (const char*)gh;
    const char* pl = (const char*)gl;
    #pragma unroll
    for (int j = 0; j < 4; j++) {
        int i = tid + j * 256;
        CP_ASYNC16(sb + OFF_W + i * 16, ph + i * 16);
        CP_ASYNC16(sb + OFF_W + LOSEP + i * 16, pl + i * 16);
    }
    CP_COMMIT();
}

// one GEMM phase: dd += Tile(baseA rows 0..63) @ Wchunk^T (64 n-rows), 3-pass hi/lo, pipelined
__device__ __forceinline__ void gemm_phase(uint32_t sb, int lane, int wm, int wn,
                                           uint32_t baseA, float (&dd)[2][2][4]) {
    uint32_t bh[2][2][2], bl[2][2][2];   // [buf][nt][frag]
    uint32_t ah[2][2][4], al[2][2][4];   // [buf][mt][frag]

    const int gq = lane >> 3;
    const int rowq = wn * 16 + ((gq >> 1) << 3) + (lane & 7);    // B rows (both nt)
    const int rra0 = wm * 32 + (lane & 15);                      // A rows, mt=0
    const int rra1 = rra0 + 16;                                  // mt=1
    const int bksel = gq & 1;
    const int aksel = lane >> 4;

    #define LD_B(buf, ksv)                                                                 \
    {                                                                                      \
        int chq = 2 * (ksv) + bksel;                                                       \
        uint32_t adq = sb + OFF_W + sw_off(rowq, chq);                                     \
        uint32_t r4[4];                                                                    \
        LDSM_X4(r4, adq);                                                                  \
        bh[buf][0][0] = r4[0]; bh[buf][0][1] = r4[1]; bh[buf][1][0] = r4[2]; bh[buf][1][1] = r4[3]; \
        LDSM_X4(r4, adq + LOSEP);                                                          \
        bl[buf][0][0] = r4[0]; bl[buf][0][1] = r4[1]; bl[buf][1][0] = r4[2]; bl[buf][1][1] = r4[3]; \
    }
    #define LD_A(buf, ksv)                                                                 \
    {                                                                                      \
        int ch = 2 * (ksv) + aksel;                                                        \
        uint32_t ad = sb + baseA + sw_off(rra0, ch);                                       \
        LDSM_X4(ah[buf][0], ad);                                                           \
        LDSM_X4(al[buf][0], ad + LOSEP);                                                   \
        ad = sb + baseA + sw_off(rra1, ch);                                                \
        LDSM_X4(ah[buf][1], ad);                                                           \
        LDSM_X4(al[buf][1], ad + LOSEP);                                                   \
    }

    LD_B(0, 0)
    LD_A(0, 0)
    #pragma unroll
    for (int ks = 0; ks < 8; ks++) {
        const int cur = ks & 1, nxt = cur ^ 1;
        if (ks < 7) {
            LD_B(nxt, ks + 1)
            LD_A(nxt, ks + 1)
        }
        #pragma unroll
        for (int nt = 0; nt < 2; nt++) {
            MMA_BF16(dd[0][nt], ah[cur][0], bh[cur][nt]);
            MMA_BF16(dd[1][nt], ah[cur][1], bh[cur][nt]);
        }
        #pragma unroll
        for (int nt = 0; nt < 2; nt++) {
            MMA_BF16(dd[0][nt], ah[cur][0], bl[cur][nt]);
            MMA_BF16(dd[1][nt], ah[cur][1], bl[cur][nt]);
        }
        #pragma unroll
        for (int nt = 0; nt < 2; nt++) {
            MMA_BF16(dd[0][nt], al[cur][0], bh[cur][nt]);
            MMA_BF16(dd[1][nt], al[cur][1], bh[cur][nt]);
        }
    }
    #undef LD_B
    #undef LD_A
}

__global__ __launch_bounds__(256, 2) void k_edge(
    const float* __restrict__ edge_attr, const void* __restrict__ ei,
    const float* __restrict__ gA, const float* __restrict__ gB,
    const float* __restrict__ b2, const float* __restrict__ gam, const float* __restrict__ bet,
    float* __restrict__ out_edge, float* __restrict__ agg)
{
    extern __shared__ char smc[];
    const uint32_t sb = smem_to_u32(smc);
    const int tid = threadIdx.x;
    const int lane = tid & 31, wid = tid >> 5;
    const int wm = wid >> 2, wn = wid & 3;           // warp grid 2(m) x 4(n)
    const int row0 = blockIdx.x * 64;

    // stage W1 chunk 0 (hidden under A convert)
    stage_w(sb, g_w1h, g_w1l, tid);

    int* sidx_s = (int*)(smc + OFF_SIDX);
    int* didx_s = (int*)(smc + OFF_DIDX);
    if (tid < 64) {
        sidx_s[tid] = eidx(ei, (long long)(row0 + tid));
        didx_s[tid] = eidx(ei, (long long)EEDGE + row0 + tid);
    }

    // edge_attr -> bf16 hi/lo swizzled A tiles (64 rows)
    for (int idx = tid; idx < 64 * 32; idx += 256) {
        int r = idx >> 5, c4 = idx & 31;
        float4 v = *(const float4*)(edge_attr + (size_t)(row0 + r) * 128 + c4 * 4);
        unsigned short h0, l0, h1, l1, h2, l2, h3, l3;
        split2(v.x, h0, l0); split2(v.y, h1, l1); split2(v.z, h2, l2); split2(v.w, h3, l3);
        uint2 ph, pl;
        ph.x = (uint32_t)h0 | ((uint32_t)h1 << 16); ph.y = (uint32_t)h2 | ((uint32_t)h3 << 16);
        pl.x = (uint32_t)l0 | ((uint32_t)l1 << 16); pl.y = (uint32_t)l2 | ((uint32_t)l3 << 16);
        uint32_t off = sw_off(r, c4 >> 1) + (c4 & 1) * 8;
        *(uint2*)(smc + OFF_A_HI + off) = ph;
        *(uint2*)(smc + OFF_A_HI + LOSEP + off) = pl;
    }
    CP_WAIT0();
    __syncthreads();

    // ---- GEMM1: 4 N-chunks of 64, accumulate D1 in regs ----
    float d1[4][2][2][4];
    #pragma unroll
    for (int cc = 0; cc < 4; cc++)
        #pragma unroll
        for (int a = 0; a < 2; a++)
            #pragma unroll
            for (int b = 0; b < 2; b++)
                #pragma unroll
                for (int q = 0; q < 4; q++) d1[cc][a][b][q] = 0.f;

    #pragma unroll 1
    for (int cc = 0; cc < 4; cc++) {
        gemm_phase(sb, lane, wm, wn, OFF_A_HI, d1[cc]);
        __syncthreads();                                     // W reads done
        if (cc < 3) {
            stage_w(sb, g_w1h + (cc + 1) * 8192, g_w1l + (cc + 1) * 8192, tid);
            CP_WAIT0();
            __syncthreads();
        }
    }
    // stage W2 chunk 0 overlapped with epi1
    stage_w(sb, g_w2h, g_w2l, tid);

    // ---- epi1: D1 + gA[src] + gB[dst], SiLU, split -> H (kc0 -> H0, kc1 -> A region) ----
    #pragma unroll 1
    for (int cc = 0; cc < 4; cc++) {
        #pragma unroll
        for (int mt = 0; mt < 2; mt++) {
            int r1 = wm * 32 + mt * 16 + (lane >> 2);
            int r2 = r1 + 8;
            int si1 = sidx_s[r1], di1 = didx_s[r1];
            int si2 = sidx_s[r2], di2 = didx_s[r2];
            #pragma unroll
            for (int nt = 0; nt < 2; nt++) {
                int cpl = wn * 16 + nt * 8 + 2 * (lane & 3);
                int gc = cc * 64 + cpl;
                float2 a1 = *(const float2*)(gA + (size_t)si1 * HHID + gc);
                float2 bb1 = *(const float2*)(gB + (size_t)di1 * HHID + gc);
                float2 a2 = *(const float2*)(gA + (size_t)si2 * HHID + gc);
                float2 bb2 = *(const float2*)(gB + (size_t)di2 * HHID + gc);
                float h00 = siluf(d1[cc][mt][nt][0] + a1.x + bb1.x);
                float h01 = siluf(d1[cc][mt][nt][1] + a1.y + bb1.y);
                float h10 = siluf(d1[cc][mt][nt][2] + a2.x + bb2.x);
                float h11 = siluf(d1[cc][mt][nt][3] + a2.y + bb2.y);
                unsigned short p0h, p0l, p1h, p1l, q0h, q0l, q1h, q1l;
                split2(h00, p0h, p0l); split2(h01, p1h, p1l);
                split2(h10, q0h, q0l); split2(h11, q1h, q1l);
                uint32_t dst = (gc >> 7) ? OFF_A_HI : OFF_H0;
                int hc = gc & 127;
                uint32_t o1 = sw_off(r1, hc >> 3) + (hc & 7) * 2;
                uint32_t o2 = sw_off(r2, hc >> 3) + (hc & 7) * 2;
                *(uint32_t*)(smc + dst + o1)         = (uint32_t)p0h | ((uint32_t)p1h << 16);
                *(uint32_t*)(smc + dst + LOSEP + o1) = (uint32_t)p0l | ((uint32_t)p1l << 16);
                *(uint32_t*)(smc + dst + o2)         = (uint32_t)q0h | ((uint32_t)q1h << 16);
                *(uint32_t*)(smc + dst + LOSEP + o2) = (uint32_t)q0l | ((uint32_t)q1l << 16);
            }
        }
    }
    CP_WAIT0();
    __syncthreads();

    // ---- GEMM2: 4 phases (nc,kc); D2[nc] accumulates over kc ----
    float d2[2][2][2][4];
    #pragma unroll
    for (int nc = 0; nc < 2; nc++)
        #pragma unroll
        for (int a = 0; a < 2; a++)
            #pragma unroll
            for (int b = 0; b < 2; b++)
                #pragma unroll
                for (int q = 0; q < 4; q++) d2[nc][a][b][q] = 0.f;

    #pragma unroll 1
    for (int p = 0; p < 4; p++) {
        int nc = p >> 1, kc = p & 1;
        gemm_phase(sb, lane, wm, wn, kc ? OFF_A_HI : OFF_H0, d2[nc]);
        __syncthreads();                                     // W reads done
        if (p < 3) {
            stage_w(sb, g_w2h + (p + 1) * 8192, g_w2l + (p + 1) * 8192, tid);
            CP_WAIT0();
            __syncthreads();
        }
    }

    // ---- epi2: +b2, LayerNorm, residual, store + stage messages ----
    float b2v[2][2][2], gmv[2][2][2], btv[2][2][2];
    #pragma unroll
    for (int nc = 0; nc < 2; nc++)
        #pragma unroll
        for (int nt = 0; nt < 2; nt++) {
            int col = nc * 64 + wn * 16 + nt * 8 + 2 * (lane & 3);
            float2 t;
            t = *(const float2*)(b2 + col);  b2v[nc][nt][0] = t.x; b2v[nc][nt][1] = t.y;
            t = *(const float2*)(gam + col); gmv[nc][nt][0] = t.x; gmv[nc][nt][1] = t.y;
            t = *(const float2*)(bet + col); btv[nc][nt][0] = t.x; btv[nc][nt][1] = t.y;
        }
    float* p1 = (float*)(smc + OFF_P1);
    float* p2 = (float*)(smc + OFF_P2);

    #pragma unroll
    for (int mt = 0; mt < 2; mt++) {
        int r1 = wm * 32 + mt * 16 + (lane >> 2);
        int r2 = r1 + 8;
        float s1a = 0.f, s2a = 0.f, s1b = 0.f, s2b = 0.f;
        #pragma unroll
        for (int nc = 0; nc < 2; nc++)
            #pragma unroll
            for (int nt = 0; nt < 2; nt++) {
                float y0 = d2[nc][mt][nt][0] + b2v[nc][nt][0];
                float y1 = d2[nc][mt][nt][1] + b2v[nc][nt][1];
                float y2 = d2[nc][mt][nt][2] + b2v[nc][nt][0];
                float y3 = d2[nc][mt][nt][3] + b2v[nc][nt][1];
                d2[nc][mt][nt][0] = y0; d2[nc][mt][nt][1] = y1;
                d2[nc][mt][nt][2] = y2; d2[nc][mt][nt][3] = y3;
                s1a += y0 + y1; s2a += y0 * y0 + y1 * y1;
                s1b += y2 + y3; s2b += y2 * y2 + y3 * y3;
            }
        #pragma unroll
        for (int m = 1; m <= 2; m <<= 1) {
            s1a += __shfl_xor_sync(0xffffffffu, s1a, m);
            s2a += __shfl_xor_sync(0xffffffffu, s2a, m);
            s1b += __shfl_xor_sync(0xffffffffu, s1b, m);
            s2b += __shfl_xor_sync(0xffffffffu, s2b, m);
        }
        if ((lane & 3) == 0) {
            p1[r1 * 4 + wn] = s1a; p2[r1 * 4 + wn] = s2a;
            p1[r2 * 4 + wn] = s1b; p2[r2 * 4 + wn] = s2b;
        }
    }
    __syncthreads();   // also: all G2 reads of A/H0 regions complete before msg writes

    float* msg = (float*)(smc + OFF_MSG);
    #pragma unroll
    for (int mt = 0; mt < 2; mt++) {
        int r1 = wm * 32 + mt * 16 + (lane >> 2);
        int r2 = r1 + 8;
        float4 q1 = *(float4*)&p1[r1 * 4];
        float4 v1 = *(float4*)&p2[r1 * 4];
        float4 q2 = *(float4*)&p1[r2 * 4];
        float4 v2 = *(float4*)&p2[r2 * 4];
        float mu1 = (q1.x + q1.y + q1.z + q1.w) * (1.0f / 128.0f);
        float mu2 = (q2.x + q2.y + q2.z + q2.w) * (1.0f / 128.0f);
        float rs1 = rsqrtf((v1.x + v1.y + v1.z + v1.w) * (1.0f / 128.0f) - mu1 * mu1 + LNEPS);
        float rs2 = rsqrtf((v2.x + v2.y + v2.z + v2.w) * (1.0f / 128.0f) - mu2 * mu2 + LNEPS);
        #pragma unroll
        for (int nc = 0; nc < 2; nc++)
            #pragma unroll
            for (int nt = 0; nt < 2; nt++) {
                int col = nc * 64 + wn * 16 + nt * 8 + 2 * (lane & 3);
                float pa0 = (d2[nc][mt][nt][0] - mu1) * rs1 * gmv[nc][nt][0] + btv[nc][nt][0];
                float pa1 = (d2[nc][mt][nt][1] - mu1) * rs1 * gmv[nc][nt][1] + btv[nc][nt][1];
                float pb0 = (d2[nc][mt][nt][2] - mu2) * rs2 * gmv[nc][nt][0] + btv[nc][nt][0];
                float pb1 = (d2[nc][mt][nt][3] - mu2) * rs2 * gmv[nc][nt][1] + btv[nc][nt][1];
                float2 x1 = *(const float2*)(edge_attr + (size_t)(row0 + r1) * 128 + col);
                float2 x2 = *(const float2*)(edge_attr + (size_t)(row0 + r2) * 128 + col);
                *(float2*)(out_edge + (size_t)(row0 + r1) * 128 + col) = make_float2(pa0 + x1.x, pa1 + x1.y);
                *(float2*)(out_edge + (size_t)(row0 + r2) * 128 + col) = make_float2(pb0 + x2.x, pb1 + x2.y);
                *(float2*)(msg + r1 * 128 + col) = make_float2(pa0, pa1);
                *(float2*)(msg + r2 * 128 + col) = make_float2(pb0, pb1);
            }
    }
    FENCE_ASYNC();
    __syncthreads();

    // scatter via bulk async reduce (one 512B row per edge)
    if (tid < 64) {
        float* gdst = agg + (size_t)didx_s[tid] * 128;
        bulk_reduce_add_f32(gdst, sb + OFF_MSG + (uint32_t)tid * 512, 512);
        asm volatile("cp.async.bulk.commit_group;" ::: "memory");
        asm volatile("cp.async.bulk.wait_group 0;" ::: "memory");
    }
}

// ==================== launcher ====================
extern "C" void kernel_launch(void* const* d_in, const int* in_sizes, int n_in,
                              void* d_out, int out_size) {
    (void)in_sizes; (void)n_in; (void)out_size;
    const float* sender_x   = (const float*)d_in[0];
    const float* receiver_x = (const float*)d_in[1];
    const float* edge_attr  = (const float*)d_in[2];
    const void*  ei         = d_in[3];
    const float* ew1  = (const float*)d_in[4];
    const float* eb1  = (const float*)d_in[5];
    const float* ew2  = (const float*)d_in[6];
    const float* eb2  = (const float*)d_in[7];
    const float* eg   = (const float*)d_in[8];
    const float* ebt  = (const float*)d_in[9];
    const float* nw1  = (const float*)d_in[10];
    const float* nb1  = (const float*)d_in[11];
    const float* nw2  = (const float*)d_in[12];
    const float* nb2  = (const float*)d_in[13];
    const float* ng   = (const float*)d_in[14];
    const float* nbt  = (const float*)d_in[15];
    const float* sw1  = (const float*)d_in[16];
    const float* sb1  = (const float*)d_in[17];
    const float* sw2  = (const float*)d_in[18];
    const float* sb2  = (const float*)d_in[19];
    const float* sg   = (const float*)d_in[20];
    const float* sbt  = (const float*)d_in[21];

    float* out = (float*)d_out;
    float* out_send = out;
    float* out_recv = out + (size_t)NNODE * DD;
    float* out_edge = out + (size_t)2 * NNODE * DD;

    void *pA, *pB, *pAgg;
    cudaGetSymbolAddress(&pA, g_A);
    cudaGetSymbolAddress(&pB, g_B);
    cudaGetSymbolAddress(&pAgg, g_agg);

    static cudaStream_t s2 = nullptr;
    static cudaEvent_t evS = nullptr, evP = nullptr, evJ = nullptr;
    if (s2 == nullptr) {
        cudaStreamCreateWithFlags(&s2, cudaStreamNonBlocking);
        cudaEventCreateWithFlags(&evS, cudaEventDisableTiming);
        cudaEventCreateWithFlags(&evP, cudaEventDisableTiming);
        cudaEventCreateWithFlags(&evJ, cudaEventDisableTiming);
    }

    const int SM_PRE = (128 * 68 + 128 * 68) * 4;
    const int SM_FU  = (128 * 68 + 128 * 68 + 64 * 68 + 64) * 4;
    cudaFuncSetAttribute(k_pregemmAB, cudaFuncAttributeMaxDynamicSharedMemorySize, SM_PRE);
    cudaFuncSetAttribute(k_pregemmR,  cudaFuncAttributeMaxDynamicSharedMemorySize, SM_PRE);
    cudaFuncSetAttribute(k_fused<1>,  cudaFuncAttributeMaxDynamicSharedMemorySize, SM_FU);
    cudaFuncSetAttribute(k_fused<2>,  cudaFuncAttributeMaxDynamicSharedMemorySize, SM_FU);
    cudaFuncSetAttribute(k_edge,      cudaFuncAttributeMaxDynamicSharedMemorySize, SM_EDGE);

    // fork: pregemmAB on s2, concurrent with init+prepcount on main
    cudaEventRecord(evS, 0);
    cudaStreamWaitEvent(s2, evS, 0);
    k_pregemmAB<<<dim3(NNODE / 64, 4, 2), 256, SM_PRE, s2>>>(sender_x, receiver_x, ew1, eb1);  // launch 1
    k_init<<<(NNODE * DD) / 256, 256>>>(ei);                                                    // launch 2
    k_prepcount<<<EEDGE / 256, 256>>>(ew1, ew2, ei);                                            // launch 3
    cudaEventRecord(evP, s2);
    cudaStreamWaitEvent(0, evP, 0);
    k_edge<<<EEDGE / 64, 256, SM_EDGE>>>(edge_attr, ei, (const float*)pA, (const float*)pB,
                                         eb2, eg, ebt, out_edge, (float*)pAgg);                 // launch 4 (ncu slot)
    // side stream overlaps k_edge: sender MLP + node GEMM1 receiver-half precompute
    k_fused<2><<<NNODE / 64, 256, SM_FU, s2>>>(sender_x, sw1, sb1, sw2, sb2, sg, sbt, out_send);
    k_pregemmR<<<dim3(NNODE / 64, 4), 256, SM_PRE, s2>>>(receiver_x, nw1, nb1);
    cudaEventRecord(evJ, s2);
    cudaStreamWaitEvent(0, evJ, 0);
    // node MLP: only agg-dependent K=128 half on the critical path
    k_fused<1><<<NNODE / 64, 256, SM_FU>>>(receiver_x, nw1 + 128 * HHID, nb1,
                                           nw2, nb2, ng, nbt, out_recv);
}

// round 10
// speedup vs baseline: 1.1034x; 1.1034x over previous
#include <cuda_runtime.h>
#include <cuda_bf16.h>
#include <math.h>
#include <cstdint>

#define NNODE 40000
#define EEDGE 640000
#define DD    128
#define HHID  256
#define LNEPS 1e-5f

// ==================== device scratch (allocation-free) ====================
__device__ __align__(128) float g_A[(size_t)NNODE * HHID];   // sender_x @ ew1[0:128]
__device__ __align__(128) float g_B[(size_t)NNODE * HHID];   // receiver_x @ ew1[128:256] + eb1
__device__ __align__(128) float g_R[(size_t)NNODE * HHID];   // receiver_x @ nw1[0:128] + nb1
__device__ __align__(128) float g_agg[(size_t)NNODE * DD];   // scatter-sum of edge messages
__device__ int   g_cnt[NNODE];
__device__ int   g_is64;
// pre-swizzled bf16 hi/lo weight tile images
__device__ __align__(16) __nv_bfloat16 g_w1h[2 * 128 * 128];  // edge W1^T, 2 chunks [128n][128k]
__device__ __align__(16) __nv_bfloat16 g_w1l[2 * 128 * 128];
__device__ __align__(16) __nv_bfloat16 g_w2h[2 * 128 * 128];  // edge W2^T, 2 chunks [128n][128k]
__device__ __align__(16) __nv_bfloat16 g_w2l[2 * 128 * 128];
__device__ __align__(16) __nv_bfloat16 g_wAh[4 * 64 * 128];   // ew1[0:128]^T, 4 chunks [64n][128k]
__device__ __align__(16) __nv_bfloat16 g_wAl[4 * 64 * 128];
__device__ __align__(16) __nv_bfloat16 g_wBh[4 * 64 * 128];   // ew1[128:256]^T
__device__ __align__(16) __nv_bfloat16 g_wBl[4 * 64 * 128];

// ==================== helpers ====================
__device__ __forceinline__ uint32_t smem_to_u32(const void* p) {
    uint32_t a;
    asm("{ .reg .u64 t; cvta.to.shared.u64 t, %1; cvt.u32.u64 %0, t; }" : "=r"(a) : "l"(p));
    return a;
}
__device__ __forceinline__ int eidx(const void* ei, long long pos) {
    return g_is64 ? (int)((const long long*)ei)[pos] : ((const int*)ei)[pos];
}
__device__ __forceinline__ float siluf(float x) { return x * (1.0f / (1.0f + __expf(-x))); }
__device__ __forceinline__ void split2(float v, unsigned short& h, unsigned short& l) {
    __nv_bfloat16 hb = __float2bfloat16(v);
    __nv_bfloat16 lb = __float2bfloat16(v - __bfloat162float(hb));
    h = __bfloat16_as_ushort(hb);
    l = __bfloat16_as_ushort(lb);
}

#define LDSM_X4(r, ad) \
    asm volatile("ldmatrix.sync.aligned.m8n8.x4.shared.b16 {%0,%1,%2,%3}, [%4];" \
        : "=r"((r)[0]), "=r"((r)[1]), "=r"((r)[2]), "=r"((r)[3]) : "r"(ad))
#define MMA_BF16(d, a, b) \
    asm volatile("mma.sync.aligned.m16n8k16.row.col.f32.bf16.bf16.f32 " \
        "{%0,%1,%2,%3}, {%4,%5,%6,%7}, {%8,%9}, {%0,%1,%2,%3};" \
        : "+f"((d)[0]), "+f"((d)[1]), "+f"((d)[2]), "+f"((d)[3]) \
        : "r"((a)[0]), "r"((a)[1]), "r"((a)[2]), "r"((a)[3]), "r"((b)[0]), "r"((b)[1]))

__device__ __forceinline__ void bulk_reduce_add_f32(float* gdst, uint32_t ssrc, uint32_t bytes) {
    asm volatile("cp.reduce.async.bulk.global.shared::cta.bulk_group.add.f32 [%0], [%1], %2;"
                 :: "l"(gdst), "r"(ssrc), "r"(bytes) : "memory");
}
#define FENCE_ASYNC() asm volatile("fence.proxy.async.shared::cta;" ::: "memory")
#define CP_ASYNC16(sdst, gsrc) \
    asm volatile("cp.async.cg.shared.global [%0], [%1], 16;" :: "r"(sdst), "l"(gsrc) : "memory")
#define CP_COMMIT() asm volatile("cp.async.commit_group;" ::: "memory")
#define CP_WAIT0()  asm volatile("cp.async.wait_group 0;" ::: "memory")

// swizzled tile: rows of 256B (128 bf16); 16B-chunk c at row r lives at (c ^ (r&7))
__device__ __forceinline__ uint32_t sw_off(int r, int chunk) {
    return (uint32_t)(r * 256 + ((chunk ^ (r & 7)) << 4));
}

// ==================== launch 1: weight prep + cnt zero + dtype detect ====================
__global__ void k_prepw(const float* __restrict__ ew1, const float* __restrict__ ew2,
                        const void* __restrict__ ei) {
    int i = blockIdx.x * 256 + threadIdx.x;   // grid 157*256 = 40192
    if (i == 0) {
        const long long* p = (const long long*)ei;
        int ok = 1;
        #pragma unroll
        for (int j = 0; j < 32; j++) {
            long long v = p[j];
            if (v < 0 || v >= NNODE) ok = 0;
        }
        g_is64 = ok;
    }
    if (i < NNODE) g_cnt[i] = 0;
    if (i < 32768) {
        // edge W1^T (2-chunk 128n format): src ew1[(256+k)*256+n]
        {
            int n = i >> 7, k = i & 127;
            float v = ew1[(size_t)(256 + k) * HHID + n];
            unsigned short h, l; split2(v, h, l);
            int chunk = n >> 7, r = n & 127;
            uint32_t off = (uint32_t)chunk * 32768 + sw_off(r, k >> 3) + (k & 7) * 2;
            *(unsigned short*)((char*)g_w1h + off) = h;
            *(unsigned short*)((char*)g_w1l + off) = l;
        }
        // edge W2^T (2-chunk 128n format): src ew2[k*128+n]
        {
            int n = i & 127, k = i >> 7;
            float v = ew2[(size_t)k * DD + n];
            unsigned short h, l; split2(v, h, l);
            int chunk = k >> 7, kk = k & 127;
            uint32_t off = (uint32_t)chunk * 32768 + sw_off(n, kk >> 3) + (kk & 7) * 2;
            *(unsigned short*)((char*)g_w2h + off) = h;
            *(unsigned short*)((char*)g_w2l + off) = l;
        }
        // pregemm wA/wB (4-chunk 64n format): src ew1[k*256+n] and ew1[(128+k)*256+n]
        {
            int n = i >> 7, k = i & 127;
            int chunk = n >> 6, r = n & 63;
            uint32_t off = (uint32_t)chunk * 16384 + sw_off(r, k >> 3) + (k & 7) * 2;
            float vA = ew1[(size_t)k * HHID + n];
            unsigned short h, l; split2(vA, h, l);
            *(unsigned short*)((char*)g_wAh + off) = h;
            *(unsigned short*)((char*)g_wAl + off) = l;
            float vB = ew1[(size_t)(128 + k) * HHID + n];
            split2(vB, h, l);
            *(unsigned short*)((char*)g_wBh + off) = h;
            *(unsigned short*)((char*)g_wBl + off) = l;
        }
    }
}

// ==================== launch 3: zero agg + degree count ====================
__global__ void k_initcount(const void* __restrict__ ei) {
    int i = blockIdx.x * 256 + threadIdx.x;   // grid 20000 -> NNODE*DD
    g_agg[i] = 0.0f;
    if (i < EEDGE) {
        int d = eidx(ei, (long long)EEDGE + i);
        atomicAdd(&g_cnt[d], 1);
    }
}

// ==================== HMMA pregemm (A and B via blockIdx.z) ====================
#define PG_A     0
#define PG_W     32768
#define PG_LOSEP 16384
#define SM_PG    65536

__device__ __forceinline__ void stage_w64(uint32_t sb, const __nv_bfloat16* gh,
                                          const __nv_bfloat16* gl, int tid) {
    const char* ph = (const char*)gh;
    const char* pl = (const char*)gl;
    #pragma unroll
    for (int j = 0; j < 4; j++) {
        int i = tid + j * 256;
        CP_ASYNC16(sb + PG_W + i * 16, ph + i * 16);
        CP_ASYNC16(sb + PG_W + PG_LOSEP + i * 16, pl + i * 16);
    }
    CP_COMMIT();
}

// dd += A(64x128) @ Wchunk^T(64x128), 3-pass hi/lo, pipelined (validated in R9)
__device__ __forceinline__ void gemm64(uint32_t sb, int lane, int wm, int wn,
                                       float (&dd)[2][2][4]) {
    uint32_t bh[2][2][2], bl[2][2][2];
    uint32_t ah[2][2][4], al[2][2][4];

    const int gq = lane >> 3;
    const int rowq = wn * 16 + ((gq >> 1) << 3) + (lane & 7);
    const int rra0 = wm * 32 + (lane & 15);
    const int rra1 = rra0 + 16;
    const int bksel = gq & 1;
    const int aksel = lane >> 4;

    #define LD_B64(buf, ksv)                                                               \
    {                                                                                      \
        int chq = 2 * (ksv) + bksel;                                                       \
        uint32_t adq = sb + PG_W + sw_off(rowq, chq);                                      \
        uint32_t r4[4];                                                                    \
        LDSM_X4(r4, adq);                                                                  \
        bh[buf][0][0] = r4[0]; bh[buf][0][1] = r4[1]; bh[buf][1][0] = r4[2]; bh[buf][1][1] = r4[3]; \
        LDSM_X4(r4, adq + PG_LOSEP);                                                       \
        bl[buf][0][0] = r4[0]; bl[buf][0][1] = r4[1]; bl[buf][1][0] = r4[2]; bl[buf][1][1] = r4[3]; \
    }
    #define LD_A64(buf, ksv)                                                               \
    {                                                                                      \
        int ch = 2 * (ksv) + aksel;                                                        \
        uint32_t ad = sb + PG_A + sw_off(rra0, ch);                                        \
        LDSM_X4(ah[buf][0], ad);                                                           \
        LDSM_X4(al[buf][0], ad + PG_LOSEP);                                                \
        ad = sb + PG_A + sw_off(rra1, ch);                                                 \
        LDSM_X4(ah[buf][1], ad);                                                           \
        LDSM_X4(al[buf][1], ad + PG_LOSEP);                                                \
    }

    LD_B64(0, 0)
    LD_A64(0, 0)
    #pragma unroll
    for (int ks = 0; ks < 8; ks++) {
        const int cur = ks & 1, nxt = cur ^ 1;
        if (ks < 7) {
            LD_B64(nxt, ks + 1)
            LD_A64(nxt, ks + 1)
        }
        #pragma unroll
        for (int nt = 0; nt < 2; nt++) {
            MMA_BF16(dd[0][nt], ah[cur][0], bh[cur][nt]);
            MMA_BF16(dd[1][nt], ah[cur][1], bh[cur][nt]);
        }
        #pragma unroll
        for (int nt = 0; nt < 2; nt++) {
            MMA_BF16(dd[0][nt], ah[cur][0], bl[cur][nt]);
            MMA_BF16(dd[1][nt], ah[cur][1], bl[cur][nt]);
        }
        #pragma unroll
        for (int nt = 0; nt < 2; nt++) {
            MMA_BF16(dd[0][nt], al[cur][0], bh[cur][nt]);
            MMA_BF16(dd[1][nt], al[cur][1], bh[cur][nt]);
        }
    }
    #undef LD_B64
    #undef LD_A64
}

__global__ __launch_bounds__(256, 2) void k_pregemmH(
    const float* __restrict__ sx, const float* __restrict__ rx,
    const float* __restrict__ eb1)
{
    extern __shared__ char smc[];
    const uint32_t sb = smem_to_u32(smc);
    const int tid = threadIdx.x;
    const int lane = tid & 31, wid = tid >> 5;
    const int wm = wid >> 2, wn = wid & 3;           // 2m x 4n
    const int row0 = blockIdx.x * 64;
    const int isB = blockIdx.z;

    const float* X = isB ? rx : sx;
    const __nv_bfloat16* wh = isB ? g_wBh : g_wAh;
    const __nv_bfloat16* wl = isB ? g_wBl : g_wAl;
    float* O = isB ? g_B : g_A;

    stage_w64(sb, wh, wl, tid);

    // X rows -> bf16 hi/lo swizzled tile
    for (int idx = tid; idx < 64 * 32; idx += 256) {
        int r = idx >> 5, c4 = idx & 31;
        float4 v = *(const float4*)(X + (size_t)(row0 + r) * 128 + c4 * 4);
        unsigned short h0, l0, h1, l1, h2, l2, h3, l3;
        split2(v.x, h0, l0); split2(v.y, h1, l1); split2(v.z, h2, l2); split2(v.w, h3, l3);
        uint2 ph, pl;
        ph.x = (uint32_t)h0 | ((uint32_t)h1 << 16); ph.y = (uint32_t)h2 | ((uint32_t)h3 << 16);
        pl.x = (uint32_t)l0 | ((uint32_t)l1 << 16); pl.y = (uint32_t)l2 | ((uint32_t)l3 << 16);
        uint32_t off = sw_off(r, c4 >> 1) + (c4 & 1) * 8;
        *(uint2*)(smc + PG_A + off) = ph;
        *(uint2*)(smc + PG_A + PG_LOSEP + off) = pl;
    }
    CP_WAIT0();
    __syncthreads();

    #pragma unroll 1
    for (int cc = 0; cc < 4; cc++) {
        float dd[2][2][4];
        #pragma unroll
        for (int a = 0; a < 2; a++)
            #pragma unroll
            for (int b = 0; b < 2; b++)
                #pragma unroll
                for (int q = 0; q < 4; q++) dd[a][b][q] = 0.f;

        gemm64(sb, lane, wm, wn, dd);
        __syncthreads();                                 // W reads done
        if (cc < 3) stage_w64(sb, wh + (cc + 1) * 8192, wl + (cc + 1) * 8192, tid);

        // write this 64-col chunk to global (overlaps next W staging)
        #pragma unroll
        for (int mt = 0; mt < 2; mt++) {
            int r1 = wm * 32 + mt * 16 + (lane >> 2);
            int r2 = r1 + 8;
            #pragma unroll
            for (int nt = 0; nt < 2; nt++) {
                int col = wn * 16 + nt * 8 + 2 * (lane & 3);
                int gc = cc * 64 + col;
                float b0 = 0.f, b1 = 0.f;
                if (isB) {
                    float2 bb = *(const float2*)(eb1 + gc);
                    b0 = bb.x; b1 = bb.y;
                }
                *(float2*)(O + (size_t)(row0 + r1) * HHID + gc) =
                    make_float2(dd[mt][nt][0] + b0, dd[mt][nt][1] + b1);
                *(float2*)(O + (size_t)(row0 + r2) * HHID + gc) =
                    make_float2(dd[mt][nt][2] + b0, dd[mt][nt][3] + b1);
            }
        }
        if (cc < 3) {
            CP_WAIT0();
            __syncthreads();
        }
    }
}

// ==================== FFMA pregemmR (node receiver-half, overlapped) ====================
#define FMA44(A_, xv, wv)                                                              \
    A_[0][0] += xv.x * wv.x; A_[0][1] += xv.x * wv.y; A_[0][2] += xv.x * wv.z; A_[0][3] += xv.x * wv.w; \
    A_[1][0] += xv.y * wv.x; A_[1][1] += xv.y * wv.y; A_[1][2] += xv.y * wv.z; A_[1][3] += xv.y * wv.w; \
    A_[2][0] += xv.z * wv.x; A_[2][1] += xv.z * wv.y; A_[2][2] += xv.z * wv.z; A_[2][3] += xv.z * wv.w; \
    A_[3][0] += xv.w * wv.x; A_[3][1] += xv.w * wv.y; A_[3][2] += xv.w * wv.z; A_[3][3] += xv.w * wv.w;

#define FMAROW(yy, hx)                                                  \
    yy[0] += hx * w0.x; yy[1] += hx * w0.y; yy[2] += hx * w0.z; yy[3] += hx * w0.w; \
    yy[4] += hx * w1v.x; yy[5] += hx * w1v.y; yy[6] += hx * w1v.z; yy[7] += hx * w1v.w;

__global__ __launch_bounds__(256) void k_pregemmR(
    const float* __restrict__ rx, const float* __restrict__ nw1, const float* __restrict__ nb1)
{
    extern __shared__ float sm[];
    float* Xs = sm;
    float* Ws = sm + 128 * 68;
    int tid = threadIdx.x;
    int row0 = blockIdx.x * 64;
    int h0 = blockIdx.y * 64;

    for (int idx = tid; idx < 64 * 32; idx += 256) {
        int r = idx >> 5, k4 = idx & 31;
        float4 v = *(const float4*)&rx[(size_t)(row0 + r) * 128 + k4 * 4];
        Xs[(k4 * 4 + 0) * 68 + r] = v.x;
        Xs[(k4 * 4 + 1) * 68 + r] = v.y;
        Xs[(k4 * 4 + 2) * 68 + r] = v.z;
        Xs[(k4 * 4 + 3) * 68 + r] = v.w;
    }
    for (int idx = tid; idx < 128 * 16; idx += 256) {
        int k = idx >> 4, c4 = idx & 15;
        *(float4*)&Ws[k * 68 + c4 * 4] = *(const float4*)&nw1[(size_t)k * HHID + h0 + c4 * 4];
    }
    __syncthreads();

    int tx = tid & 15, ty = tid >> 4;
    float acc[4][4] = {};
    #pragma unroll 4
    for (int k = 0; k < 128; k++) {
        float4 xv = *(const float4*)&Xs[k * 68 + ty * 4];
        float4 wv = *(const float4*)&Ws[k * 68 + tx * 4];
        FMA44(acc, xv, wv)
    }
    #pragma unroll
    for (int i = 0; i < 4; i++) {
        float4 o = make_float4(acc[i][0], acc[i][1], acc[i][2], acc[i][3]);
        o.x += nb1[h0 + tx * 4 + 0];
        o.y += nb1[h0 + tx * 4 + 1];
        o.z += nb1[h0 + tx * 4 + 2];
        o.w += nb1[h0 + tx * 4 + 3];
        *(float4*)&g_R[(size_t)(row0 + ty * 4 + i) * HHID + h0 + tx * 4] = o;
    }
}

// ==================== FFMA fused node/sender (K=128 both) ====================
template <int MODE>   // 1: node (agg @ nw1[128:256] + g_R), 2: sender
__global__ __launch_bounds__(256) void k_fused(
    const float* __restrict__ Xin,
    const float* __restrict__ w1, const float* __restrict__ b1,
    const float* __restrict__ w2, const float* __restrict__ b2,
    const float* __restrict__ gam, const float* __restrict__ bet,
    float* __restrict__ out)
{
    extern __shared__ float sm[];
    float* Xs = sm;
    float* Ws = Xs + 128 * 68;
    float* Hs = Ws + 128 * 68;
    float* rc = Hs + 64 * 68;

    int tid = threadIdx.x;
    int row0 = blockIdx.x * 64;

    if (MODE == 2) {
        for (int idx = tid; idx < 64 * 32; idx += 256) {
            int r = idx >> 5, k4 = idx & 31;
            float4 v = *(const float4*)&Xin[(size_t)(row0 + r) * 128 + k4 * 4];
            Xs[(k4 * 4 + 0) * 68 + r] = v.x;
            Xs[(k4 * 4 + 1) * 68 + r] = v.y;
            Xs[(k4 * 4 + 2) * 68 + r] = v.z;
            Xs[(k4 * 4 + 3) * 68 + r] = v.w;
        }
    } else {
        if (tid < 64) {
            int c = g_cnt[row0 + tid];
            rc[tid] = 1.0f / (float)(c > 1 ? c : 1);
        }
        __syncthreads();
        for (int idx = tid; idx < 64 * 32; idx += 256) {
            int r = idx >> 5, k4 = idx & 31;
            float s = rc[r];
            float4 v = *(const float4*)&g_agg[(size_t)(row0 + r) * 128 + k4 * 4];
            Xs[(k4 * 4 + 0) * 68 + r] = v.x * s;
            Xs[(k4 * 4 + 1) * 68 + r] = v.y * s;
            Xs[(k4 * 4 + 2) * 68 + r] = v.z * s;
            Xs[(k4 * 4 + 3) * 68 + r] = v.w * s;
        }
    }
    __syncthreads();

    int tx = tid & 15, ty = tid >> 4;
    float y[4][8] = {};

    #pragma unroll 1
    for (int hc = 0; hc < 4; hc++) {
        int h0 = hc * 64;
        for (int idx = tid; idx < 128 * 16; idx += 256) {
            int k = idx >> 4, c4 = idx & 15;
            *(float4*)&Ws[k * 68 + c4 * 4] = *(const float4*)&w1[(size_t)k * HHID + h0 + c4 * 4];
        }
        __syncthreads();

        float h[4][4] = {};
        #pragma unroll 4
        for (int k = 0; k < 128; k++) {
            float4 xv = *(const float4*)&Xs[k * 68 + ty * 4];
            float4 wv = *(const float4*)&Ws[k * 68 + tx * 4];
            FMA44(h, xv, wv)
        }

        if (MODE == 1) {
            #pragma unroll
            for (int i = 0; i < 4; i++) {
                float4 av = *(const float4*)&g_R[(size_t)(row0 + ty * 4 + i) * HHID + h0 + tx * 4];
                h[i][0] += av.x; h[i][1] += av.y; h[i][2] += av.z; h[i][3] += av.w;
            }
        } else {
            float4 bv = *(const float4*)&b1[h0 + tx * 4];
            #pragma unroll
            for (int i = 0; i < 4; i++) {
                h[i][0] += bv.x; h[i][1] += bv.y; h[i][2] += bv.z; h[i][3] += bv.w;
            }
        }

        #pragma unroll
        for (int j = 0; j < 4; j++) {
            float4 hv;
            hv.x = siluf(h[0][j]);
            hv.y = siluf(h[1][j]);
            hv.z = siluf(h[2][j]);
            hv.w = siluf(h[3][j]);
            *(float4*)&Hs[(tx * 4 + j) * 68 + ty * 4] = hv;
        }
        __syncthreads();

        for (int idx = tid; idx < 64 * 32; idx += 256) {
            int k = idx >> 5, c4 = idx & 31;
            *(float4*)&Ws[k * 132 + c4 * 4] = *(const float4*)&w2[(size_t)(h0 + k) * 128 + c4 * 4];
        }
        __syncthreads();

        #pragma unroll 2
        for (int k = 0; k < 64; k++) {
            float4 hv = *(const float4*)&Hs[k * 68 + ty * 4];
            float4 w0 = *(const float4*)&Ws[k * 132 + tx * 8];
            float4 w1v = *(const float4*)&Ws[k * 132 + tx * 8 + 4];
            FMAROW(y[0], hv.x)
            FMAROW(y[1], hv.y)
            FMAROW(y[2], hv.z)
            FMAROW(y[3], hv.w)
        }
        __syncthreads();
    }

    float b2r[8], gr[8], br[8];
    #pragma unroll
    for (int c = 0; c < 8; c++) {
        b2r[c] = b2[tx * 8 + c];
        gr[c] = gam[tx * 8 + c];
        br[c] = bet[tx * 8 + c];
    }
    #pragma unroll
    for (int i = 0; i < 4; i++) {
        #pragma unroll
        for (int c = 0; c < 8; c++) y[i][c] += b2r[c];

        float s1 = 0.f, s2 = 0.f;
        #pragma unroll
        for (int c = 0; c < 8; c++) { float v = y[i][c]; s1 += v; s2 += v * v; }
        #pragma unroll
        for (int m = 8; m >= 1; m >>= 1) {
            s1 += __shfl_xor_sync(0xffffffffu, s1, m);
            s2 += __shfl_xor_sync(0xffffffffu, s2, m);
        }
        float mu = s1 * (1.0f / 128.0f);
        float rs = rsqrtf(s2 * (1.0f / 128.0f) - mu * mu + LNEPS);

        int r = ty * 4 + i;
        float o[8];
        if (MODE == 1) {
            float4 x0 = *(const float4*)&Xin[(size_t)(row0 + r) * 128 + tx * 8];
            float4 x1 = *(const float4*)&Xin[(size_t)(row0 + r) * 128 + tx * 8 + 4];
            float xr[8] = {x0.x, x0.y, x0.z, x0.w, x1.x, x1.y, x1.z, x1.w};
            #pragma unroll
            for (int c = 0; c < 8; c++)
                o[c] = (y[i][c] - mu) * rs * gr[c] + br[c] + xr[c];
        } else {
            #pragma unroll
            for (int c = 0; c < 8; c++)
                o[c] = (y[i][c] - mu) * rs * gr[c] + br[c] + Xs[(tx * 8 + c) * 68 + r];
        }
        size_t gout = (size_t)(row0 + r) * 128 + tx * 8;
        *(float4*)&out[gout]     = make_float4(o[0], o[1], o[2], o[3]);
        *(float4*)&out[gout + 4] = make_float4(o[4], o[5], o[6], o[7]);
    }
}

// ==================== HMMA edge kernel (R8, 512 threads, pipelined fragments) ====================
#define OFF_SIDX   0
#define OFF_DIDX   512
#define OFF_P1     1024
#define OFF_P2     3072
#define OFF_A_HI   5120
#define OFF_A_LO   37888
#define OFF_MSG    5120
#define OFF_W_HI   70656
#define OFF_W_LO   103424
#define OFF_H_HI   136192
#define OFF_H_LO   168960
#define SM_EDGE    201728

__device__ __forceinline__ void stage_w(uint32_t sb, const __nv_bfloat16* gh,
                                        const __nv_bfloat16* gl, int tid) {
    const char* ph = (const char*)gh;
    const char* pl = (const char*)gl;
    #pragma unroll
    for (int j = 0; j < 4; j++) {
        int i = tid + j * 512;
        CP_ASYNC16(sb + OFF_W_HI + i * 16, ph + i * 16);
        CP_ASYNC16(sb + OFF_W_LO + i * 16, pl + i * 16);
    }
    CP_COMMIT();
}

__device__ __forceinline__ void gemm_phase(uint32_t sb, int lane, int wm, int wn,
                                           uint32_t baseA, float (&dd)[2][4][4]) {
    uint32_t bh[2][4][2], bl[2][4][2];
    uint32_t ah[2][2][4], al[2][2][4];

    const int gq = lane >> 3;
    const int rowq0 = wn * 32 + ((gq >> 1) << 3) + (lane & 7);
    const int rowq1 = rowq0 + 16;
    const int rra0 = wm * 32 + (lane & 15);
    const int rra1 = rra0 + 16;
    const int bksel = gq & 1;
    const int aksel = lane >> 4;

    #define LD_B(buf, ksv)                                                                 \
    {                                                                                      \
        int chq = 2 * (ksv) + bksel;                                                       \
        uint32_t adq = sb + OFF_W_HI + sw_off(rowq0, chq);                                 \
        uint32_t r4[4];                                                                    \
        LDSM_X4(r4, adq);                                                                  \
        bh[buf][0][0] = r4[0]; bh[buf][0][1] = r4[1]; bh[buf][1][0] = r4[2]; bh[buf][1][1] = r4[3]; \
        LDSM_X4(r4, adq + 32768);                                                          \
        bl[buf][0][0] = r4[0]; bl[buf][0][1] = r4[1]; bl[buf][1][0] = r4[2]; bl[buf][1][1] = r4[3]; \
        adq = sb + OFF_W_HI + sw_off(rowq1, chq);                                          \
        LDSM_X4(r4, adq);                                                                  \
        bh[buf][2][0] = r4[0]; bh[buf][2][1] = r4[1]; bh[buf][3][0] = r4[2]; bh[buf][3][1] = r4[3]; \
        LDSM_X4(r4, adq + 32768);                                                          \
        bl[buf][2][0] = r4[0]; bl[buf][2][1] = r4[1]; bl[buf][3][0] = r4[2]; bl[buf][3][1] = r4[3]; \
    }
    #define LD_A(buf, ksv)                                                                 \
    {                                                                                      \
        int ch = 2 * (ksv) + aksel;                                                        \
        uint32_t ad = sb + baseA + sw_off(rra0, ch);                                       \
        LDSM_X4(ah[buf][0], ad);                                                           \
        LDSM_X4(al[buf][0], ad + 32768);                                                   \
        ad = sb + baseA + sw_off(rra1, ch);                                                \
        LDSM_X4(ah[buf][1], ad);                                                           \
        LDSM_X4(al[buf][1], ad + 32768);                                                   \
    }

    LD_B(0, 0)
    LD_A(0, 0)
    #pragma unroll
    for (int ks = 0; ks < 8; ks++) {
        const int cur = ks & 1, nxt = cur ^ 1;
        if (ks < 7) {
            LD_B(nxt, ks + 1)
            LD_A(nxt, ks + 1)
        }
        #pragma unroll
        for (int nt = 0; nt < 4; nt++) {
            MMA_BF16(dd[0][nt], ah[cur][0], bh[cur][nt]);
            MMA_BF16(dd[1][nt], ah[cur][1], bh[cur][nt]);
        }
        #pragma unroll
        for (int nt = 0; nt < 4; nt++) {
            MMA_BF16(dd[0][nt], ah[cur][0], bl[cur][nt]);
            MMA_BF16(dd[1][nt], ah[cur][1], bl[cur][nt]);
        }
        #pragma unroll
        for (int nt = 0; nt < 4; nt++) {
            MMA_BF16(dd[0][nt], al[cur][0], bh[cur][nt]);
            MMA_BF16(dd[1][nt], al[cur][1], bh[cur][nt]);
        }
    }
    #undef LD_B
    #undef LD_A
}

__device__ __forceinline__ void epi1_phase(char* smc, const int* sidx_s, const int* didx_s,
    const float* gA, const float* gB, float (&d1)[2][4][4],
    int wm, int wn, int lane, int c, uint32_t dstHi)
{
    #pragma unroll
    for (int mt = 0; mt < 2; mt++) {
        int r1 = wm * 32 + mt * 16 + (lane >> 2);
        int r2 = r1 + 8;
        int si1 = sidx_s[r1], di1 = didx_s[r1];
        int si2 = sidx_s[r2], di2 = didx_s[r2];
        #pragma unroll
        for (int nt = 0; nt < 4; nt++) {
            int cpl = wn * 32 + nt * 8 + 2 * (lane & 3);
            int gc = c * 128 + cpl;
            float2 a1 = *(const float2*)(gA + (size_t)si1 * HHID + gc);
            float2 bb1 = *(const float2*)(gB + (size_t)di1 * HHID + gc);
            float2 a2 = *(const float2*)(gA + (size_t)si2 * HHID + gc);
            float2 bb2 = *(const float2*)(gB + (size_t)di2 * HHID + gc);
            float h00 = siluf(d1[mt][nt][0] + a1.x + bb1.x);
            float h01 = siluf(d1[mt][nt][1] + a1.y + bb1.y);
            float h10 = siluf(d1[mt][nt][2] + a2.x + bb2.x);
            float h11 = siluf(d1[mt][nt][3] + a2.y + bb2.y);
            unsigned short p0h, p0l, p1h, p1l, q0h, q0l, q1h, q1l;
            split2(h00, p0h, p0l); split2(h01, p1h, p1l);
            split2(h10, q0h, q0l); split2(h11, q1h, q1l);
            uint32_t o1 = sw_off(r1, (cpl >> 3)) + (cpl & 7) * 2;
            uint32_t o2 = sw_off(r2, (cpl >> 3)) + (cpl & 7) * 2;
            *(uint32_t*)(smc + dstHi + o1)         = (uint32_t)p0h | ((uint32_t)p1h << 16);
            *(uint32_t*)(smc + dstHi + 32768 + o1) = (uint32_t)p0l | ((uint32_t)p1l << 16);
            *(uint32_t*)(smc + dstHi + o2)         = (uint32_t)q0h | ((uint32_t)q1h << 16);
            *(uint32_t*)(smc + dstHi + 32768 + o2) = (uint32_t)q0l | ((uint32_t)q1l << 16);
        }
    }
}

__global__ __launch_bounds__(512, 1) void k_edge(
    const float* __restrict__ edge_attr, const void* __restrict__ ei,
    const float* __restrict__ gA, const float* __restrict__ gB,
    const float* __restrict__ b2, const float* __restrict__ gam, const float* __restrict__ bet,
    float* __restrict__ out_edge, float* __restrict__ agg)
{
    extern __shared__ char smc[];
    const uint32_t sb = smem_to_u32(smc);
    const int tid = threadIdx.x;
    const int lane = tid & 31, wid = tid >> 5;
    const int wm = wid >> 2, wn = wid & 3;
    const int row0 = blockIdx.x * 128;

    stage_w(sb, g_w1h, g_w1l, tid);

    int* sidx_s = (int*)(smc + OFF_SIDX);
    int* didx_s = (int*)(smc + OFF_DIDX);
    if (tid < 128) {
        sidx_s[tid] = eidx(ei, (long long)(row0 + tid));
        didx_s[tid] = eidx(ei, (long long)EEDGE + row0 + tid);
    }

    for (int idx = tid; idx < 128 * 32; idx += 512) {
        int r = idx >> 5, c4 = idx & 31;
        float4 v = *(const float4*)(edge_attr + (size_t)(row0 + r) * 128 + c4 * 4);
        unsigned short h0, l0, h1, l1, h2, l2, h3, l3;
        split2(v.x, h0, l0); split2(v.y, h1, l1); split2(v.z, h2, l2); split2(v.w, h3, l3);
        uint2 ph, pl;
        ph.x = (uint32_t)h0 | ((uint32_t)h1 << 16); ph.y = (uint32_t)h2 | ((uint32_t)h3 << 16);
        pl.x = (uint32_t)l0 | ((uint32_t)l1 << 16); pl.y = (uint32_t)l2 | ((uint32_t)l3 << 16);
        uint32_t off = sw_off(r, c4 >> 1) + (c4 & 1) * 8;
        *(uint2*)(smc + OFF_A_HI + off) = ph;
        *(uint2*)(smc + OFF_A_LO + off) = pl;
    }
    CP_WAIT0();
    __syncthreads();

    float d1[2][4][4];
    #pragma unroll
    for (int a = 0; a < 2; a++)
        #pragma unroll
        for (int b = 0; b < 4; b++)
            #pragma unroll
            for (int q = 0; q < 4; q++) d1[a][b][q] = 0.f;

    gemm_phase(sb, lane, wm, wn, OFF_A_HI, d1);
    __syncthreads();
    stage_w(sb, g_w1h + 16384, g_w1l + 16384, tid);
    epi1_phase(smc, sidx_s, didx_s, gA, gB, d1, wm, wn, lane, 0, OFF_H_HI);
    CP_WAIT0();
    __syncthreads();

    #pragma unroll
    for (int a = 0; a < 2; a++)
        #pragma unroll
        for (int b = 0; b < 4; b++)
            #pragma unroll
            for (int q = 0; q < 4; q++) d1[a][b][q] = 0.f;
    gemm_phase(sb, lane, wm, wn, OFF_A_HI, d1);
    __syncthreads();
    stage_w(sb, g_w2h, g_w2l, tid);
    epi1_phase(smc, sidx_s, didx_s, gA, gB, d1, wm, wn, lane, 1, OFF_A_HI);
    CP_WAIT0();
    __syncthreads();

    float d2[2][4][4];
    #pragma unroll
    for (int a = 0; a < 2; a++)
        #pragma unroll
        for (int b = 0; b < 4; b++)
            #pragma unroll
            for (int q = 0; q < 4; q++) d2[a][b][q] = 0.f;
    gemm_phase(sb, lane, wm, wn, OFF_H_HI, d2);
    __syncthreads();
    stage_w(sb, g_w2h + 16384, g_w2l + 16384, tid);
    CP_WAIT0();
    __syncthreads();

    gemm_phase(sb, lane, wm, wn, OFF_A_HI, d2);

    float b2v[4][2], gmv[4][2], btv[4][2];
    #pragma unroll
    for (int nt = 0; nt < 4; nt++) {
        int col = wn * 32 + nt * 8 + 2 * (lane & 3);
        float2 t;
        t = *(const float2*)(b2 + col);  b2v[nt][0] = t.x; b2v[nt][1] = t.y;
        t = *(const float2*)(gam + col); gmv[nt][0] = t.x; gmv[nt][1] = t.y;
        t = *(const float2*)(bet + col); btv[nt][0] = t.x; btv[nt][1] = t.y;
    }
    float* p1 = (float*)(smc + OFF_P1);
    float* p2 = (float*)(smc + OFF_P2);

    #pragma unroll
    for (int mt = 0; mt < 2; mt++) {
        int r1 = wm * 32 + mt * 16 + (lane >> 2);
        int r2 = r1 + 8;
        float s1a = 0.f, s2a = 0.f, s1b = 0.f, s2b = 0.f;
        #pragma unroll
        for (int nt = 0; nt < 4; nt++) {
            float y0 = d2[mt][nt][0] + b2v[nt][0];
            float y1 = d2[mt][nt][1] + b2v[nt][1];
            float y2 = d2[mt][nt][2] + b2v[nt][0];
            float y3 = d2[mt][nt][3] + b2v[nt][1];
            d2[mt][nt][0] = y0; d2[mt][nt][1] = y1; d2[mt][nt][2] = y2; d2[mt][nt][3] = y3;
            s1a += y0 + y1; s2a += y0 * y0 + y1 * y1;
            s1b += y2 + y3; s2b += y2 * y2 + y3 * y3;
        }
        #pragma unroll
        for (int m = 1; m <= 2; m <<= 1) {
            s1a += __shfl_xor_sync(0xffffffffu, s1a, m);
            s2a += __shfl_xor_sync(0xffffffffu, s2a, m);
            s1b += __shfl_xor_sync(0xffffffffu, s1b, m);
            s2b += __shfl_xor_sync(0xffffffffu, s2b, m);
        }
        if ((lane & 3) == 0) {
            p1[r1 * 4 + wn] = s1a; p2[r1 * 4 + wn] = s2a;
            p1[r2 * 4 + wn] = s1b; p2[r2 * 4 + wn] = s2b;
        }
    }
    __syncthreads();

    float* msg = (float*)(smc + OFF_MSG);
    #pragma unroll
    for (int mt = 0; mt < 2; mt++) {
        int r1 = wm * 32 + mt * 16 + (lane >> 2);
        int r2 = r1 + 8;
        float4 q1 = *(float4*)&p1[r1 * 4];
        float4 v1 = *(float4*)&p2[r1 * 4];
        float4 q2 = *(float4*)&p1[r2 * 4];
        float4 v2 = *(float4*)&p2[r2 * 4];
        float mu1 = (q1.x + q1.y + q1.z + q1.w) * (1.0f / 128.0f);
        float mu2 = (q2.x + q2.y + q2.z + q2.w) * (1.0f / 128.0f);
        float rs1 = rsqrtf((v1.x + v1.y + v1.z + v1.w) * (1.0f / 128.0f) - mu1 * mu1 + LNEPS);
        float rs2 = rsqrtf((v2.x + v2.y + v2.z + v2.w) * (1.0f / 128.0f) - mu2 * mu2 + LNEPS);
        #pragma unroll
        for (int nt = 0; nt < 4; nt++) {
            int col = wn * 32 + nt * 8 + 2 * (lane & 3);
            float pa0 = (d2[mt][nt][0] - mu1) * rs1 * gmv[nt][0] + btv[nt][0];
            float pa1 = (d2[mt][nt][1] - mu1) * rs1 * gmv[nt][1] + btv[nt][1];
            float pb0 = (d2[mt][nt][2] - mu2) * rs2 * gmv[nt][0] + btv[nt][0];
            float pb1 = (d2[mt][nt][3] - mu2) * rs2 * gmv[nt][1] + btv[nt][1];
            float2 x1 = *(const float2*)(edge_attr + (size_t)(row0 + r1) * 128 + col);
            float2 x2 = *(const float2*)(edge_attr + (size_t)(row0 + r2) * 128 + col);
            *(float2*)(out_edge + (size_t)(row0 + r1) * 128 + col) = make_float2(pa0 + x1.x, pa1 + x1.y);
            *(float2*)(out_edge + (size_t)(row0 + r2) * 128 + col) = make_float2(pb0 + x2.x, pb1 + x2.y);
            *(float2*)(msg + r1 * 128 + col) = make_float2(pa0, pa1);
            *(float2*)(msg + r2 * 128 + col) = make_float2(pb0, pb1);
        }
    }
    FENCE_ASYNC();
    __syncthreads();

    if (tid < 128) {
        float* gdst = agg + (size_t)didx_s[tid] * 128;
        bulk_reduce_add_f32(gdst, sb + OFF_MSG + (uint32_t)tid * 512, 512);
        asm volatile("cp.async.bulk.commit_group;" ::: "memory");
        asm volatile("cp.async.bulk.wait_group 0;" ::: "memory");
    }
}

// ==================== launcher ====================
extern "C" void kernel_launch(void* const* d_in, const int* in_sizes, int n_in,
                              void* d_out, int out_size) {
    (void)in_sizes; (void)n_in; (void)out_size;
    const float* sender_x   = (const float*)d_in[0];
    const float* receiver_x = (const float*)d_in[1];
    const float* edge_attr  = (const float*)d_in[2];
    const void*  ei         = d_in[3];
    const float* ew1  = (const float*)d_in[4];
    const float* eb1  = (const float*)d_in[5];
    const float* ew2  = (const float*)d_in[6];
    const float* eb2  = (const float*)d_in[7];
    const float* eg   = (const float*)d_in[8];
    const float* ebt  = (const float*)d_in[9];
    const float* nw1  = (const float*)d_in[10];
    const float* nb1  = (const float*)d_in[11];
    const float* nw2  = (const float*)d_in[12];
    const float* nb2  = (const float*)d_in[13];
    const float* ng   = (const float*)d_in[14];
    const float* nbt  = (const float*)d_in[15];
    const float* sw1  = (const float*)d_in[16];
    const float* sb1  = (const float*)d_in[17];
    const float* sw2  = (const float*)d_in[18];
    const float* sb2  = (const float*)d_in[19];
    const float* sg   = (const float*)d_in[20];
    const float* sbt  = (const float*)d_in[21];

    float* out = (float*)d_out;
    float* out_send = out;
    float* out_recv = out + (size_t)NNODE * DD;
    float* out_edge = out + (size_t)2 * NNODE * DD;

    void *pA, *pB, *pAgg;
    cudaGetSymbolAddress(&pA, g_A);
    cudaGetSymbolAddress(&pB, g_B);
    cudaGetSymbolAddress(&pAgg, g_agg);

    static cudaStream_t s2 = nullptr;
    static cudaEvent_t evS = nullptr, evP = nullptr, evJ = nullptr;
    if (s2 == nullptr) {
        cudaStreamCreateWithFlags(&s2, cudaStreamNonBlocking);
        cudaEventCreateWithFlags(&evS, cudaEventDisableTiming);
        cudaEventCreateWithFlags(&evP, cudaEventDisableTiming);
        cudaEventCreateWithFlags(&evJ, cudaEventDisableTiming);
    }

    const int SM_PRE = (128 * 68 + 128 * 68) * 4;
    const int SM_FU  = (128 * 68 + 128 * 68 + 64 * 68 + 64) * 4;
    cudaFuncSetAttribute(k_pregemmH, cudaFuncAttributeMaxDynamicSharedMemorySize, SM_PG);
    cudaFuncSetAttribute(k_pregemmR, cudaFuncAttributeMaxDynamicSharedMemorySize, SM_PRE);
    cudaFuncSetAttribute(k_fused<1>, cudaFuncAttributeMaxDynamicSharedMemorySize, SM_FU);
    cudaFuncSetAttribute(k_fused<2>, cudaFuncAttributeMaxDynamicSharedMemorySize, SM_FU);
    cudaFuncSetAttribute(k_edge,     cudaFuncAttributeMaxDynamicSharedMemorySize, SM_EDGE);

    // launch 1: weight prep + cnt zero + dtype detect (main)
    k_prepw<<<157, 256>>>(ew1, ew2, ei);
    cudaEventRecord(evS, 0);
    // launch 2: HMMA pregemm A/B on side stream (needs prepped wA/wB)
    cudaStreamWaitEvent(s2, evS, 0);
    k_pregemmH<<<dim3(NNODE / 64, 1, 2), 256, SM_PG, s2>>>(sender_x, receiver_x, eb1);
    // launch 3: zero agg + degree count (main, concurrent with pregemmH)
    k_initcount<<<(NNODE * DD) / 256, 256>>>(ei);
    cudaEventRecord(evP, s2);
    cudaStreamWaitEvent(0, evP, 0);
    // launch 4 (ncu slot): edge kernel
    k_edge<<<EEDGE / 128, 512, SM_EDGE>>>(edge_attr, ei, (const float*)pA, (const float*)pB,
                                          eb2, eg, ebt, out_edge, (float*)pAgg);
    // side stream overlaps edge: sender MLP + node receiver-half precompute
    k_fused<2><<<NNODE / 64, 256, SM_FU, s2>>>(sender_x, sw1, sb1, sw2, sb2, sg, sbt, out_send);
    k_pregemmR<<<dim3(NNODE / 64, 4), 256, SM_PRE, s2>>>(receiver_x, nw1, nb1);
    cudaEventRecord(evJ, s2);
    cudaStreamWaitEvent(0, evJ, 0);
    // node MLP: agg-dependent half only
    k_fused<1><<<NNODE / 64, 256, SM_FU>>>(receiver_x, nw1 + 128 * HHID, nb1,
                                           nw2, nb2, ng, nbt, out_recv);
}

// round 11
// speedup vs baseline: 1.1773x; 1.0669x over previous
#include <cuda_runtime.h>
#include <cuda_bf16.h>
#include <math.h>
#include <cstdint>

#define NNODE 40000
#define EEDGE 640000
#define DD    128
#define HHID  256
#define LNEPS 1e-5f

// ==================== device scratch (allocation-free) ====================
__device__ __align__(128) float g_A[(size_t)NNODE * HHID];   // sender_x @ ew1[0:128]
__device__ __align__(128) float g_B[(size_t)NNODE * HHID];   // receiver_x @ ew1[128:256] + eb1
__device__ __align__(128) float g_R[(size_t)NNODE * HHID];   // receiver_x @ nw1[0:128] + nb1
__device__ __align__(128) float g_agg[(size_t)NNODE * DD];   // scatter-sum of edge messages
__device__ int   g_cnt[NNODE];
__device__ int   g_is64;
// pre-swizzled bf16 hi/lo weight tile images
__device__ __align__(16) __nv_bfloat16 g_w1h[2 * 128 * 128];  // edge W1^T, 2 chunks [128n][128k]
__device__ __align__(16) __nv_bfloat16 g_w1l[2 * 128 * 128];
__device__ __align__(16) __nv_bfloat16 g_w2h[2 * 128 * 128];  // edge W2^T
__device__ __align__(16) __nv_bfloat16 g_w2l[2 * 128 * 128];
__device__ __align__(16) __nv_bfloat16 g_nw1h[2 * 128 * 128]; // node W1[128:256]^T
__device__ __align__(16) __nv_bfloat16 g_nw1l[2 * 128 * 128];
__device__ __align__(16) __nv_bfloat16 g_nw2h[2 * 128 * 128]; // node W2^T
__device__ __align__(16) __nv_bfloat16 g_nw2l[2 * 128 * 128];
__device__ __align__(16) __nv_bfloat16 g_wAh[4 * 64 * 128];   // ew1[0:128]^T, 4 chunks [64n][128k]
__device__ __align__(16) __nv_bfloat16 g_wAl[4 * 64 * 128];
__device__ __align__(16) __nv_bfloat16 g_wBh[4 * 64 * 128];   // ew1[128:256]^T
__device__ __align__(16) __nv_bfloat16 g_wBl[4 * 64 * 128];

// ==================== helpers ====================
__device__ __forceinline__ uint32_t smem_to_u32(const void* p) {
    uint32_t a;
    asm("{ .reg .u64 t; cvta.to.shared.u64 t, %1; cvt.u32.u64 %0, t; }" : "=r"(a) : "l"(p));
    return a;
}
__device__ __forceinline__ int eidx(const void* ei, long long pos) {
    return g_is64 ? (int)((const long long*)ei)[pos] : ((const int*)ei)[pos];
}
__device__ __forceinline__ float siluf(float x) { return x * (1.0f / (1.0f + __expf(-x))); }
__device__ __forceinline__ void split2(float v, unsigned short& h, unsigned short& l) {
    __nv_bfloat16 hb = __float2bfloat16(v);
    __nv_bfloat16 lb = __float2bfloat16(v - __bfloat162float(hb));
    h = __bfloat16_as_ushort(hb);
    l = __bfloat16_as_ushort(lb);
}

#define LDSM_X4(r, ad) \
    asm volatile("ldmatrix.sync.aligned.m8n8.x4.shared.b16 {%0,%1,%2,%3}, [%4];" \
        : "=r"((r)[0]), "=r"((r)[1]), "=r"((r)[2]), "=r"((r)[3]) : "r"(ad))
#define MMA_BF16(d, a, b) \
    asm volatile("mma.sync.aligned.m16n8k16.row.col.f32.bf16.bf16.f32 " \
        "{%0,%1,%2,%3}, {%4,%5,%6,%7}, {%8,%9}, {%0,%1,%2,%3};" \
        : "+f"((d)[0]), "+f"((d)[1]), "+f"((d)[2]), "+f"((d)[3]) \
        : "r"((a)[0]), "r"((a)[1]), "r"((a)[2]), "r"((a)[3]), "r"((b)[0]), "r"((b)[1]))

__device__ __forceinline__ void bulk_reduce_add_f32(float* gdst, uint32_t ssrc, uint32_t bytes) {
    asm volatile("cp.reduce.async.bulk.global.shared::cta.bulk_group.add.f32 [%0], [%1], %2;"
                 :: "l"(gdst), "r"(ssrc), "r"(bytes) : "memory");
}
#define FENCE_ASYNC() asm volatile("fence.proxy.async.shared::cta;" ::: "memory")
#define CP_ASYNC16(sdst, gsrc) \
    asm volatile("cp.async.cg.shared.global [%0], [%1], 16;" :: "r"(sdst), "l"(gsrc) : "memory")
#define CP_COMMIT() asm volatile("cp.async.commit_group;" ::: "memory")
#define CP_WAIT0()  asm volatile("cp.async.wait_group 0;" ::: "memory")

// swizzled tile: rows of 256B (128 bf16); 16B-chunk c at row r lives at (c ^ (r&7))
__device__ __forceinline__ uint32_t sw_off(int r, int chunk) {
    return (uint32_t)(r * 256 + ((chunk ^ (r & 7)) << 4));
}

// ==================== launch 1: weight prep + cnt zero + dtype detect ====================
__global__ void k_prepw(const float* __restrict__ ew1, const float* __restrict__ ew2,
                        const float* __restrict__ nw1, const float* __restrict__ nw2,
                        const void* __restrict__ ei) {
    int i = blockIdx.x * 256 + threadIdx.x;   // grid 157*256 = 40192
    if (i == 0) {
        const long long* p = (const long long*)ei;
        int ok = 1;
        #pragma unroll
        for (int j = 0; j < 32; j++) {
            long long v = p[j];
            if (v < 0 || v >= NNODE) ok = 0;
        }
        g_is64 = ok;
    }
    if (i < NNODE) g_cnt[i] = 0;
    if (i < 32768) {
        // edge W1^T (2-chunk 128n): src ew1[(256+k)*256+n]
        {
            int n = i >> 7, k = i & 127;
            int chunk = n >> 7, r = n & 127;
            uint32_t off = (uint32_t)chunk * 32768 + sw_off(r, k >> 3) + (k & 7) * 2;
            unsigned short h, l;
            split2(ew1[(size_t)(256 + k) * HHID + n], h, l);
            *(unsigned short*)((char*)g_w1h + off) = h;
            *(unsigned short*)((char*)g_w1l + off) = l;
            // node W1[128:256]^T same layout: src nw1[(128+k)*256+n]
            split2(nw1[(size_t)(128 + k) * HHID + n], h, l);
            *(unsigned short*)((char*)g_nw1h + off) = h;
            *(unsigned short*)((char*)g_nw1l + off) = l;
        }
        // edge/node W2^T (2-chunk 128n): src w2[k*128+n]
        {
            int n = i & 127, k = i >> 7;
            int chunk = k >> 7, kk = k & 127;
            uint32_t off = (uint32_t)chunk * 32768 + sw_off(n, kk >> 3) + (kk & 7) * 2;
            unsigned short h, l;
            split2(ew2[(size_t)k * DD + n], h, l);
            *(unsigned short*)((char*)g_w2h + off) = h;
            *(unsigned short*)((char*)g_w2l + off) = l;
            split2(nw2[(size_t)k * DD + n], h, l);
            *(unsigned short*)((char*)g_nw2h + off) = h;
            *(unsigned short*)((char*)g_nw2l + off) = l;
        }
        // pregemm wA/wB (4-chunk 64n): src ew1[k*256+n], ew1[(128+k)*256+n]
        {
            int n = i >> 7, k = i & 127;
            int chunk = n >> 6, r = n & 63;
            uint32_t off = (uint32_t)chunk * 16384 + sw_off(r, k >> 3) + (k & 7) * 2;
            unsigned short h, l;
            split2(ew1[(size_t)k * HHID + n], h, l);
            *(unsigned short*)((char*)g_wAh + off) = h;
            *(unsigned short*)((char*)g_wAl + off) = l;
            split2(ew1[(size_t)(128 + k) * HHID + n], h, l);
            *(unsigned short*)((char*)g_wBh + off) = h;
            *(unsigned short*)((char*)g_wBl + off) = l;
        }
    }
}

// ==================== launch 3: zero agg + degree count ====================
__global__ void k_initcount(const void* __restrict__ ei) {
    int i = blockIdx.x * 256 + threadIdx.x;
    g_agg[i] = 0.0f;
    if (i < EEDGE) {
        int d = eidx(ei, (long long)EEDGE + i);
        atomicAdd(&g_cnt[d], 1);
    }
}

// ==================== HMMA pregemm (A and B via blockIdx.z) ====================
#define PG_A     0
#define PG_W     32768
#define PG_LOSEP 16384
#define SM_PG    65536

__device__ __forceinline__ void stage_w64(uint32_t sb, const __nv_bfloat16* gh,
                                          const __nv_bfloat16* gl, int tid) {
    const char* ph = (const char*)gh;
    const char* pl = (const char*)gl;
    #pragma unroll
    for (int j = 0; j < 4; j++) {
        int i = tid + j * 256;
        CP_ASYNC16(sb + PG_W + i * 16, ph + i * 16);
        CP_ASYNC16(sb + PG_W + PG_LOSEP + i * 16, pl + i * 16);
    }
    CP_COMMIT();
}

__device__ __forceinline__ void gemm64(uint32_t sb, int lane, int wm, int wn,
                                       float (&dd)[2][2][4]) {
    uint32_t bh[2][2][2], bl[2][2][2];
    uint32_t ah[2][2][4], al[2][2][4];

    const int gq = lane >> 3;
    const int rowq = wn * 16 + ((gq >> 1) << 3) + (lane & 7);
    const int rra0 = wm * 32 + (lane & 15);
    const int rra1 = rra0 + 16;
    const int bksel = gq & 1;
    const int aksel = lane >> 4;

    #define LD_B64(buf, ksv)                                                               \
    {                                                                                      \
        int chq = 2 * (ksv) + bksel;                                                       \
        uint32_t adq = sb + PG_W + sw_off(rowq, chq);                                      \
        uint32_t r4[4];                                                                    \
        LDSM_X4(r4, adq);                                                                  \
        bh[buf][0][0] = r4[0]; bh[buf][0][1] = r4[1]; bh[buf][1][0] = r4[2]; bh[buf][1][1] = r4[3]; \
        LDSM_X4(r4, adq + PG_LOSEP);                                                       \
        bl[buf][0][0] = r4[0]; bl[buf][0][1] = r4[1]; bl[buf][1][0] = r4[2]; bl[buf][1][1] = r4[3]; \
    }
    #define LD_A64(buf, ksv)                                                               \
    {                                                                                      \
        int ch = 2 * (ksv) + aksel;                                                        \
        uint32_t ad = sb + PG_A + sw_off(rra0, ch);                                        \
        LDSM_X4(ah[buf][0], ad);                                                           \
        LDSM_X4(al[buf][0], ad + PG_LOSEP);                                                \
        ad = sb + PG_A + sw_off(rra1, ch);                                                 \
        LDSM_X4(ah[buf][1], ad);                                                           \
        LDSM_X4(al[buf][1], ad + PG_LOSEP);                                                \
    }

    LD_B64(0, 0)
    LD_A64(0, 0)
    #pragma unroll
    for (int ks = 0; ks < 8; ks++) {
        const int cur = ks & 1, nxt = cur ^ 1;
        if (ks < 7) {
            LD_B64(nxt, ks + 1)
            LD_A64(nxt, ks + 1)
        }
        #pragma unroll
        for (int nt = 0; nt < 2; nt++) {
            MMA_BF16(dd[0][nt], ah[cur][0], bh[cur][nt]);
            MMA_BF16(dd[1][nt], ah[cur][1], bh[cur][nt]);
        }
        #pragma unroll
        for (int nt = 0; nt < 2; nt++) {
            MMA_BF16(dd[0][nt], ah[cur][0], bl[cur][nt]);
            MMA_BF16(dd[1][nt], ah[cur][1], bl[cur][nt]);
        }
        #pragma unroll
        for (int nt = 0; nt < 2; nt++) {
            MMA_BF16(dd[0][nt], al[cur][0], bh[cur][nt]);
            MMA_BF16(dd[1][nt], al[cur][1], bh[cur][nt]);
        }
    }
    #undef LD_B64
    #undef LD_A64
}

__global__ __launch_bounds__(256, 2) void k_pregemmH(
    const float* __restrict__ sx, const float* __restrict__ rx,
    const float* __restrict__ eb1)
{
    extern __shared__ char smc[];
    const uint32_t sb = smem_to_u32(smc);
    const int tid = threadIdx.x;
    const int lane = tid & 31, wid = tid >> 5;
    const int wm = wid >> 2, wn = wid & 3;
    const int row0 = blockIdx.x * 64;
    const int isB = blockIdx.z;

    const float* X = isB ? rx : sx;
    const __nv_bfloat16* wh = isB ? g_wBh : g_wAh;
    const __nv_bfloat16* wl = isB ? g_wBl : g_wAl;
    float* O = isB ? g_B : g_A;

    stage_w64(sb, wh, wl, tid);

    for (int idx = tid; idx < 64 * 32; idx += 256) {
        int r = idx >> 5, c4 = idx & 31;
        float4 v = *(const float4*)(X + (size_t)(row0 + r) * 128 + c4 * 4);
        unsigned short h0, l0, h1, l1, h2, l2, h3, l3;
        split2(v.x, h0, l0); split2(v.y, h1, l1); split2(v.z, h2, l2); split2(v.w, h3, l3);
        uint2 ph, pl;
        ph.x = (uint32_t)h0 | ((uint32_t)h1 << 16); ph.y = (uint32_t)h2 | ((uint32_t)h3 << 16);
        pl.x = (uint32_t)l0 | ((uint32_t)l1 << 16); pl.y = (uint32_t)l2 | ((uint32_t)l3 << 16);
        uint32_t off = sw_off(r, c4 >> 1) + (c4 & 1) * 8;
        *(uint2*)(smc + PG_A + off) = ph;
        *(uint2*)(smc + PG_A + PG_LOSEP + off) = pl;
    }
    CP_WAIT0();
    __syncthreads();

    #pragma unroll 1
    for (int cc = 0; cc < 4; cc++) {
        float dd[2][2][4];
        #pragma unroll
        for (int a = 0; a < 2; a++)
            #pragma unroll
            for (int b = 0; b < 2; b++)
                #pragma unroll
                for (int q = 0; q < 4; q++) dd[a][b][q] = 0.f;

        gemm64(sb, lane, wm, wn, dd);
        __syncthreads();
        if (cc < 3) stage_w64(sb, wh + (cc + 1) * 8192, wl + (cc + 1) * 8192, tid);

        #pragma unroll
        for (int mt = 0; mt < 2; mt++) {
            int r1 = wm * 32 + mt * 16 + (lane >> 2);
            int r2 = r1 + 8;
            #pragma unroll
            for (int nt = 0; nt < 2; nt++) {
                int col = wn * 16 + nt * 8 + 2 * (lane & 3);
                int gc = cc * 64 + col;
                float b0 = 0.f, b1 = 0.f;
                if (isB) {
                    float2 bb = *(const float2*)(eb1 + gc);
                    b0 = bb.x; b1 = bb.y;
                }
                *(float2*)(O + (size_t)(row0 + r1) * HHID + gc) =
                    make_float2(dd[mt][nt][0] + b0, dd[mt][nt][1] + b1);
                *(float2*)(O + (size_t)(row0 + r2) * HHID + gc) =
                    make_float2(dd[mt][nt][2] + b0, dd[mt][nt][3] + b1);
            }
        }
        if (cc < 3) {
            CP_WAIT0();
            __syncthreads();
        }
    }
}

// ==================== FFMA pregemmR (node receiver-half, overlapped) ====================
#define FMA44(A_, xv, wv)                                                              \
    A_[0][0] += xv.x * wv.x; A_[0][1] += xv.x * wv.y; A_[0][2] += xv.x * wv.z; A_[0][3] += xv.x * wv.w; \
    A_[1][0] += xv.y * wv.x; A_[1][1] += xv.y * wv.y; A_[1][2] += xv.y * wv.z; A_[1][3] += xv.y * wv.w; \
    A_[2][0] += xv.z * wv.x; A_[2][1] += xv.z * wv.y; A_[2][2] += xv.z * wv.z; A_[2][3] += xv.z * wv.w; \
    A_[3][0] += xv.w * wv.x; A_[3][1] += xv.w * wv.y; A_[3][2] += xv.w * wv.z; A_[3][3] += xv.w * wv.w;

#define FMAROW(yy, hx)                                                  \
    yy[0] += hx * w0.x; yy[1] += hx * w0.y; yy[2] += hx * w0.z; yy[3] += hx * w0.w; \
    yy[4] += hx * w1v.x; yy[5] += hx * w1v.y; yy[6] += hx * w1v.z; yy[7] += hx * w1v.w;

__global__ __launch_bounds__(256) void k_pregemmR(
    const float* __restrict__ rx, const float* __restrict__ nw1, const float* __restrict__ nb1)
{
    extern __shared__ float sm[];
    float* Xs = sm;
    float* Ws = sm + 128 * 68;
    int tid = threadIdx.x;
    int row0 = blockIdx.x * 64;
    int h0 = blockIdx.y * 64;

    for (int idx = tid; idx < 64 * 32; idx += 256) {
        int r = idx >> 5, k4 = idx & 31;
        float4 v = *(const float4*)&rx[(size_t)(row0 + r) * 128 + k4 * 4];
        Xs[(k4 * 4 + 0) * 68 + r] = v.x;
        Xs[(k4 * 4 + 1) * 68 + r] = v.y;
        Xs[(k4 * 4 + 2) * 68 + r] = v.z;
        Xs[(k4 * 4 + 3) * 68 + r] = v.w;
    }
    for (int idx = tid; idx < 128 * 16; idx += 256) {
        int k = idx >> 4, c4 = idx & 15;
        *(float4*)&Ws[k * 68 + c4 * 4] = *(const float4*)&nw1[(size_t)k * HHID + h0 + c4 * 4];
    }
    __syncthreads();

    int tx = tid & 15, ty = tid >> 4;
    float acc[4][4] = {};
    #pragma unroll 4
    for (int k = 0; k < 128; k++) {
        float4 xv = *(const float4*)&Xs[k * 68 + ty * 4];
        float4 wv = *(const float4*)&Ws[k * 68 + tx * 4];
        FMA44(acc, xv, wv)
    }
    #pragma unroll
    for (int i = 0; i < 4; i++) {
        float4 o = make_float4(acc[i][0], acc[i][1], acc[i][2], acc[i][3]);
        o.x += nb1[h0 + tx * 4 + 0];
        o.y += nb1[h0 + tx * 4 + 1];
        o.z += nb1[h0 + tx * 4 + 2];
        o.w += nb1[h0 + tx * 4 + 3];
        *(float4*)&g_R[(size_t)(row0 + ty * 4 + i) * HHID + h0 + tx * 4] = o;
    }
}

// ==================== FFMA fused sender (overlapped under edge) ====================
__global__ __launch_bounds__(256) void k_sender(
    const float* __restrict__ Xin,
    const float* __restrict__ w1, const float* __restrict__ b1,
    const float* __restrict__ w2, const float* __restrict__ b2,
    const float* __restrict__ gam, const float* __restrict__ bet,
    float* __restrict__ out)
{
    extern __shared__ float sm[];
    float* Xs = sm;
    float* Ws = Xs + 128 * 68;
    float* Hs = Ws + 128 * 68;

    int tid = threadIdx.x;
    int row0 = blockIdx.x * 64;

    for (int idx = tid; idx < 64 * 32; idx += 256) {
        int r = idx >> 5, k4 = idx & 31;
        float4 v = *(const float4*)&Xin[(size_t)(row0 + r) * 128 + k4 * 4];
        Xs[(k4 * 4 + 0) * 68 + r] = v.x;
        Xs[(k4 * 4 + 1) * 68 + r] = v.y;
        Xs[(k4 * 4 + 2) * 68 + r] = v.z;
        Xs[(k4 * 4 + 3) * 68 + r] = v.w;
    }
    __syncthreads();

    int tx = tid & 15, ty = tid >> 4;
    float y[4][8] = {};

    #pragma unroll 1
    for (int hc = 0; hc < 4; hc++) {
        int h0 = hc * 64;
        for (int idx = tid; idx < 128 * 16; idx += 256) {
            int k = idx >> 4, c4 = idx & 15;
            *(float4*)&Ws[k * 68 + c4 * 4] = *(const float4*)&w1[(size_t)k * HHID + h0 + c4 * 4];
        }
        __syncthreads();

        float h[4][4] = {};
        #pragma unroll 4
        for (int k = 0; k < 128; k++) {
            float4 xv = *(const float4*)&Xs[k * 68 + ty * 4];
            float4 wv = *(const float4*)&Ws[k * 68 + tx * 4];
            FMA44(h, xv, wv)
        }

        float4 bv = *(const float4*)&b1[h0 + tx * 4];
        #pragma unroll
        for (int i = 0; i < 4; i++) {
            h[i][0] += bv.x; h[i][1] += bv.y; h[i][2] += bv.z; h[i][3] += bv.w;
        }

        #pragma unroll
        for (int j = 0; j < 4; j++) {
            float4 hv;
            hv.x = siluf(h[0][j]);
            hv.y = siluf(h[1][j]);
            hv.z = siluf(h[2][j]);
            hv.w = siluf(h[3][j]);
            *(float4*)&Hs[(tx * 4 + j) * 68 + ty * 4] = hv;
        }
        __syncthreads();

        for (int idx = tid; idx < 64 * 32; idx += 256) {
            int k = idx >> 5, c4 = idx & 31;
            *(float4*)&Ws[k * 132 + c4 * 4] = *(const float4*)&w2[(size_t)(h0 + k) * 128 + c4 * 4];
        }
        __syncthreads();

        #pragma unroll 2
        for (int k = 0; k < 64; k++) {
            float4 hv = *(const float4*)&Hs[k * 68 + ty * 4];
            float4 w0 = *(const float4*)&Ws[k * 132 + tx * 8];
            float4 w1v = *(const float4*)&Ws[k * 132 + tx * 8 + 4];
            FMAROW(y[0], hv.x)
            FMAROW(y[1], hv.y)
            FMAROW(y[2], hv.z)
            FMAROW(y[3], hv.w)
        }
        __syncthreads();
    }

    float b2r[8], gr[8], br[8];
    #pragma unroll
    for (int c = 0; c < 8; c++) {
        b2r[c] = b2[tx * 8 + c];
        gr[c] = gam[tx * 8 + c];
        br[c] = bet[tx * 8 + c];
    }
    #pragma unroll
    for (int i = 0; i < 4; i++) {
        #pragma unroll
        for (int c = 0; c < 8; c++) y[i][c] += b2r[c];

        float s1 = 0.f, s2 = 0.f;
        #pragma unroll
        for (int c = 0; c < 8; c++) { float v = y[i][c]; s1 += v; s2 += v * v; }
        #pragma unroll
        for (int m = 8; m >= 1; m >>= 1) {
            s1 += __shfl_xor_sync(0xffffffffu, s1, m);
            s2 += __shfl_xor_sync(0xffffffffu, s2, m);
        }
        float mu = s1 * (1.0f / 128.0f);
        float rs = rsqrtf(s2 * (1.0f / 128.0f) - mu * mu + LNEPS);

        int r = ty * 4 + i;
        float o[8];
        #pragma unroll
        for (int c = 0; c < 8; c++)
            o[c] = (y[i][c] - mu) * rs * gr[c] + br[c] + Xs[(tx * 8 + c) * 68 + r];
        size_t gout = (size_t)(row0 + r) * 128 + tx * 8;
        *(float4*)&out[gout]     = make_float4(o[0], o[1], o[2], o[3]);
        *(float4*)&out[gout + 4] = make_float4(o[4], o[5], o[6], o[7]);
    }
}

// ==================== HMMA MLP kernel: MODE 0 = edge, MODE 1 = node ====================
#define OFF_SIDX   0
#define OFF_DIDX   512
#define OFF_P1     1024
#define OFF_P2     3072
#define OFF_A_HI   5120
#define OFF_A_LO   37888
#define OFF_MSG    5120
#define OFF_W_HI   70656
#define OFF_W_LO   103424
#define OFF_H_HI   136192
#define OFF_H_LO   168960
#define SM_EDGE    201728

__device__ __forceinline__ void stage_w(uint32_t sb, const __nv_bfloat16* gh,
                                        const __nv_bfloat16* gl, int tid) {
    const char* ph = (const char*)gh;
    const char* pl = (const char*)gl;
    #pragma unroll
    for (int j = 0; j < 4; j++) {
        int i = tid + j * 512;
        CP_ASYNC16(sb + OFF_W_HI + i * 16, ph + i * 16);
        CP_ASYNC16(sb + OFF_W_LO + i * 16, pl + i * 16);
    }
    CP_COMMIT();
}

__device__ __forceinline__ void gemm_phase(uint32_t sb, int lane, int wm, int wn,
                                           uint32_t baseA, float (&dd)[2][4][4]) {
    uint32_t bh[2][4][2], bl[2][4][2];
    uint32_t ah[2][2][4], al[2][2][4];

    const int gq = lane >> 3;
    const int rowq0 = wn * 32 + ((gq >> 1) << 3) + (lane & 7);
    const int rowq1 = rowq0 + 16;
    const int rra0 = wm * 32 + (lane & 15);
    const int rra1 = rra0 + 16;
    const int bksel = gq & 1;
    const int aksel = lane >> 4;

    #define LD_B(buf, ksv)                                                                 \
    {                                                                                      \
        int chq = 2 * (ksv) + bksel;                                                       \
        uint32_t adq = sb + OFF_W_HI + sw_off(rowq0, chq);                                 \
        uint32_t r4[4];                                                                    \
        LDSM_X4(r4, adq);                                                                  \
        bh[buf][0][0] = r4[0]; bh[buf][0][1] = r4[1]; bh[buf][1][0] = r4[2]; bh[buf][1][1] = r4[3]; \
        LDSM_X4(r4, adq + 32768);                                                          \
        bl[buf][0][0] = r4[0]; bl[buf][0][1] = r4[1]; bl[buf][1][0] = r4[2]; bl[buf][1][1] = r4[3]; \
        adq = sb + OFF_W_HI + sw_off(rowq1, chq);                                          \
        LDSM_X4(r4, adq);                                                                  \
        bh[buf][2][0] = r4[0]; bh[buf][2][1] = r4[1]; bh[buf][3][0] = r4[2]; bh[buf][3][1] = r4[3]; \
        LDSM_X4(r4, adq + 32768);                                                          \
        bl[buf][2][0] = r4[0]; bl[buf][2][1] = r4[1]; bl[buf][3][0] = r4[2]; bl[buf][3][1] = r4[3]; \
    }
    #define LD_A(buf, ksv)                                                                 \
    {                                                                                      \
        int ch = 2 * (ksv) + aksel;                                                        \
        uint32_t ad = sb + baseA + sw_off(rra0, ch);                                       \
        LDSM_X4(ah[buf][0], ad);                                                           \
        LDSM_X4(al[buf][0], ad + 32768);                                                   \
        ad = sb + baseA + sw_off(rra1, ch);                                                \
        LDSM_X4(ah[buf][1], ad);                                                           \
        LDSM_X4(al[buf][1], ad + 32768);                                                   \
    }

    LD_B(0, 0)
    LD_A(0, 0)
    #pragma unroll
    for (int ks = 0; ks < 8; ks++) {
        const int cur = ks & 1, nxt = cur ^ 1;
        if (ks < 7) {
            LD_B(nxt, ks + 1)
            LD_A(nxt, ks + 1)
        }
        #pragma unroll
        for (int nt = 0; nt < 4; nt++) {
            MMA_BF16(dd[0][nt], ah[cur][0], bh[cur][nt]);
            MMA_BF16(dd[1][nt], ah[cur][1], bh[cur][nt]);
        }
        #pragma unroll
        for (int nt = 0; nt < 4; nt++) {
            MMA_BF16(dd[0][nt], ah[cur][0], bl[cur][nt]);
            MMA_BF16(dd[1][nt], ah[cur][1], bl[cur][nt]);
        }
        #pragma unroll
        for (int nt = 0; nt < 4; nt++) {
            MMA_BF16(dd[0][nt], al[cur][0], bh[cur][nt]);
            MMA_BF16(dd[1][nt], al[cur][1], bh[cur][nt]);
        }
    }
    #undef LD_B
    #undef LD_A
}

// epi1: MODE 0: D1 + gA[src] + gB[dst]; MODE 1: D1 + gA[row] (gA = g_R)
template <int MODE>
__device__ __forceinline__ void epi1_phase(char* smc, const int* sidx_s, const int* didx_s,
    const float* gA, const float* gB, float (&d1)[2][4][4],
    int wm, int wn, int lane, int c, uint32_t dstHi, int row0)
{
    #pragma unroll
    for (int mt = 0; mt < 2; mt++) {
        int r1 = wm * 32 + mt * 16 + (lane >> 2);
        int r2 = r1 + 8;
        int si1, di1, si2, di2;
        if (MODE == 0) {
            si1 = sidx_s[r1]; di1 = didx_s[r1];
            si2 = sidx_s[r2]; di2 = didx_s[r2];
        } else {
            si1 = row0 + r1; if (si1 >= NNODE) si1 = NNODE - 1;
            si2 = row0 + r2; if (si2 >= NNODE) si2 = NNODE - 1;
            di1 = di2 = 0;
        }
        #pragma unroll
        for (int nt = 0; nt < 4; nt++) {
            int cpl = wn * 32 + nt * 8 + 2 * (lane & 3);
            int gc = c * 128 + cpl;
            float2 a1 = *(const float2*)(gA + (size_t)si1 * HHID + gc);
            float2 a2 = *(const float2*)(gA + (size_t)si2 * HHID + gc);
            float g10 = a1.x, g11 = a1.y, g20 = a2.x, g21 = a2.y;
            if (MODE == 0) {
                float2 bb1 = *(const float2*)(gB + (size_t)di1 * HHID + gc);
                float2 bb2 = *(const float2*)(gB + (size_t)di2 * HHID + gc);
                g10 += bb1.x; g11 += bb1.y; g20 += bb2.x; g21 += bb2.y;
            }
            float h00 = siluf(d1[mt][nt][0] + g10);
            float h01 = siluf(d1[mt][nt][1] + g11);
            float h10 = siluf(d1[mt][nt][2] + g20);
            float h11 = siluf(d1[mt][nt][3] + g21);
            unsigned short p0h, p0l, p1h, p1l, q0h, q0l, q1h, q1l;
            split2(h00, p0h, p0l); split2(h01, p1h, p1l);
            split2(h10, q0h, q0l); split2(h11, q1h, q1l);
            uint32_t o1 = sw_off(r1, (cpl >> 3)) + (cpl & 7) * 2;
            uint32_t o2 = sw_off(r2, (cpl >> 3)) + (cpl & 7) * 2;
            *(uint32_t*)(smc + dstHi + o1)         = (uint32_t)p0h | ((uint32_t)p1h << 16);
            *(uint32_t*)(smc + dstHi + 32768 + o1) = (uint32_t)p0l | ((uint32_t)p1l << 16);
            *(uint32_t*)(smc + dstHi + o2)         = (uint32_t)q0h | ((uint32_t)q1h << 16);
            *(uint32_t*)(smc + dstHi + 32768 + o2) = (uint32_t)q0l | ((uint32_t)q1l << 16);
        }
    }
}

template <int MODE>
__global__ __launch_bounds__(512, 1) void k_mlp(
    const float* __restrict__ Ain, const void* __restrict__ ei,
    const float* __restrict__ gA, const float* __restrict__ gB,
    const __nv_bfloat16* __restrict__ w1h, const __nv_bfloat16* __restrict__ w1l,
    const __nv_bfloat16* __restrict__ w2h, const __nv_bfloat16* __restrict__ w2l,
    const float* __restrict__ b2, const float* __restrict__ gam, const float* __restrict__ bet,
    const float* __restrict__ resid, float* __restrict__ out, float* __restrict__ agg)
{
    extern __shared__ char smc[];
    const uint32_t sb = smem_to_u32(smc);
    const int tid = threadIdx.x;
    const int lane = tid & 31, wid = tid >> 5;
    const int wm = wid >> 2, wn = wid & 3;
    const int row0 = blockIdx.x * 128;

    stage_w(sb, w1h, w1l, tid);

    int* sidx_s = (int*)(smc + OFF_SIDX);
    int* didx_s = (int*)(smc + OFF_DIDX);
    float* rc_s = (float*)(smc + OFF_SIDX);   // MODE 1 reuses this region

    if (MODE == 0) {
        if (tid < 128) {
            sidx_s[tid] = eidx(ei, (long long)(row0 + tid));
            didx_s[tid] = eidx(ei, (long long)EEDGE + row0 + tid);
        }
    } else {
        if (tid < 128) {
            int rr = row0 + tid; if (rr >= NNODE) rr = NNODE - 1;
            int cval = g_cnt[rr];
            rc_s[tid] = 1.0f / (float)(cval > 1 ? cval : 1);
        }
        __syncthreads();   // rc_s ready before A convert
    }

    // A tile -> bf16 hi/lo swizzled
    for (int idx = tid; idx < 128 * 32; idx += 512) {
        int r = idx >> 5, c4 = idx & 31;
        int gr = row0 + r;
        if (MODE == 1 && gr >= NNODE) gr = NNODE - 1;
        float4 v = *(const float4*)(Ain + (size_t)gr * 128 + c4 * 4);
        if (MODE == 1) {
            float s = rc_s[r];
            v.x *= s; v.y *= s; v.z *= s; v.w *= s;
        }
        unsigned short h0, l0, h1, l1, h2, l2, h3, l3;
        split2(v.x, h0, l0); split2(v.y, h1, l1); split2(v.z, h2, l2); split2(v.w, h3, l3);
        uint2 ph, pl;
        ph.x = (uint32_t)h0 | ((uint32_t)h1 << 16); ph.y = (uint32_t)h2 | ((uint32_t)h3 << 16);
        pl.x = (uint32_t)l0 | ((uint32_t)l1 << 16); pl.y = (uint32_t)l2 | ((uint32_t)l3 << 16);
        uint32_t off = sw_off(r, c4 >> 1) + (c4 & 1) * 8;
        *(uint2*)(smc + OFF_A_HI + off) = ph;
        *(uint2*)(smc + OFF_A_LO + off) = pl;
    }
    CP_WAIT0();
    __syncthreads();

    float d1[2][4][4];
    #pragma unroll
    for (int a = 0; a < 2; a++)
        #pragma unroll
        for (int b = 0; b < 4; b++)
            #pragma unroll
            for (int q = 0; q < 4; q++) d1[a][b][q] = 0.f;

    gemm_phase(sb, lane, wm, wn, OFF_A_HI, d1);
    __syncthreads();
    stage_w(sb, w1h + 16384, w1l + 16384, tid);
    epi1_phase<MODE>(smc, sidx_s, didx_s, gA, gB, d1, wm, wn, lane, 0, OFF_H_HI, row0);
    CP_WAIT0();
    __syncthreads();

    #pragma unroll
    for (int a = 0; a < 2; a++)
        #pragma unroll
        for (int b = 0; b < 4; b++)
            #pragma unroll
            for (int q = 0; q < 4; q++) d1[a][b][q] = 0.f;
    gemm_phase(sb, lane, wm, wn, OFF_A_HI, d1);
    __syncthreads();
    stage_w(sb, w2h, w2l, tid);
    epi1_phase<MODE>(smc, sidx_s, didx_s, gA, gB, d1, wm, wn, lane, 1, OFF_A_HI, row0);
    CP_WAIT0();
    __syncthreads();

    float d2[2][4][4];
    #pragma unroll
    for (int a = 0; a < 2; a++)
        #pragma unroll
        for (int b = 0; b < 4; b++)
            #pragma unroll
            for (int q = 0; q < 4; q++) d2[a][b][q] = 0.f;
    gemm_phase(sb, lane, wm, wn, OFF_H_HI, d2);
    __syncthreads();
    stage_w(sb, w2h + 16384, w2l + 16384, tid);
    CP_WAIT0();
    __syncthreads();

    gemm_phase(sb, lane, wm, wn, OFF_A_HI, d2);

    // ---- epi2: +b2, LayerNorm, residual, store (+ messages for MODE 0) ----
    float b2v[4][2], gmv[4][2], btv[4][2];
    #pragma unroll
    for (int nt = 0; nt < 4; nt++) {
        int col = wn * 32 + nt * 8 + 2 * (lane & 3);
        float2 t;
        t = *(const float2*)(b2 + col);  b2v[nt][0] = t.x; b2v[nt][1] = t.y;
        t = *(const float2*)(gam + col); gmv[nt][0] = t.x; gmv[nt][1] = t.y;
        t = *(const float2*)(bet + col); btv[nt][0] = t.x; btv[nt][1] = t.y;
    }
    float* p1 = (float*)(smc + OFF_P1);
    float* p2 = (float*)(smc + OFF_P2);

    #pragma unroll
    for (int mt = 0; mt < 2; mt++) {
        int r1 = wm * 32 + mt * 16 + (lane >> 2);
        int r2 = r1 + 8;
        float s1a = 0.f, s2a = 0.f, s1b = 0.f, s2b = 0.f;
        #pragma unroll
        for (int nt = 0; nt < 4; nt++) {
            float y0 = d2[mt][nt][0] + b2v[nt][0];
            float y1 = d2[mt][nt][1] + b2v[nt][1];
            float y2 = d2[mt][nt][2] + b2v[nt][0];
            float y3 = d2[mt][nt][3] + b2v[nt][1];
            d2[mt][nt][0] = y0; d2[mt][nt][1] = y1; d2[mt][nt][2] = y2; d2[mt][nt][3] = y3;
            s1a += y0 + y1; s2a += y0 * y0 + y1 * y1;
            s1b += y2 + y3; s2b += y2 * y2 + y3 * y3;
        }
        #pragma unroll
        for (int m = 1; m <= 2; m <<= 1) {
            s1a += __shfl_xor_sync(0xffffffffu, s1a, m);
            s2a += __shfl_xor_sync(0xffffffffu, s2a, m);
            s1b += __shfl_xor_sync(0xffffffffu, s1b, m);
            s2b += __shfl_xor_sync(0xffffffffu, s2b, m);
        }
        if ((lane & 3) == 0) {
            p1[r1 * 4 + wn] = s1a; p2[r1 * 4 + wn] = s2a;
            p1[r2 * 4 + wn] = s1b; p2[r2 * 4 + wn] = s2b;
        }
    }
    __syncthreads();

    float* msg = (float*)(smc + OFF_MSG);
    #pragma unroll
    for (int mt = 0; mt < 2; mt++) {
        int r1 = wm * 32 + mt * 16 + (lane >> 2);
        int r2 = r1 + 8;
        float4 q1 = *(float4*)&p1[r1 * 4];
        float4 v1 = *(float4*)&p2[r1 * 4];
        float4 q2 = *(float4*)&p1[r2 * 4];
        float4 v2 = *(float4*)&p2[r2 * 4];
        float mu1 = (q1.x + q1.y + q1.z + q1.w) * (1.0f / 128.0f);
        float mu2 = (q2.x + q2.y + q2.z + q2.w) * (1.0f / 128.0f);
        float rs1 = rsqrtf((v1.x + v1.y + v1.z + v1.w) * (1.0f / 128.0f) - mu1 * mu1 + LNEPS);
        float rs2 = rsqrtf((v2.x + v2.y + v2.z + v2.w) * (1.0f / 128.0f) - mu2 * mu2 + LNEPS);
        bool w1ok = (MODE == 0) || (row0 + r1 < NNODE);
        bool w2ok = (MODE == 0) || (row0 + r2 < NNODE);
        #pragma unroll
        for (int nt = 0; nt < 4; nt++) {
            int col = wn * 32 + nt * 8 + 2 * (lane & 3);
            float pa0 = (d2[mt][nt][0] - mu1) * rs1 * gmv[nt][0] + btv[nt][0];
            float pa1 = (d2[mt][nt][1] - mu1) * rs1 * gmv[nt][1] + btv[nt][1];
            float pb0 = (d2[mt][nt][2] - mu2) * rs2 * gmv[nt][0] + btv[nt][0];
            float pb1 = (d2[mt][nt][3] - mu2) * rs2 * gmv[nt][1] + btv[nt][1];
            if (w1ok) {
                float2 x1 = *(const float2*)(resid + (size_t)(row0 + r1) * 128 + col);
                *(float2*)(out + (size_t)(row0 + r1) * 128 + col) = make_float2(pa0 + x1.x, pa1 + x1.y);
            }
            if (w2ok) {
                float2 x2 = *(const float2*)(resid + (size_t)(row0 + r2) * 128 + col);
                *(float2*)(out + (size_t)(row0 + r2) * 128 + col) = make_float2(pb0 + x2.x, pb1 + x2.y);
            }
            if (MODE == 0) {
                *(float2*)(msg + r1 * 128 + col) = make_float2(pa0, pa1);
                *(float2*)(msg + r2 * 128 + col) = make_float2(pb0, pb1);
            }
        }
    }

    if (MODE == 0) {
        FENCE_ASYNC();
        __syncthreads();
        if (tid < 128) {
            float* gdst = agg + (size_t)didx_s[tid] * 128;
            bulk_reduce_add_f32(gdst, sb + OFF_MSG + (uint32_t)tid * 512, 512);
            asm volatile("cp.async.bulk.commit_group;" ::: "memory");
            asm volatile("cp.async.bulk.wait_group 0;" ::: "memory");
        }
    }
}

// ==================== launcher ====================
extern "C" void kernel_launch(void* const* d_in, const int* in_sizes, int n_in,
                              void* d_out, int out_size) {
    (void)in_sizes; (void)n_in; (void)out_size;
    const float* sender_x   = (const float*)d_in[0];
    const float* receiver_x = (const float*)d_in[1];
    const float* edge_attr  = (const float*)d_in[2];
    const void*  ei         = d_in[3];
    const float* ew1  = (const float*)d_in[4];
    const float* eb1  = (const float*)d_in[5];
    const float* ew2  = (const float*)d_in[6];
    const float* eb2  = (const float*)d_in[7];
    const float* eg   = (const float*)d_in[8];
    const float* ebt  = (const float*)d_in[9];
    const float* nw1  = (const float*)d_in[10];
    const float* nb1  = (const float*)d_in[11];
    const float* nw2  = (const float*)d_in[12];
    const float* nb2  = (const float*)d_in[13];
    const float* ng   = (const float*)d_in[14];
    const float* nbt  = (const float*)d_in[15];
    const float* sw1  = (const float*)d_in[16];
    const float* sb1  = (const float*)d_in[17];
    const float* sw2  = (const float*)d_in[18];
    const float* sb2  = (const float*)d_in[19];
    const float* sg   = (const float*)d_in[20];
    const float* sbt  = (const float*)d_in[21];

    float* out = (float*)d_out;
    float* out_send = out;
    float* out_recv = out + (size_t)NNODE * DD;
    float* out_edge = out + (size_t)2 * NNODE * DD;

    void *pA, *pB, *pR, *pAgg;
    void *pw1h, *pw1l, *pw2h, *pw2l, *pn1h, *pn1l, *pn2h, *pn2l;
    cudaGetSymbolAddress(&pA, g_A);
    cudaGetSymbolAddress(&pB, g_B);
    cudaGetSymbolAddress(&pR, g_R);
    cudaGetSymbolAddress(&pAgg, g_agg);
    cudaGetSymbolAddress(&pw1h, g_w1h);
    cudaGetSymbolAddress(&pw1l, g_w1l);
    cudaGetSymbolAddress(&pw2h, g_w2h);
    cudaGetSymbolAddress(&pw2l, g_w2l);
    cudaGetSymbolAddress(&pn1h, g_nw1h);
    cudaGetSymbolAddress(&pn1l, g_nw1l);
    cudaGetSymbolAddress(&pn2h, g_nw2h);
    cudaGetSymbolAddress(&pn2l, g_nw2l);

    static cudaStream_t s2 = nullptr;
    static cudaEvent_t evS = nullptr, evP = nullptr, evJ = nullptr;
    if (s2 == nullptr) {
        cudaStreamCreateWithFlags(&s2, cudaStreamNonBlocking);
        cudaEventCreateWithFlags(&evS, cudaEventDisableTiming);
        cudaEventCreateWithFlags(&evP, cudaEventDisableTiming);
        cudaEventCreateWithFlags(&evJ, cudaEventDisableTiming);
    }

    const int SM_PRE = (128 * 68 + 128 * 68) * 4;
    const int SM_FU  = (128 * 68 + 128 * 68 + 64 * 68 + 64) * 4;
    cudaFuncSetAttribute(k_pregemmH, cudaFuncAttributeMaxDynamicSharedMemorySize, SM_PG);
    cudaFuncSetAttribute(k_pregemmR, cudaFuncAttributeMaxDynamicSharedMemorySize, SM_PRE);
    cudaFuncSetAttribute(k_sender,   cudaFuncAttributeMaxDynamicSharedMemorySize, SM_FU);
    cudaFuncSetAttribute(k_mlp<0>,   cudaFuncAttributeMaxDynamicSharedMemorySize, SM_EDGE);
    cudaFuncSetAttribute(k_mlp<1>,   cudaFuncAttributeMaxDynamicSharedMemorySize, SM_EDGE);

    // launch 1: weight prep + cnt zero + dtype detect (main)
    k_prepw<<<157, 256>>>(ew1, ew2, nw1, nw2, ei);
    cudaEventRecord(evS, 0);
    // launch 2: HMMA pregemm A/B on side stream
    cudaStreamWaitEvent(s2, evS, 0);
    k_pregemmH<<<dim3(NNODE / 64, 1, 2), 256, SM_PG, s2>>>(sender_x, receiver_x, eb1);
    // launch 3: zero agg + degree count (main)
    k_initcount<<<(NNODE * DD) / 256, 256>>>(ei);
    cudaEventRecord(evP, s2);
    cudaStreamWaitEvent(0, evP, 0);
    // launch 4 (ncu slot): edge kernel
    k_mlp<0><<<EEDGE / 128, 512, SM_EDGE>>>(
        edge_attr, ei, (const float*)pA, (const float*)pB,
        (const __nv_bfloat16*)pw1h, (const __nv_bfloat16*)pw1l,
        (const __nv_bfloat16*)pw2h, (const __nv_bfloat16*)pw2l,
        eb2, eg, ebt, edge_attr, out_edge, (float*)pAgg);
    // side stream overlaps edge: sender MLP + node receiver-half precompute
    k_sender<<<NNODE / 64, 256, SM_FU, s2>>>(sender_x, sw1, sb1, sw2, sb2, sg, sbt, out_send);
    k_pregemmR<<<dim3(NNODE / 64, 4), 256, SM_PRE, s2>>>(receiver_x, nw1, nb1);
    cudaEventRecord(evJ, s2);
    cudaStreamWaitEvent(0, evJ, 0);
    // node MLP (HMMA): agg-dependent half, g_R gathered densely
    k_mlp<1><<<(NNODE + 127) / 128, 512, SM_EDGE>>>(
        (const float*)pAgg, nullptr, (const float*)pR, nullptr,
        (const __nv_bfloat16*)pn1h, (const __nv_bfloat16*)pn1l,
        (const __nv_bfloat16*)pn2h, (const __nv_bfloat16*)pn2l,
        nb2, ng, nbt, receiver_x, out_recv, nullptr);
}

// round 12
// speedup vs baseline: 1.3893x; 1.1801x over previous
#include <cuda_runtime.h>
#include <cuda_bf16.h>
#include <cuda_fp16.h>
#include <math.h>
#include <cstdint>

#define NNODE 40000
#define EEDGE 640000
#define DD    128
#define HHID  256
#define LNEPS 1e-5f

// ==================== device scratch (allocation-free) ====================
__device__ __align__(128) float g_A[(size_t)NNODE * HHID];   // sender_x @ ew1[0:128]
__device__ __align__(128) float g_B[(size_t)NNODE * HHID];   // receiver_x @ ew1[128:256] + eb1
__device__ __align__(128) float g_R[(size_t)NNODE * HHID];   // receiver_x @ nw1[0:128] + nb1
__device__ __align__(128) float g_agg[(size_t)NNODE * DD];   // scatter-sum of edge messages
__device__ int   g_cnt[NNODE];
__device__ int   g_is64;
// fp16 single-precision weight images for the HMMA MLP kernels (2 chunks [128n][128k])
__device__ __align__(16) __half g_w1f[2 * 128 * 128];   // edge W1[256:384]^T
__device__ __align__(16) __half g_w2f[2 * 128 * 128];   // edge W2^T
__device__ __align__(16) __half g_nw1f[2 * 128 * 128];  // node W1[128:256]^T
__device__ __align__(16) __half g_nw2f[2 * 128 * 128];  // node W2^T
// bf16 hi/lo images for the high-precision pregemm (4 chunks [64n][128k])
__device__ __align__(16) __nv_bfloat16 g_wAh[4 * 64 * 128];
__device__ __align__(16) __nv_bfloat16 g_wAl[4 * 64 * 128];
__device__ __align__(16) __nv_bfloat16 g_wBh[4 * 64 * 128];
__device__ __align__(16) __nv_bfloat16 g_wBl[4 * 64 * 128];

// ==================== helpers ====================
__device__ __forceinline__ uint32_t smem_to_u32(const void* p) {
    uint32_t a;
    asm("{ .reg .u64 t; cvta.to.shared.u64 t, %1; cvt.u32.u64 %0, t; }" : "=r"(a) : "l"(p));
    return a;
}
__device__ __forceinline__ int eidx(const void* ei, long long pos) {
    return g_is64 ? (int)((const long long*)ei)[pos] : ((const int*)ei)[pos];
}
__device__ __forceinline__ float siluf(float x) { return x * (1.0f / (1.0f + __expf(-x))); }
__device__ __forceinline__ void split2(float v, unsigned short& h, unsigned short& l) {
    __nv_bfloat16 hb = __float2bfloat16(v);
    __nv_bfloat16 lb = __float2bfloat16(v - __bfloat162float(hb));
    h = __bfloat16_as_ushort(hb);
    l = __bfloat16_as_ushort(lb);
}
__device__ __forceinline__ void split2h(float v, unsigned short& h, unsigned short& l) {
    __half hh = __float2half_rn(v);
    __half ll = __float2half_rn(v - __half2float(hh));
    h = __half_as_ushort(hh);
    l = __half_as_ushort(ll);
}

#define LDSM_X4(r, ad) \
    asm volatile("ldmatrix.sync.aligned.m8n8.x4.shared.b16 {%0,%1,%2,%3}, [%4];" \
        : "=r"((r)[0]), "=r"((r)[1]), "=r"((r)[2]), "=r"((r)[3]) : "r"(ad))
#define MMA_BF16(d, a, b) \
    asm volatile("mma.sync.aligned.m16n8k16.row.col.f32.bf16.bf16.f32 " \
        "{%0,%1,%2,%3}, {%4,%5,%6,%7}, {%8,%9}, {%0,%1,%2,%3};" \
        : "+f"((d)[0]), "+f"((d)[1]), "+f"((d)[2]), "+f"((d)[3]) \
        : "r"((a)[0]), "r"((a)[1]), "r"((a)[2]), "r"((a)[3]), "r"((b)[0]), "r"((b)[1]))
#define MMA_FP16(d, a, b) \
    asm volatile("mma.sync.aligned.m16n8k16.row.col.f32.f16.f16.f32 " \
        "{%0,%1,%2,%3}, {%4,%5,%6,%7}, {%8,%9}, {%0,%1,%2,%3};" \
        : "+f"((d)[0]), "+f"((d)[1]), "+f"((d)[2]), "+f"((d)[3]) \
        : "r"((a)[0]), "r"((a)[1]), "r"((a)[2]), "r"((a)[3]), "r"((b)[0]), "r"((b)[1]))

__device__ __forceinline__ void bulk_reduce_add_f32(float* gdst, uint32_t ssrc, uint32_t bytes) {
    asm volatile("cp.reduce.async.bulk.global.shared::cta.bulk_group.add.f32 [%0], [%1], %2;"
                 :: "l"(gdst), "r"(ssrc), "r"(bytes) : "memory");
}
#define FENCE_ASYNC() asm volatile("fence.proxy.async.shared::cta;" ::: "memory")
#define CP_ASYNC16(sdst, gsrc) \
    asm volatile("cp.async.cg.shared.global [%0], [%1], 16;" :: "r"(sdst), "l"(gsrc) : "memory")
#define CP_COMMIT() asm volatile("cp.async.commit_group;" ::: "memory")
#define CP_WAIT0()  asm volatile("cp.async.wait_group 0;" ::: "memory")

// swizzled tile: rows of 256B (128 b16); 16B-chunk c at row r lives at (c ^ (r&7))
__device__ __forceinline__ uint32_t sw_off(int r, int chunk) {
    return (uint32_t)(r * 256 + ((chunk ^ (r & 7)) << 4));
}

// ==================== launch 1: weight prep + cnt zero + dtype detect ====================
__global__ void k_prepw(const float* __restrict__ ew1, const float* __restrict__ ew2,
                        const float* __restrict__ nw1, const float* __restrict__ nw2,
                        const void* __restrict__ ei) {
    int i = blockIdx.x * 256 + threadIdx.x;   // grid 157*256 = 40192
    if (i == 0) {
        const long long* p = (const long long*)ei;
        int ok = 1;
        #pragma unroll
        for (int j = 0; j < 32; j++) {
            long long v = p[j];
            if (v < 0 || v >= NNODE) ok = 0;
        }
        g_is64 = ok;
    }
    if (i < NNODE) g_cnt[i] = 0;
    if (i < 32768) {
        // edge/node W1^T fp16 (2-chunk 128n): src ew1[(256+k)*256+n], nw1[(128+k)*256+n]
        {
            int n = i >> 7, k = i & 127;
            int chunk = n >> 7, r = n & 127;
            uint32_t off = (uint32_t)chunk * 32768 + sw_off(r, k >> 3) + (k & 7) * 2;
            *(unsigned short*)((char*)g_w1f + off) =
                __half_as_ushort(__float2half_rn(ew1[(size_t)(256 + k) * HHID + n]));
            *(unsigned short*)((char*)g_nw1f + off) =
                __half_as_ushort(__float2half_rn(nw1[(size_t)(128 + k) * HHID + n]));
        }
        // edge/node W2^T fp16 (2-chunk 128n): src w2[k*128+n]
        {
            int n = i & 127, k = i >> 7;
            int chunk = k >> 7, kk = k & 127;
            uint32_t off = (uint32_t)chunk * 32768 + sw_off(n, kk >> 3) + (kk & 7) * 2;
            *(unsigned short*)((char*)g_w2f + off) =
                __half_as_ushort(__float2half_rn(ew2[(size_t)k * DD + n]));
            *(unsigned short*)((char*)g_nw2f + off) =
                __half_as_ushort(__float2half_rn(nw2[(size_t)k * DD + n]));
        }
        // pregemm wA/wB bf16 hi/lo (4-chunk 64n): src ew1[k*256+n], ew1[(128+k)*256+n]
        {
            int n = i >> 7, k = i & 127;
            int chunk = n >> 6, r = n & 63;
            uint32_t off = (uint32_t)chunk * 16384 + sw_off(r, k >> 3) + (k & 7) * 2;
            unsigned short h, l;
            split2(ew1[(size_t)k * HHID + n], h, l);
            *(unsigned short*)((char*)g_wAh + off) = h;
            *(unsigned short*)((char*)g_wAl + off) = l;
            split2(ew1[(size_t)(128 + k) * HHID + n], h, l);
            *(unsigned short*)((char*)g_wBh + off) = h;
            *(unsigned short*)((char*)g_wBl + off) = l;
        }
    }
}

// ==================== launch 3: zero agg + degree count ====================
__global__ void k_initcount(const void* __restrict__ ei) {
    int i = blockIdx.x * 256 + threadIdx.x;
    g_agg[i] = 0.0f;
    if (i < EEDGE) {
        int d = eidx(ei, (long long)EEDGE + i);
        atomicAdd(&g_cnt[d], 1);
    }
}

// ==================== HMMA pregemm (bf16 3-pass, off critical path) ====================
#define PG_A     0
#define PG_W     32768
#define PG_LOSEP 16384
#define SM_PG    65536

__device__ __forceinline__ void stage_w64(uint32_t sb, const __nv_bfloat16* gh,
                                          const __nv_bfloat16* gl, int tid) {
    const char* ph = (const char*)gh;
    const char* pl = (const char*)gl;
    #pragma unroll
    for (int j = 0; j < 4; j++) {
        int i = tid + j * 256;
        CP_ASYNC16(sb + PG_W + i * 16, ph + i * 16);
        CP_ASYNC16(sb + PG_W + PG_LOSEP + i * 16, pl + i * 16);
    }
    CP_COMMIT();
}

__device__ __forceinline__ void gemm64(uint32_t sb, int lane, int wm, int wn,
                                       float (&dd)[2][2][4]) {
    uint32_t bh[2][2][2], bl[2][2][2];
    uint32_t ah[2][2][4], al[2][2][4];

    const int gq = lane >> 3;
    const int rowq = wn * 16 + ((gq >> 1) << 3) + (lane & 7);
    const int rra0 = wm * 32 + (lane & 15);
    const int rra1 = rra0 + 16;
    const int bksel = gq & 1;
    const int aksel = lane >> 4;

    #define LD_B64(buf, ksv)                                                               \
    {                                                                                      \
        int chq = 2 * (ksv) + bksel;                                                       \
        uint32_t adq = sb + PG_W + sw_off(rowq, chq);                                      \
        uint32_t r4[4];                                                                    \
        LDSM_X4(r4, adq);                                                                  \
        bh[buf][0][0] = r4[0]; bh[buf][0][1] = r4[1]; bh[buf][1][0] = r4[2]; bh[buf][1][1] = r4[3]; \
        LDSM_X4(r4, adq + PG_LOSEP);                                                       \
        bl[buf][0][0] = r4[0]; bl[buf][0][1] = r4[1]; bl[buf][1][0] = r4[2]; bl[buf][1][1] = r4[3]; \
    }
    #define LD_A64(buf, ksv)                                                               \
    {                                                                                      \
        int ch = 2 * (ksv) + aksel;                                                        \
        uint32_t ad = sb + PG_A + sw_off(rra0, ch);                                        \
        LDSM_X4(ah[buf][0], ad);                                                           \
        LDSM_X4(al[buf][0], ad + PG_LOSEP);                                                \
        ad = sb + PG_A + sw_off(rra1, ch);                                                 \
        LDSM_X4(ah[buf][1], ad);                                                           \
        LDSM_X4(al[buf][1], ad + PG_LOSEP);                                                \
    }

    LD_B64(0, 0)
    LD_A64(0, 0)
    #pragma unroll
    for (int ks = 0; ks < 8; ks++) {
        const int cur = ks & 1, nxt = cur ^ 1;
        if (ks < 7) {
            LD_B64(nxt, ks + 1)
            LD_A64(nxt, ks + 1)
        }
        #pragma unroll
        for (int nt = 0; nt < 2; nt++) {
            MMA_BF16(dd[0][nt], ah[cur][0], bh[cur][nt]);
            MMA_BF16(dd[1][nt], ah[cur][1], bh[cur][nt]);
        }
        #pragma unroll
        for (int nt = 0; nt < 2; nt++) {
            MMA_BF16(dd[0][nt], ah[cur][0], bl[cur][nt]);
            MMA_BF16(dd[1][nt], ah[cur][1], bl[cur][nt]);
        }
        #pragma unroll
        for (int nt = 0; nt < 2; nt++) {
            MMA_BF16(dd[0][nt], al[cur][0], bh[cur][nt]);
            MMA_BF16(dd[1][nt], al[cur][1], bh[cur][nt]);
        }
    }
    #undef LD_B64
    #undef LD_A64
}

__global__ __launch_bounds__(256, 2) void k_pregemmH(
    const float* __restrict__ sx, const float* __restrict__ rx,
    const float* __restrict__ eb1)
{
    extern __shared__ char smc[];
    const uint32_t sb = smem_to_u32(smc);
    const int tid = threadIdx.x;
    const int lane = tid & 31, wid = tid >> 5;
    const int wm = wid >> 2, wn = wid & 3;
    const int row0 = blockIdx.x * 64;
    const int isB = blockIdx.z;

    const float* X = isB ? rx : sx;
    const __nv_bfloat16* wh = isB ? g_wBh : g_wAh;
    const __nv_bfloat16* wl = isB ? g_wBl : g_wAl;
    float* O = isB ? g_B : g_A;

    stage_w64(sb, wh, wl, tid);

    for (int idx = tid; idx < 64 * 32; idx += 256) {
        int r = idx >> 5, c4 = idx & 31;
        float4 v = *(const float4*)(X + (size_t)(row0 + r) * 128 + c4 * 4);
        unsigned short h0, l0, h1, l1, h2, l2, h3, l3;
        split2(v.x, h0, l0); split2(v.y, h1, l1); split2(v.z, h2, l2); split2(v.w, h3, l3);
        uint2 ph, pl;
        ph.x = (uint32_t)h0 | ((uint32_t)h1 << 16); ph.y = (uint32_t)h2 | ((uint32_t)h3 << 16);
        pl.x = (uint32_t)l0 | ((uint32_t)l1 << 16); pl.y = (uint32_t)l2 | ((uint32_t)l3 << 16);
        uint32_t off = sw_off(r, c4 >> 1) + (c4 & 1) * 8;
        *(uint2*)(smc + PG_A + off) = ph;
        *(uint2*)(smc + PG_A + PG_LOSEP + off) = pl;
    }
    CP_WAIT0();
    __syncthreads();

    #pragma unroll 1
    for (int cc = 0; cc < 4; cc++) {
        float dd[2][2][4];
        #pragma unroll
        for (int a = 0; a < 2; a++)
            #pragma unroll
            for (int b = 0; b < 2; b++)
                #pragma unroll
                for (int q = 0; q < 4; q++) dd[a][b][q] = 0.f;

        gemm64(sb, lane, wm, wn, dd);
        __syncthreads();
        if (cc < 3) stage_w64(sb, wh + (cc + 1) * 8192, wl + (cc + 1) * 8192, tid);

        #pragma unroll
        for (int mt = 0; mt < 2; mt++) {
            int r1 = wm * 32 + mt * 16 + (lane >> 2);
            int r2 = r1 + 8;
            #pragma unroll
            for (int nt = 0; nt < 2; nt++) {
                int col = wn * 16 + nt * 8 + 2 * (lane & 3);
                int gc = cc * 64 + col;
                float b0 = 0.f, b1 = 0.f;
                if (isB) {
                    float2 bb = *(const float2*)(eb1 + gc);
                    b0 = bb.x; b1 = bb.y;
                }
                *(float2*)(O + (size_t)(row0 + r1) * HHID + gc) =
                    make_float2(dd[mt][nt][0] + b0, dd[mt][nt][1] + b1);
                *(float2*)(O + (size_t)(row0 + r2) * HHID + gc) =
                    make_float2(dd[mt][nt][2] + b0, dd[mt][nt][3] + b1);
            }
        }
        if (cc < 3) {
            CP_WAIT0();
            __syncthreads();
        }
    }
}

// ==================== FFMA pregemmR (node receiver-half, overlapped) ====================
#define FMA44(A_, xv, wv)                                                              \
    A_[0][0] += xv.x * wv.x; A_[0][1] += xv.x * wv.y; A_[0][2] += xv.x * wv.z; A_[0][3] += xv.x * wv.w; \
    A_[1][0] += xv.y * wv.x; A_[1][1] += xv.y * wv.y; A_[1][2] += xv.y * wv.z; A_[1][3] += xv.y * wv.w; \
    A_[2][0] += xv.z * wv.x; A_[2][1] += xv.z * wv.y; A_[2][2] += xv.z * wv.z; A_[2][3] += xv.z * wv.w; \
    A_[3][0] += xv.w * wv.x; A_[3][1] += xv.w * wv.y; A_[3][2] += xv.w * wv.z; A_[3][3] += xv.w * wv.w;

#define FMAROW(yy, hx)                                                  \
    yy[0] += hx * w0.x; yy[1] += hx * w0.y; yy[2] += hx * w0.z; yy[3] += hx * w0.w; \
    yy[4] += hx * w1v.x; yy[5] += hx * w1v.y; yy[6] += hx * w1v.z; yy[7] += hx * w1v.w;

__global__ __launch_bounds__(256) void k_pregemmR(
    const float* __restrict__ rx, const float* __restrict__ nw1, const float* __restrict__ nb1)
{
    extern __shared__ float sm[];
    float* Xs = sm;
    float* Ws = sm + 128 * 68;
    int tid = threadIdx.x;
    int row0 = blockIdx.x * 64;
    int h0 = blockIdx.y * 64;

    for (int idx = tid; idx < 64 * 32; idx += 256) {
        int r = idx >> 5, k4 = idx & 31;
        float4 v = *(const float4*)&rx[(size_t)(row0 + r) * 128 + k4 * 4];
        Xs[(k4 * 4 + 0) * 68 + r] = v.x;
        Xs[(k4 * 4 + 1) * 68 + r] = v.y;
        Xs[(k4 * 4 + 2) * 68 + r] = v.z;
        Xs[(k4 * 4 + 3) * 68 + r] = v.w;
    }
    for (int idx = tid; idx < 128 * 16; idx += 256) {
        int k = idx >> 4, c4 = idx & 15;
        *(float4*)&Ws[k * 68 + c4 * 4] = *(const float4*)&nw1[(size_t)k * HHID + h0 + c4 * 4];
    }
    __syncthreads();

    int tx = tid & 15, ty = tid >> 4;
    float acc[4][4] = {};
    #pragma unroll 4
    for (int k = 0; k < 128; k++) {
        float4 xv = *(const float4*)&Xs[k * 68 + ty * 4];
        float4 wv = *(const float4*)&Ws[k * 68 + tx * 4];
        FMA44(acc, xv, wv)
    }
    #pragma unroll
    for (int i = 0; i < 4; i++) {
        float4 o = make_float4(acc[i][0], acc[i][1], acc[i][2], acc[i][3]);
        o.x += nb1[h0 + tx * 4 + 0];
        o.y += nb1[h0 + tx * 4 + 1];
        o.z += nb1[h0 + tx * 4 + 2];
        o.w += nb1[h0 + tx * 4 + 3];
        *(float4*)&g_R[(size_t)(row0 + ty * 4 + i) * HHID + h0 + tx * 4] = o;
    }
}

// ==================== FFMA fused sender (overlapped under edge) ====================
__global__ __launch_bounds__(256) void k_sender(
    const float* __restrict__ Xin,
    const float* __restrict__ w1, const float* __restrict__ b1,
    const float* __restrict__ w2, const float* __restrict__ b2,
    const float* __restrict__ gam, const float* __restrict__ bet,
    float* __restrict__ out)
{
    extern __shared__ float sm[];
    float* Xs = sm;
    float* Ws = Xs + 128 * 68;
    float* Hs = Ws + 128 * 68;

    int tid = threadIdx.x;
    int row0 = blockIdx.x * 64;

    for (int idx = tid; idx < 64 * 32; idx += 256) {
        int r = idx >> 5, k4 = idx & 31;
        float4 v = *(const float4*)&Xin[(size_t)(row0 + r) * 128 + k4 * 4];
        Xs[(k4 * 4 + 0) * 68 + r] = v.x;
        Xs[(k4 * 4 + 1) * 68 + r] = v.y;
        Xs[(k4 * 4 + 2) * 68 + r] = v.z;
        Xs[(k4 * 4 + 3) * 68 + r] = v.w;
    }
    __syncthreads();

    int tx = tid & 15, ty = tid >> 4;
    float y[4][8] = {};

    #pragma unroll 1
    for (int hc = 0; hc < 4; hc++) {
        int h0 = hc * 64;
        for (int idx = tid; idx < 128 * 16; idx += 256) {
            int k = idx >> 4, c4 = idx & 15;
            *(float4*)&Ws[k * 68 + c4 * 4] = *(const float4*)&w1[(size_t)k * HHID + h0 + c4 * 4];
        }
        __syncthreads();

        float h[4][4] = {};
        #pragma unroll 4
        for (int k = 0; k < 128; k++) {
            float4 xv = *(const float4*)&Xs[k * 68 + ty * 4];
            float4 wv = *(const float4*)&Ws[k * 68 + tx * 4];
            FMA44(h, xv, wv)
        }

        float4 bv = *(const float4*)&b1[h0 + tx * 4];
        #pragma unroll
        for (int i = 0; i < 4; i++) {
            h[i][0] += bv.x; h[i][1] += bv.y; h[i][2] += bv.z; h[i][3] += bv.w;
        }

        #pragma unroll
        for (int j = 0; j < 4; j++) {
            float4 hv;
            hv.x = siluf(h[0][j]);
            hv.y = siluf(h[1][j]);
            hv.z = siluf(h[2][j]);
            hv.w = siluf(h[3][j]);
            *(float4*)&Hs[(tx * 4 + j) * 68 + ty * 4] = hv;
        }
        __syncthreads();

        for (int idx = tid; idx < 64 * 32; idx += 256) {
            int k = idx >> 5, c4 = idx & 31;
            *(float4*)&Ws[k * 132 + c4 * 4] = *(const float4*)&w2[(size_t)(h0 + k) * 128 + c4 * 4];
        }
        __syncthreads();

        #pragma unroll 2
        for (int k = 0; k < 64; k++) {
            float4 hv = *(const float4*)&Hs[k * 68 + ty * 4];
            float4 w0 = *(const float4*)&Ws[k * 132 + tx * 8];
            float4 w1v = *(const float4*)&Ws[k * 132 + tx * 8 + 4];
            FMAROW(y[0], hv.x)
            FMAROW(y[1], hv.y)
            FMAROW(y[2], hv.z)
            FMAROW(y[3], hv.w)
        }
        __syncthreads();
    }

    float b2r[8], gr[8], br[8];
    #pragma unroll
    for (int c = 0; c < 8; c++) {
        b2r[c] = b2[tx * 8 + c];
        gr[c] = gam[tx * 8 + c];
        br[c] = bet[tx * 8 + c];
    }
    #pragma unroll
    for (int i = 0; i < 4; i++) {
        #pragma unroll
        for (int c = 0; c < 8; c++) y[i][c] += b2r[c];

        float s1 = 0.f, s2 = 0.f;
        #pragma unroll
        for (int c = 0; c < 8; c++) { float v = y[i][c]; s1 += v; s2 += v * v; }
        #pragma unroll
        for (int m = 8; m >= 1; m >>= 1) {
            s1 += __shfl_xor_sync(0xffffffffu, s1, m);
            s2 += __shfl_xor_sync(0xffffffffu, s2, m);
        }
        float mu = s1 * (1.0f / 128.0f);
        float rs = rsqrtf(s2 * (1.0f / 128.0f) - mu * mu + LNEPS);

        int r = ty * 4 + i;
        float o[8];
        #pragma unroll
        for (int c = 0; c < 8; c++)
            o[c] = (y[i][c] - mu) * rs * gr[c] + br[c] + Xs[(tx * 8 + c) * 68 + r];
        size_t gout = (size_t)(row0 + r) * 128 + tx * 8;
        *(float4*)&out[gout]     = make_float4(o[0], o[1], o[2], o[3]);
        *(float4*)&out[gout + 4] = make_float4(o[4], o[5], o[6], o[7]);
    }
}

// ==================== HMMA MLP kernel (fp16 2-pass): MODE 0 = edge, 1 = node ====================
#define OFF_SIDX   0
#define OFF_DIDX   512
#define OFF_P1     1024
#define OFF_P2     3072
#define OFF_A_HI   5120       // A hi 32K, lo at +32768; later H_c1; later MSG
#define OFF_MSG    5120
#define OFF_W      70656      // fp16 W chunk, 32K
#define OFF_H_HI   103424     // H hi 32K, lo at +32768
#define SM_EDGE    168960

// stage one fp16 W chunk (32KB)
__device__ __forceinline__ void stage_w(uint32_t sb, const __half* g, int tid) {
    const char* p = (const char*)g;
    #pragma unroll
    for (int j = 0; j < 4; j++) {
        int i = tid + j * 512;
        CP_ASYNC16(sb + OFF_W + i * 16, p + i * 16);
    }
    CP_COMMIT();
}

// dd += A(128x128, hi/lo fp16 exact-split) @ W^T(128x128, single fp16); 2-pass, pipelined
__device__ __forceinline__ void gemm_phase(uint32_t sb, int lane, int wm, int wn,
                                           uint32_t baseA, float (&dd)[2][4][4]) {
    uint32_t bf[2][4][2];
    uint32_t ah[2][2][4], al[2][2][4];

    const int gq = lane >> 3;
    const int rowq0 = wn * 32 + ((gq >> 1) << 3) + (lane & 7);
    const int rowq1 = rowq0 + 16;
    const int rra0 = wm * 32 + (lane & 15);
    const int rra1 = rra0 + 16;
    const int bksel = gq & 1;
    const int aksel = lane >> 4;

    #define LD_B(buf, ksv)                                                                 \
    {                                                                                      \
        int chq = 2 * (ksv) + bksel;                                                       \
        uint32_t adq = sb + OFF_W + sw_off(rowq0, chq);                                    \
        uint32_t r4[4];                                                                    \
        LDSM_X4(r4, adq);                                                                  \
        bf[buf][0][0] = r4[0]; bf[buf][0][1] = r4[1]; bf[buf][1][0] = r4[2]; bf[buf][1][1] = r4[3]; \
        adq = sb + OFF_W + sw_off(rowq1, chq);                                             \
        LDSM_X4(r4, adq);                                                                  \
        bf[buf][2][0] = r4[0]; bf[buf][2][1] = r4[1]; bf[buf][3][0] = r4[2]; bf[buf][3][1] = r4[3]; \
    }
    #define LD_A(buf, ksv)                                                                 \
    {                                                                                      \
        int ch = 2 * (ksv) + aksel;                                                        \
        uint32_t ad = sb + baseA + sw_off(rra0, ch);                                       \
        LDSM_X4(ah[buf][0], ad);                                                           \
        LDSM_X4(al[buf][0], ad + 32768);                                                   \
        ad = sb + baseA + sw_off(rra1, ch);                                                \
        LDSM_X4(ah[buf][1], ad);                                                           \
        LDSM_X4(al[buf][1], ad + 32768);                                                   \
    }

    LD_B(0, 0)
    LD_A(0, 0)
    #pragma unroll
    for (int ks = 0; ks < 8; ks++) {
        const int cur = ks & 1, nxt = cur ^ 1;
        if (ks < 7) {
            LD_B(nxt, ks + 1)
            LD_A(nxt, ks + 1)
        }
        #pragma unroll
        for (int nt = 0; nt < 4; nt++) {
            MMA_FP16(dd[0][nt], ah[cur][0], bf[cur][nt]);
            MMA_FP16(dd[1][nt], ah[cur][1], bf[cur][nt]);
        }
        #pragma unroll
        for (int nt = 0; nt < 4; nt++) {
            MMA_FP16(dd[0][nt], al[cur][0], bf[cur][nt]);
            MMA_FP16(dd[1][nt], al[cur][1], bf[cur][nt]);
        }
    }
    #undef LD_B
    #undef LD_A
}

// epi1: MODE 0: D1 + gA[src] + gB[dst]; MODE 1: D1 + gA[row] (gA = g_R)
template <int MODE>
__device__ __forceinline__ void epi1_phase(char* smc, const int* sidx_s, const int* didx_s,
    const float* gA, const float* gB, float (&d1)[2][4][4],
    int wm, int wn, int lane, int c, uint32_t dstHi, int row0)
{
    #pragma unroll
    for (int mt = 0; mt < 2; mt++) {
        int r1 = wm * 32 + mt * 16 + (lane >> 2);
        int r2 = r1 + 8;
        int si1, di1, si2, di2;
        if (MODE == 0) {
            si1 = sidx_s[r1]; di1 = didx_s[r1];
            si2 = sidx_s[r2]; di2 = didx_s[r2];
        } else {
            si1 = row0 + r1; if (si1 >= NNODE) si1 = NNODE - 1;
            si2 = row0 + r2; if (si2 >= NNODE) si2 = NNODE - 1;
            di1 = di2 = 0;
        }
        #pragma unroll
        for (int nt = 0; nt < 4; nt++) {
            int cpl = wn * 32 + nt * 8 + 2 * (lane & 3);
            int gc = c * 128 + cpl;
            float2 a1 = *(const float2*)(gA + (size_t)si1 * HHID + gc);
            float2 a2 = *(const float2*)(gA + (size_t)si2 * HHID + gc);
            float g10 = a1.x, g11 = a1.y, g20 = a2.x, g21 = a2.y;
            if (MODE == 0) {
                float2 bb1 = *(const float2*)(gB + (size_t)di1 * HHID + gc);
                float2 bb2 = *(const float2*)(gB + (size_t)di2 * HHID + gc);
                g10 += bb1.x; g11 += bb1.y; g20 += bb2.x; g21 += bb2.y;
            }
            float h00 = siluf(d1[mt][nt][0] + g10);
            float h01 = siluf(d1[mt][nt][1] + g11);
            float h10 = siluf(d1[mt][nt][2] + g20);
            float h11 = siluf(d1[mt][nt][3] + g21);
            unsigned short p0h, p0l, p1h, p1l, q0h, q0l, q1h, q1l;
            split2h(h00, p0h, p0l); split2h(h01, p1h, p1l);
            split2h(h10, q0h, q0l); split2h(h11, q1h, q1l);
            uint32_t o1 = sw_off(r1, (cpl >> 3)) + (cpl & 7) * 2;
            uint32_t o2 = sw_off(r2, (cpl >> 3)) + (cpl & 7) * 2;
            *(uint32_t*)(smc + dstHi + o1)         = (uint32_t)p0h | ((uint32_t)p1h << 16);
            *(uint32_t*)(smc + dstHi + 32768 + o1) = (uint32_t)p0l | ((uint32_t)p1l << 16);
            *(uint32_t*)(smc + dstHi + o2)         = (uint32_t)q0h | ((uint32_t)q1h << 16);
            *(uint32_t*)(smc + dstHi + 32768 + o2) = (uint32_t)q0l | ((uint32_t)q1l << 16);
        }
    }
}

template <int MODE>
__global__ __launch_bounds__(512, 1) void k_mlp(
    const float* __restrict__ Ain, const void* __restrict__ ei,
    const float* __restrict__ gA, const float* __restrict__ gB,
    const __half* __restrict__ w1f, const __half* __restrict__ w2f,
    const float* __restrict__ b2, const float* __restrict__ gam, const float* __restrict__ bet,
    const float* __restrict__ resid, float* __restrict__ out, float* __restrict__ agg)
{
    extern __shared__ char smc[];
    const uint32_t sb = smem_to_u32(smc);
    const int tid = threadIdx.x;
    const int lane = tid & 31, wid = tid >> 5;
    const int wm = wid >> 2, wn = wid & 3;
    const int row0 = blockIdx.x * 128;

    stage_w(sb, w1f, tid);

    int* sidx_s = (int*)(smc + OFF_SIDX);
    int* didx_s = (int*)(smc + OFF_DIDX);
    float* rc_s = (float*)(smc + OFF_SIDX);

    if (MODE == 0) {
        if (tid < 128) {
            sidx_s[tid] = eidx(ei, (long long)(row0 + tid));
            didx_s[tid] = eidx(ei, (long long)EEDGE + row0 + tid);
        }
    } else {
        if (tid < 128) {
            int rr = row0 + tid; if (rr >= NNODE) rr = NNODE - 1;
            int cval = g_cnt[rr];
            rc_s[tid] = 1.0f / (float)(cval > 1 ? cval : 1);
        }
        __syncthreads();
    }

    // A tile -> fp16 hi/lo exact-split swizzled
    for (int idx = tid; idx < 128 * 32; idx += 512) {
        int r = idx >> 5, c4 = idx & 31;
        int gr = row0 + r;
        if (MODE == 1 && gr >= NNODE) gr = NNODE - 1;
        float4 v = *(const float4*)(Ain + (size_t)gr * 128 + c4 * 4);
        if (MODE == 1) {
            float s = rc_s[r];
            v.x *= s; v.y *= s; v.z *= s; v.w *= s;
        }
        unsigned short h0, l0, h1, l1, h2, l2, h3, l3;
        split2h(v.x, h0, l0); split2h(v.y, h1, l1); split2h(v.z, h2, l2); split2h(v.w, h3, l3);
        uint2 ph, pl;
        ph.x = (uint32_t)h0 | ((uint32_t)h1 << 16); ph.y = (uint32_t)h2 | ((uint32_t)h3 << 16);
        pl.x = (uint32_t)l0 | ((uint32_t)l1 << 16); pl.y = (uint32_t)l2 | ((uint32_t)l3 << 16);
        uint32_t off = sw_off(r, c4 >> 1) + (c4 & 1) * 8;
        *(uint2*)(smc + OFF_A_HI + off) = ph;
        *(uint2*)(smc + OFF_A_HI + 32768 + off) = pl;
    }
    CP_WAIT0();
    __syncthreads();

    float d1[2][4][4];
    #pragma unroll
    for (int a = 0; a < 2; a++)
        #pragma unroll
        for (int b = 0; b < 4; b++)
            #pragma unroll
            for (int q = 0; q < 4; q++) d1[a][b][q] = 0.f;

    // G1 c0
    gemm_phase(sb, lane, wm, wn, OFF_A_HI, d1);
    __syncthreads();
    stage_w(sb, w1f + 16384, tid);
    epi1_phase<MODE>(smc, sidx_s, didx_s, gA, gB, d1, wm, wn, lane, 0, OFF_H_HI, row0);
    CP_WAIT0();
    __syncthreads();

    // G1 c1
    #pragma unroll
    for (int a = 0; a < 2; a++)
        #pragma unroll
        for (int b = 0; b < 4; b++)
            #pragma unroll
            for (int q = 0; q < 4; q++) d1[a][b][q] = 0.f;
    gemm_phase(sb, lane, wm, wn, OFF_A_HI, d1);
    __syncthreads();
    stage_w(sb, w2f, tid);
    epi1_phase<MODE>(smc, sidx_s, didx_s, gA, gB, d1, wm, wn, lane, 1, OFF_A_HI, row0);
    CP_WAIT0();
    __syncthreads();

    // G2 c0
    float d2[2][4][4];
    #pragma unroll
    for (int a = 0; a < 2; a++)
        #pragma unroll
        for (int b = 0; b < 4; b++)
            #pragma unroll
            for (int q = 0; q < 4; q++) d2[a][b][q] = 0.f;
    gemm_phase(sb, lane, wm, wn, OFF_H_HI, d2);
    __syncthreads();
    stage_w(sb, w2f + 16384, tid);
    CP_WAIT0();
    __syncthreads();

    // G2 c1 (H_c1 lives in A region)
    gemm_phase(sb, lane, wm, wn, OFF_A_HI, d2);

    // ---- epi2: +b2, LayerNorm, residual, store (+ messages for MODE 0) ----
    float b2v[4][2], gmv[4][2], btv[4][2];
    #pragma unroll
    for (int nt = 0; nt < 4; nt++) {
        int col = wn * 32 + nt * 8 + 2 * (lane & 3);
        float2 t;
        t = *(const float2*)(b2 + col);  b2v[nt][0] = t.x; b2v[nt][1] = t.y;
        t = *(const float2*)(gam + col); gmv[nt][0] = t.x; gmv[nt][1] = t.y;
        t = *(const float2*)(bet + col); btv[nt][0] = t.x; btv[nt][1] = t.y;
    }
    float* p1 = (float*)(smc + OFF_P1);
    float* p2 = (float*)(smc + OFF_P2);

    #pragma unroll
    for (int mt = 0; mt < 2; mt++) {
        int r1 = wm * 32 + mt * 16 + (lane >> 2);
        int r2 = r1 + 8;
        float s1a = 0.f, s2a = 0.f, s1b = 0.f, s2b = 0.f;
        #pragma unroll
        for (int nt = 0; nt < 4; nt++) {
            float y0 = d2[mt][nt][0] + b2v[nt][0];
            float y1 = d2[mt][nt][1] + b2v[nt][1];
            float y2 = d2[mt][nt][2] + b2v[nt][0];
            float y3 = d2[mt][nt][3] + b2v[nt][1];
            d2[mt][nt][0] = y0; d2[mt][nt][1] = y1; d2[mt][nt][2] = y2; d2[mt][nt][3] = y3;
            s1a += y0 + y1; s2a += y0 * y0 + y1 * y1;
            s1b += y2 + y3; s2b += y2 * y2 + y3 * y3;
        }
        #pragma unroll
        for (int m = 1; m <= 2; m <<= 1) {
            s1a += __shfl_xor_sync(0xffffffffu, s1a, m);
            s2a += __shfl_xor_sync(0xffffffffu, s2a, m);
            s1b += __shfl_xor_sync(0xffffffffu, s1b, m);
            s2b += __shfl_xor_sync(0xffffffffu, s2b, m);
        }
        if ((lane & 3) == 0) {
            p1[r1 * 4 + wn] = s1a; p2[r1 * 4 + wn] = s2a;
            p1[r2 * 4 + wn] = s1b; p2[r2 * 4 + wn] = s2b;
        }
    }
    __syncthreads();

    float* msg = (float*)(smc + OFF_MSG);
    #pragma unroll
    for (int mt = 0; mt < 2; mt++) {
        int r1 = wm * 32 + mt * 16 + (lane >> 2);
        int r2 = r1 + 8;
        float4 q1 = *(float4*)&p1[r1 * 4];
        float4 v1 = *(float4*)&p2[r1 * 4];
        float4 q2 = *(float4*)&p1[r2 * 4];
        float4 v2 = *(float4*)&p2[r2 * 4];
        float mu1 = (q1.x + q1.y + q1.z + q1.w) * (1.0f / 128.0f);
        float mu2 = (q2.x + q2.y + q2.z + q2.w) * (1.0f / 128.0f);
        float rs1 = rsqrtf((v1.x + v1.y + v1.z + v1.w) * (1.0f / 128.0f) - mu1 * mu1 + LNEPS);
        float rs2 = rsqrtf((v2.x + v2.y + v2.z + v2.w) * (1.0f / 128.0f) - mu2 * mu2 + LNEPS);
        bool w1ok = (MODE == 0) || (row0 + r1 < NNODE);
        bool w2ok = (MODE == 0) || (row0 + r2 < NNODE);
        #pragma unroll
        for (int nt = 0; nt < 4; nt++) {
            int col = wn * 32 + nt * 8 + 2 * (lane & 3);
            float pa0 = (d2[mt][nt][0] - mu1) * rs1 * gmv[nt][0] + btv[nt][0];
            float pa1 = (d2[mt][nt][1] - mu1) * rs1 * gmv[nt][1] + btv[nt][1];
            float pb0 = (d2[mt][nt][2] - mu2) * rs2 * gmv[nt][0] + btv[nt][0];
            float pb1 = (d2[mt][nt][3] - mu2) * rs2 * gmv[nt][1] + btv[nt][1];
            if (w1ok) {
                float2 x1 = *(const float2*)(resid + (size_t)(row0 + r1) * 128 + col);
                *(float2*)(out + (size_t)(row0 + r1) * 128 + col) = make_float2(pa0 + x1.x, pa1 + x1.y);
            }
            if (w2ok) {
                float2 x2 = *(const float2*)(resid + (size_t)(row0 + r2) * 128 + col);
                *(float2*)(out + (size_t)(row0 + r2) * 128 + col) = make_float2(pb0 + x2.x, pb1 + x2.y);
            }
            if (MODE == 0) {
                *(float2*)(msg + r1 * 128 + col) = make_float2(pa0, pa1);
                *(float2*)(msg + r2 * 128 + col) = make_float2(pb0, pb1);
            }
        }
    }

    if (MODE == 0) {
        FENCE_ASYNC();
        __syncthreads();
        if (tid < 128) {
            float* gdst = agg + (size_t)didx_s[tid] * 128;
            bulk_reduce_add_f32(gdst, sb + OFF_MSG + (uint32_t)tid * 512, 512);
            asm volatile("cp.async.bulk.commit_group;" ::: "memory");
            asm volatile("cp.async.bulk.wait_group 0;" ::: "memory");
        }
    }
}

// ==================== launcher ====================
extern "C" void kernel_launch(void* const* d_in, const int* in_sizes, int n_in,
                              void* d_out, int out_size) {
    (void)in_sizes; (void)n_in; (void)out_size;
    const float* sender_x   = (const float*)d_in[0];
    const float* receiver_x = (const float*)d_in[1];
    const float* edge_attr  = (const float*)d_in[2];
    const void*  ei         = d_in[3];
    const float* ew1  = (const float*)d_in[4];
    const float* eb1  = (const float*)d_in[5];
    const float* ew2  = (const float*)d_in[6];
    const float* eb2  = (const float*)d_in[7];
    const float* eg   = (const float*)d_in[8];
    const float* ebt  = (const float*)d_in[9];
    const float* nw1  = (const float*)d_in[10];
    const float* nb1  = (const float*)d_in[11];
    const float* nw2  = (const float*)d_in[12];
    const float* nb2  = (const float*)d_in[13];
    const float* ng   = (const float*)d_in[14];
    const float* nbt  = (const float*)d_in[15];
    const float* sw1  = (const float*)d_in[16];
    const float* sb1  = (const float*)d_in[17];
    const float* sw2  = (const float*)d_in[18];
    const float* sb2  = (const float*)d_in[19];
    const float* sg   = (const float*)d_in[20];
    const float* sbt  = (const float*)d_in[21];

    float* out = (float*)d_out;
    float* out_send = out;
    float* out_recv = out + (size_t)NNODE * DD;
    float* out_edge = out + (size_t)2 * NNODE * DD;

    void *pA, *pB, *pR, *pAgg, *pw1f, *pw2f, *pn1f, *pn2f;
    cudaGetSymbolAddress(&pA, g_A);
    cudaGetSymbolAddress(&pB, g_B);
    cudaGetSymbolAddress(&pR, g_R);
    cudaGetSymbolAddress(&pAgg, g_agg);
    cudaGetSymbolAddress(&pw1f, g_w1f);
    cudaGetSymbolAddress(&pw2f, g_w2f);
    cudaGetSymbolAddress(&pn1f, g_nw1f);
    cudaGetSymbolAddress(&pn2f, g_nw2f);

    static cudaStream_t s2 = nullptr;
    static cudaEvent_t evS = nullptr, evP = nullptr, evJ = nullptr;
    if (s2 == nullptr) {
        cudaStreamCreateWithFlags(&s2, cudaStreamNonBlocking);
        cudaEventCreateWithFlags(&evS, cudaEventDisableTiming);
        cudaEventCreateWithFlags(&evP, cudaEventDisableTiming);
        cudaEventCreateWithFlags(&evJ, cudaEventDisableTiming);
    }

    const int SM_PRE = (128 * 68 + 128 * 68) * 4;
    const int SM_FU  = (128 * 68 + 128 * 68 + 64 * 68 + 64) * 4;
    cudaFuncSetAttribute(k_pregemmH, cudaFuncAttributeMaxDynamicSharedMemorySize, SM_PG);
    cudaFuncSetAttribute(k_pregemmR, cudaFuncAttributeMaxDynamicSharedMemorySize, SM_PRE);
    cudaFuncSetAttribute(k_sender,   cudaFuncAttributeMaxDynamicSharedMemorySize, SM_FU);
    cudaFuncSetAttribute(k_mlp<0>,   cudaFuncAttributeMaxDynamicSharedMemorySize, SM_EDGE);
    cudaFuncSetAttribute(k_mlp<1>,   cudaFuncAttributeMaxDynamicSharedMemorySize, SM_EDGE);

    // launch 1: weight prep + cnt zero + dtype detect (main)
    k_prepw<<<157, 256>>>(ew1, ew2, nw1, nw2, ei);
    cudaEventRecord(evS, 0);
    // launch 2: HMMA pregemm A/B on side stream
    cudaStreamWaitEvent(s2, evS, 0);
    k_pregemmH<<<dim3(NNODE / 64, 1, 2), 256, SM_PG, s2>>>(sender_x, receiver_x, eb1);
    // launch 3: zero agg + degree count (main)
    k_initcount<<<(NNODE * DD) / 256, 256>>>(ei);
    cudaEventRecord(evP, s2);
    cudaStreamWaitEvent(0, evP, 0);
    // launch 4 (ncu slot): edge kernel
    k_mlp<0><<<EEDGE / 128, 512, SM_EDGE>>>(
        edge_attr, ei, (const float*)pA, (const float*)pB,
        (const __half*)pw1f, (const __half*)pw2f,
        eb2, eg, ebt, edge_attr, out_edge, (float*)pAgg);
    // side stream overlaps edge: sender MLP + node receiver-half precompute
    k_sender<<<NNODE / 64, 256, SM_FU, s2>>>(sender_x, sw1, sb1, sw2, sb2, sg, sbt, out_send);
    k_pregemmR<<<dim3(NNODE / 64, 4), 256, SM_PRE, s2>>>(receiver_x, nw1, nb1);
    cudaEventRecord(evJ, s2);
    cudaStreamWaitEvent(0, evJ, 0);
    // node MLP (HMMA fp16 2-pass): agg-dependent half, g_R gathered densely
    k_mlp<1><<<(NNODE + 127) / 128, 512, SM_EDGE>>>(
        (const float*)pAgg, nullptr, (const float*)pR, nullptr,
        (const __half*)pn1f, (const __half*)pn2f,
        nb2, ng, nbt, receiver_x, out_recv, nullptr);
}

// round 13
// speedup vs baseline: 1.5356x; 1.1053x over previous
#include <cuda_runtime.h>
#include <cuda_bf16.h>
#include <cuda_fp16.h>
#include <math.h>
#include <cstdint>

#define NNODE 40000
#define EEDGE 640000
#define DD    128
#define HHID  256
#define LNEPS 1e-5f

// ==================== device scratch (allocation-free) ====================
__device__ __align__(128) float g_A[(size_t)NNODE * HHID];   // sender_x @ ew1[0:128]
__device__ __align__(128) float g_B[(size_t)NNODE * HHID];   // receiver_x @ ew1[128:256] + eb1
__device__ __align__(128) float g_R[(size_t)NNODE * HHID];   // receiver_x @ nw1[0:128] + nb1
__device__ __align__(128) float g_agg[(size_t)NNODE * DD];   // scatter-sum of edge messages
__device__ int   g_cnt[NNODE];
__device__ int   g_is64;
// fp16 single-precision weight images for the HMMA MLP kernels (2 chunks [128n][128k])
__device__ __align__(16) __half g_w1f[2 * 128 * 128];   // edge W1[256:384]^T
__device__ __align__(16) __half g_w2f[2 * 128 * 128];   // edge W2^T
__device__ __align__(16) __half g_nw1f[2 * 128 * 128];  // node W1[128:256]^T
__device__ __align__(16) __half g_nw2f[2 * 128 * 128];  // node W2^T
// bf16 hi/lo images for the high-precision pregemm (4 chunks [64n][128k])
__device__ __align__(16) __nv_bfloat16 g_wAh[4 * 64 * 128];
__device__ __align__(16) __nv_bfloat16 g_wAl[4 * 64 * 128];
__device__ __align__(16) __nv_bfloat16 g_wBh[4 * 64 * 128];
__device__ __align__(16) __nv_bfloat16 g_wBl[4 * 64 * 128];

// ==================== helpers ====================
__device__ __forceinline__ uint32_t smem_to_u32(const void* p) {
    uint32_t a;
    asm("{ .reg .u64 t; cvta.to.shared.u64 t, %1; cvt.u32.u64 %0, t; }" : "=r"(a) : "l"(p));
    return a;
}
__device__ __forceinline__ int eidx(const void* ei, long long pos) {
    return g_is64 ? (int)((const long long*)ei)[pos] : ((const int*)ei)[pos];
}
__device__ __forceinline__ float siluf(float x) { return x * (1.0f / (1.0f + __expf(-x))); }
__device__ __forceinline__ void split2(float v, unsigned short& h, unsigned short& l) {
    __nv_bfloat16 hb = __float2bfloat16(v);
    __nv_bfloat16 lb = __float2bfloat16(v - __bfloat162float(hb));
    h = __bfloat16_as_ushort(hb);
    l = __bfloat16_as_ushort(lb);
}

#define LDSM_X4(r, ad) \
    asm volatile("ldmatrix.sync.aligned.m8n8.x4.shared.b16 {%0,%1,%2,%3}, [%4];" \
        : "=r"((r)[0]), "=r"((r)[1]), "=r"((r)[2]), "=r"((r)[3]) : "r"(ad))
#define MMA_BF16(d, a, b) \
    asm volatile("mma.sync.aligned.m16n8k16.row.col.f32.bf16.bf16.f32 " \
        "{%0,%1,%2,%3}, {%4,%5,%6,%7}, {%8,%9}, {%0,%1,%2,%3};" \
        : "+f"((d)[0]), "+f"((d)[1]), "+f"((d)[2]), "+f"((d)[3]) \
        : "r"((a)[0]), "r"((a)[1]), "r"((a)[2]), "r"((a)[3]), "r"((b)[0]), "r"((b)[1]))
#define MMA_FP16(d, a, b) \
    asm volatile("mma.sync.aligned.m16n8k16.row.col.f32.f16.f16.f32 " \
        "{%0,%1,%2,%3}, {%4,%5,%6,%7}, {%8,%9}, {%0,%1,%2,%3};" \
        : "+f"((d)[0]), "+f"((d)[1]), "+f"((d)[2]), "+f"((d)[3]) \
        : "r"((a)[0]), "r"((a)[1]), "r"((a)[2]), "r"((a)[3]), "r"((b)[0]), "r"((b)[1]))

__device__ __forceinline__ void bulk_reduce_add_f32(float* gdst, uint32_t ssrc, uint32_t bytes) {
    asm volatile("cp.reduce.async.bulk.global.shared::cta.bulk_group.add.f32 [%0], [%1], %2;"
                 :: "l"(gdst), "r"(ssrc), "r"(bytes) : "memory");
}
#define FENCE_ASYNC() asm volatile("fence.proxy.async.shared::cta;" ::: "memory")
#define CP_ASYNC16(sdst, gsrc) \
    asm volatile("cp.async.cg.shared.global [%0], [%1], 16;" :: "r"(sdst), "l"(gsrc) : "memory")
#define CP_COMMIT() asm volatile("cp.async.commit_group;" ::: "memory")
#define CP_WAIT0()  asm volatile("cp.async.wait_group 0;" ::: "memory")

// swizzled tile: rows of 256B (128 b16); 16B-chunk c at row r lives at (c ^ (r&7))
__device__ __forceinline__ uint32_t sw_off(int r, int chunk) {
    return (uint32_t)(r * 256 + ((chunk ^ (r & 7)) << 4));
}

// ==================== launch 1: weight prep + cnt zero + dtype detect ====================
__global__ void k_prepw(const float* __restrict__ ew1, const float* __restrict__ ew2,
                        const float* __restrict__ nw1, const float* __restrict__ nw2,
                        const void* __restrict__ ei) {
    int i = blockIdx.x * 256 + threadIdx.x;   // grid 157*256 = 40192
    if (i == 0) {
        const long long* p = (const long long*)ei;
        int ok = 1;
        #pragma unroll
        for (int j = 0; j < 32; j++) {
            long long v = p[j];
            if (v < 0 || v >= NNODE) ok = 0;
        }
        g_is64 = ok;
    }
    if (i < NNODE) g_cnt[i] = 0;
    if (i < 32768) {
        // edge/node W1^T fp16 (2-chunk 128n): src ew1[(256+k)*256+n], nw1[(128+k)*256+n]
        {
            int n = i >> 7, k = i & 127;
            int chunk = n >> 7, r = n & 127;
            uint32_t off = (uint32_t)chunk * 32768 + sw_off(r, k >> 3) + (k & 7) * 2;
            *(unsigned short*)((char*)g_w1f + off) =
                __half_as_ushort(__float2half_rn(ew1[(size_t)(256 + k) * HHID + n]));
            *(unsigned short*)((char*)g_nw1f + off) =
                __half_as_ushort(__float2half_rn(nw1[(size_t)(128 + k) * HHID + n]));
        }
        // edge/node W2^T fp16 (2-chunk 128n): src w2[k*128+n]
        {
            int n = i & 127, k = i >> 7;
            int chunk = k >> 7, kk = k & 127;
            uint32_t off = (uint32_t)chunk * 32768 + sw_off(n, kk >> 3) + (kk & 7) * 2;
            *(unsigned short*)((char*)g_w2f + off) =
                __half_as_ushort(__float2half_rn(ew2[(size_t)k * DD + n]));
            *(unsigned short*)((char*)g_nw2f + off) =
                __half_as_ushort(__float2half_rn(nw2[(size_t)k * DD + n]));
        }
        // pregemm wA/wB bf16 hi/lo (4-chunk 64n): src ew1[k*256+n], ew1[(128+k)*256+n]
        {
            int n = i >> 7, k = i & 127;
            int chunk = n >> 6, r = n & 63;
            uint32_t off = (uint32_t)chunk * 16384 + sw_off(r, k >> 3) + (k & 7) * 2;
            unsigned short h, l;
            split2(ew1[(size_t)k * HHID + n], h, l);
            *(unsigned short*)((char*)g_wAh + off) = h;
            *(unsigned short*)((char*)g_wAl + off) = l;
            split2(ew1[(size_t)(128 + k) * HHID + n], h, l);
            *(unsigned short*)((char*)g_wBh + off) = h;
            *(unsigned short*)((char*)g_wBl + off) = l;
        }
    }
}

// ==================== launch 3: zero agg + degree count ====================
__global__ void k_initcount(const void* __restrict__ ei) {
    int i = blockIdx.x * 256 + threadIdx.x;
    g_agg[i] = 0.0f;
    if (i < EEDGE) {
        int d = eidx(ei, (long long)EEDGE + i);
        atomicAdd(&g_cnt[d], 1);
    }
}

// ==================== HMMA pregemm (bf16 3-pass, off critical path) ====================
#define PG_A     0
#define PG_W     32768
#define PG_LOSEP 16384
#define SM_PG    65536

__device__ __forceinline__ void stage_w64(uint32_t sb, const __nv_bfloat16* gh,
                                          const __nv_bfloat16* gl, int tid) {
    const char* ph = (const char*)gh;
    const char* pl = (const char*)gl;
    #pragma unroll
    for (int j = 0; j < 4; j++) {
        int i = tid + j * 256;
        CP_ASYNC16(sb + PG_W + i * 16, ph + i * 16);
        CP_ASYNC16(sb + PG_W + PG_LOSEP + i * 16, pl + i * 16);
    }
    CP_COMMIT();
}

__device__ __forceinline__ void gemm64(uint32_t sb, int lane, int wm, int wn,
                                       float (&dd)[2][2][4]) {
    uint32_t bh[2][2][2], bl[2][2][2];
    uint32_t ah[2][2][4], al[2][2][4];

    const int gq = lane >> 3;
    const int rowq = wn * 16 + ((gq >> 1) << 3) + (lane & 7);
    const int rra0 = wm * 32 + (lane & 15);
    const int rra1 = rra0 + 16;
    const int bksel = gq & 1;
    const int aksel = lane >> 4;

    #define LD_B64(buf, ksv)                                                               \
    {                                                                                      \
        int chq = 2 * (ksv) + bksel;                                                       \
        uint32_t adq = sb + PG_W + sw_off(rowq, chq);                                      \
        uint32_t r4[4];                                                                    \
        LDSM_X4(r4, adq);                                                                  \
        bh[buf][0][0] = r4[0]; bh[buf][0][1] = r4[1]; bh[buf][1][0] = r4[2]; bh[buf][1][1] = r4[3]; \
        LDSM_X4(r4, adq + PG_LOSEP);                                                       \
        bl[buf][0][0] = r4[0]; bl[buf][0][1] = r4[1]; bl[buf][1][0] = r4[2]; bl[buf][1][1] = r4[3]; \
    }
    #define LD_A64(buf, ksv)                                                               \
    {                                                                                      \
        int ch = 2 * (ksv) + aksel;                                                        \
        uint32_t ad = sb + PG_A + sw_off(rra0, ch);                                        \
        LDSM_X4(ah[buf][0], ad);                                                           \
        LDSM_X4(al[buf][0], ad + PG_LOSEP);                                                \
        ad = sb + PG_A + sw_off(rra1, ch);                                                 \
        LDSM_X4(ah[buf][1], ad);                                                           \
        LDSM_X4(al[buf][1], ad + PG_LOSEP);                                                \
    }

    LD_B64(0, 0)
    LD_A64(0, 0)
    #pragma unroll
    for (int ks = 0; ks < 8; ks++) {
        const int cur = ks & 1, nxt = cur ^ 1;
        if (ks < 7) {
            LD_B64(nxt, ks + 1)
            LD_A64(nxt, ks + 1)
        }
        #pragma unroll
        for (int nt = 0; nt < 2; nt++) {
            MMA_BF16(dd[0][nt], ah[cur][0], bh[cur][nt]);
            MMA_BF16(dd[1][nt], ah[cur][1], bh[cur][nt]);
        }
        #pragma unroll
        for (int nt = 0; nt < 2; nt++) {
            MMA_BF16(dd[0][nt], ah[cur][0], bl[cur][nt]);
            MMA_BF16(dd[1][nt], ah[cur][1], bl[cur][nt]);
        }
        #pragma unroll
        for (int nt = 0; nt < 2; nt++) {
            MMA_BF16(dd[0][nt], al[cur][0], bh[cur][nt]);
            MMA_BF16(dd[1][nt], al[cur][1], bh[cur][nt]);
        }
    }
    #undef LD_B64
    #undef LD_A64
}

__global__ __launch_bounds__(256, 2) void k_pregemmH(
    const float* __restrict__ sx, const float* __restrict__ rx,
    const float* __restrict__ eb1)
{
    extern __shared__ char smc[];
    const uint32_t sb = smem_to_u32(smc);
    const int tid = threadIdx.x;
    const int lane = tid & 31, wid = tid >> 5;
    const int wm = wid >> 2, wn = wid & 3;
    const int row0 = blockIdx.x * 64;
    const int isB = blockIdx.z;

    const float* X = isB ? rx : sx;
    const __nv_bfloat16* wh = isB ? g_wBh : g_wAh;
    const __nv_bfloat16* wl = isB ? g_wBl : g_wAl;
    float* O = isB ? g_B : g_A;

    stage_w64(sb, wh, wl, tid);

    for (int idx = tid; idx < 64 * 32; idx += 256) {
        int r = idx >> 5, c4 = idx & 31;
        float4 v = *(const float4*)(X + (size_t)(row0 + r) * 128 + c4 * 4);
        unsigned short h0, l0, h1, l1, h2, l2, h3, l3;
        split2(v.x, h0, l0); split2(v.y, h1, l1); split2(v.z, h2, l2); split2(v.w, h3, l3);
        uint2 ph, pl;
        ph.x = (uint32_t)h0 | ((uint32_t)h1 << 16); ph.y = (uint32_t)h2 | ((uint32_t)h3 << 16);
        pl.x = (uint32_t)l0 | ((uint32_t)l1 << 16); pl.y = (uint32_t)l2 | ((uint32_t)l3 << 16);
        uint32_t off = sw_off(r, c4 >> 1) + (c4 & 1) * 8;
        *(uint2*)(smc + PG_A + off) = ph;
        *(uint2*)(smc + PG_A + PG_LOSEP + off) = pl;
    }
    CP_WAIT0();
    __syncthreads();

    #pragma unroll 1
    for (int cc = 0; cc < 4; cc++) {
        float dd[2][2][4];
        #pragma unroll
        for (int a = 0; a < 2; a++)
            #pragma unroll
            for (int b = 0; b < 2; b++)
                #pragma unroll
                for (int q = 0; q < 4; q++) dd[a][b][q] = 0.f;

        gemm64(sb, lane, wm, wn, dd);
        __syncthreads();
        if (cc < 3) stage_w64(sb, wh + (cc + 1) * 8192, wl + (cc + 1) * 8192, tid);

        #pragma unroll
        for (int mt = 0; mt < 2; mt++) {
            int r1 = wm * 32 + mt * 16 + (lane >> 2);
            int r2 = r1 + 8;
            #pragma unroll
            for (int nt = 0; nt < 2; nt++) {
                int col = wn * 16 + nt * 8 + 2 * (lane & 3);
                int gc = cc * 64 + col;
                float b0 = 0.f, b1 = 0.f;
                if (isB) {
                    float2 bb = *(const float2*)(eb1 + gc);
                    b0 = bb.x; b1 = bb.y;
                }
                *(float2*)(O + (size_t)(row0 + r1) * HHID + gc) =
                    make_float2(dd[mt][nt][0] + b0, dd[mt][nt][1] + b1);
                *(float2*)(O + (size_t)(row0 + r2) * HHID + gc) =
                    make_float2(dd[mt][nt][2] + b0, dd[mt][nt][3] + b1);
            }
        }
        if (cc < 3) {
            CP_WAIT0();
            __syncthreads();
        }
    }
}

// ==================== FFMA pregemmR (node receiver-half, overlapped) ====================
#define FMA44(A_, xv, wv)                                                              \
    A_[0][0] += xv.x * wv.x; A_[0][1] += xv.x * wv.y; A_[0][2] += xv.x * wv.z; A_[0][3] += xv.x * wv.w; \
    A_[1][0] += xv.y * wv.x; A_[1][1] += xv.y * wv.y; A_[1][2] += xv.y * wv.z; A_[1][3] += xv.y * wv.w; \
    A_[2][0] += xv.z * wv.x; A_[2][1] += xv.z * wv.y; A_[2][2] += xv.z * wv.z; A_[2][3] += xv.z * wv.w; \
    A_[3][0] += xv.w * wv.x; A_[3][1] += xv.w * wv.y; A_[3][2] += xv.w * wv.z; A_[3][3] += xv.w * wv.w;

#define FMAROW(yy, hx)                                                  \
    yy[0] += hx * w0.x; yy[1] += hx * w0.y; yy[2] += hx * w0.z; yy[3] += hx * w0.w; \
    yy[4] += hx * w1v.x; yy[5] += hx * w1v.y; yy[6] += hx * w1v.z; yy[7] += hx * w1v.w;

__global__ __launch_bounds__(256) void k_pregemmR(
    const float* __restrict__ rx, const float* __restrict__ nw1, const float* __restrict__ nb1)
{
    extern __shared__ float sm[];
    float* Xs = sm;
    float* Ws = sm + 128 * 68;
    int tid = threadIdx.x;
    int row0 = blockIdx.x * 64;
    int h0 = blockIdx.y * 64;

    for (int idx = tid; idx < 64 * 32; idx += 256) {
        int r = idx >> 5, k4 = idx & 31;
        float4 v = *(const float4*)&rx[(size_t)(row0 + r) * 128 + k4 * 4];
        Xs[(k4 * 4 + 0) * 68 + r] = v.x;
        Xs[(k4 * 4 + 1) * 68 + r] = v.y;
        Xs[(k4 * 4 + 2) * 68 + r] = v.z;
        Xs[(k4 * 4 + 3) * 68 + r] = v.w;
    }
    for (int idx = tid; idx < 128 * 16; idx += 256) {
        int k = idx >> 4, c4 = idx & 15;
        *(float4*)&Ws[k * 68 + c4 * 4] = *(const float4*)&nw1[(size_t)k * HHID + h0 + c4 * 4];
    }
    __syncthreads();

    int tx = tid & 15, ty = tid >> 4;
    float acc[4][4] = {};
    #pragma unroll 4
    for (int k = 0; k < 128; k++) {
        float4 xv = *(const float4*)&Xs[k * 68 + ty * 4];
        float4 wv = *(const float4*)&Ws[k * 68 + tx * 4];
        FMA44(acc, xv, wv)
    }
    #pragma unroll
    for (int i = 0; i < 4; i++) {
        float4 o = make_float4(acc[i][0], acc[i][1], acc[i][2], acc[i][3]);
        o.x += nb1[h0 + tx * 4 + 0];
        o.y += nb1[h0 + tx * 4 + 1];
        o.z += nb1[h0 + tx * 4 + 2];
        o.w += nb1[h0 + tx * 4 + 3];
        *(float4*)&g_R[(size_t)(row0 + ty * 4 + i) * HHID + h0 + tx * 4] = o;
    }
}

// ==================== FFMA fused sender (overlapped under edge) ====================
__global__ __launch_bounds__(256) void k_sender(
    const float* __restrict__ Xin,
    const float* __restrict__ w1, const float* __restrict__ b1,
    const float* __restrict__ w2, const float* __restrict__ b2,
    const float* __restrict__ gam, const float* __restrict__ bet,
    float* __restrict__ out)
{
    extern __shared__ float sm[];
    float* Xs = sm;
    float* Ws = Xs + 128 * 68;
    float* Hs = Ws + 128 * 68;

    int tid = threadIdx.x;
    int row0 = blockIdx.x * 64;

    for (int idx = tid; idx < 64 * 32; idx += 256) {
        int r = idx >> 5, k4 = idx & 31;
        float4 v = *(const float4*)&Xin[(size_t)(row0 + r) * 128 + k4 * 4];
        Xs[(k4 * 4 + 0) * 68 + r] = v.x;
        Xs[(k4 * 4 + 1) * 68 + r] = v.y;
        Xs[(k4 * 4 + 2) * 68 + r] = v.z;
        Xs[(k4 * 4 + 3) * 68 + r] = v.w;
    }
    __syncthreads();

    int tx = tid & 15, ty = tid >> 4;
    float y[4][8] = {};

    #pragma unroll 1
    for (int hc = 0; hc < 4; hc++) {
        int h0 = hc * 64;
        for (int idx = tid; idx < 128 * 16; idx += 256) {
            int k = idx >> 4, c4 = idx & 15;
            *(float4*)&Ws[k * 68 + c4 * 4] = *(const float4*)&w1[(size_t)k * HHID + h0 + c4 * 4];
        }
        __syncthreads();

        float h[4][4] = {};
        #pragma unroll 4
        for (int k = 0; k < 128; k++) {
            float4 xv = *(const float4*)&Xs[k * 68 + ty * 4];
            float4 wv = *(const float4*)&Ws[k * 68 + tx * 4];
            FMA44(h, xv, wv)
        }

        float4 bv = *(const float4*)&b1[h0 + tx * 4];
        #pragma unroll
        for (int i = 0; i < 4; i++) {
            h[i][0] += bv.x; h[i][1] += bv.y; h[i][2] += bv.z; h[i][3] += bv.w;
        }

        #pragma unroll
        for (int j = 0; j < 4; j++) {
            float4 hv;
            hv.x = siluf(h[0][j]);
            hv.y = siluf(h[1][j]);
            hv.z = siluf(h[2][j]);
            hv.w = siluf(h[3][j]);
            *(float4*)&Hs[(tx * 4 + j) * 68 + ty * 4] = hv;
        }
        __syncthreads();

        for (int idx = tid; idx < 64 * 32; idx += 256) {
            int k = idx >> 5, c4 = idx & 31;
            *(float4*)&Ws[k * 132 + c4 * 4] = *(const float4*)&w2[(size_t)(h0 + k) * 128 + c4 * 4];
        }
        __syncthreads();

        #pragma unroll 2
        for (int k = 0; k < 64; k++) {
            float4 hv = *(const float4*)&Hs[k * 68 + ty * 4];
            float4 w0 = *(const float4*)&Ws[k * 132 + tx * 8];
            float4 w1v = *(const float4*)&Ws[k * 132 + tx * 8 + 4];
            FMAROW(y[0], hv.x)
            FMAROW(y[1], hv.y)
            FMAROW(y[2], hv.z)
            FMAROW(y[3], hv.w)
        }
        __syncthreads();
    }

    float b2r[8], gr[8], br[8];
    #pragma unroll
    for (int c = 0; c < 8; c++) {
        b2r[c] = b2[tx * 8 + c];
        gr[c] = gam[tx * 8 + c];
        br[c] = bet[tx * 8 + c];
    }
    #pragma unroll
    for (int i = 0; i < 4; i++) {
        #pragma unroll
        for (int c = 0; c < 8; c++) y[i][c] += b2r[c];

        float s1 = 0.f, s2 = 0.f;
        #pragma unroll
        for (int c = 0; c < 8; c++) { float v = y[i][c]; s1 += v; s2 += v * v; }
        #pragma unroll
        for (int m = 8; m >= 1; m >>= 1) {
            s1 += __shfl_xor_sync(0xffffffffu, s1, m);
            s2 += __shfl_xor_sync(0xffffffffu, s2, m);
        }
        float mu = s1 * (1.0f / 128.0f);
        float rs = rsqrtf(s2 * (1.0f / 128.0f) - mu * mu + LNEPS);

        int r = ty * 4 + i;
        float o[8];
        #pragma unroll
        for (int c = 0; c < 8; c++)
            o[c] = (y[i][c] - mu) * rs * gr[c] + br[c] + Xs[(tx * 8 + c) * 68 + r];
        size_t gout = (size_t)(row0 + r) * 128 + tx * 8;
        *(float4*)&out[gout]     = make_float4(o[0], o[1], o[2], o[3]);
        *(float4*)&out[gout + 4] = make_float4(o[4], o[5], o[6], o[7]);
    }
}

// ==================== HMMA MLP kernel (fp16 single-pass): MODE 0 = edge, 1 = node ====================
#define OFF_SIDX   0
#define OFF_DIDX   512
#define OFF_P1     1024
#define OFF_P2     3072
#define OFF_A      5120       // A fp16 32K; later H_c1; MSG spans A+W (64K) after GEMMs
#define OFF_MSG    5120
#define OFF_W      37888      // fp16 W chunk 32K
#define OFF_H      70656      // H fp16 32K
#define SM_EDGE    103424

// stage one fp16 W chunk (32KB)
__device__ __forceinline__ void stage_w(uint32_t sb, const __half* g, int tid) {
    const char* p = (const char*)g;
    #pragma unroll
    for (int j = 0; j < 4; j++) {
        int i = tid + j * 512;
        CP_ASYNC16(sb + OFF_W + i * 16, p + i * 16);
    }
    CP_COMMIT();
}

// dd += A(128x128 fp16) @ W^T(128x128 fp16); single pass, pipelined fragments
__device__ __forceinline__ void gemm_phase(uint32_t sb, int lane, int wm, int wn,
                                           uint32_t baseA, float (&dd)[2][4][4]) {
    uint32_t bf[2][4][2];
    uint32_t af[2][2][4];

    const int gq = lane >> 3;
    const int rowq0 = wn * 32 + ((gq >> 1) << 3) + (lane & 7);
    const int rowq1 = rowq0 + 16;
    const int rra0 = wm * 32 + (lane & 15);
    const int rra1 = rra0 + 16;
    const int bksel = gq & 1;
    const int aksel = lane >> 4;

    #define LD_B(buf, ksv)                                                                 \
    {                                                                                      \
        int chq = 2 * (ksv) + bksel;                                                       \
        uint32_t adq = sb + OFF_W + sw_off(rowq0, chq);                                    \
        uint32_t r4[4];                                                                    \
        LDSM_X4(r4, adq);                                                                  \
        bf[buf][0][0] = r4[0]; bf[buf][0][1] = r4[1]; bf[buf][1][0] = r4[2]; bf[buf][1][1] = r4[3]; \
        adq = sb + OFF_W + sw_off(rowq1, chq);                                             \
        LDSM_X4(r4, adq);                                                                  \
        bf[buf][2][0] = r4[0]; bf[buf][2][1] = r4[1]; bf[buf][3][0] = r4[2]; bf[buf][3][1] = r4[3]; \
    }
    #define LD_A(buf, ksv)                                                                 \
    {                                                                                      \
        int ch = 2 * (ksv) + aksel;                                                        \
        uint32_t ad = sb + baseA + sw_off(rra0, ch);                                       \
        LDSM_X4(af[buf][0], ad);                                                           \
        ad = sb + baseA + sw_off(rra1, ch);                                                \
        LDSM_X4(af[buf][1], ad);                                                           \
    }

    LD_B(0, 0)
    LD_A(0, 0)
    #pragma unroll
    for (int ks = 0; ks < 8; ks++) {
        const int cur = ks & 1, nxt = cur ^ 1;
        if (ks < 7) {
            LD_B(nxt, ks + 1)
            LD_A(nxt, ks + 1)
        }
        #pragma unroll
        for (int nt = 0; nt < 4; nt++) {
            MMA_FP16(dd[0][nt], af[cur][0], bf[cur][nt]);
            MMA_FP16(dd[1][nt], af[cur][1], bf[cur][nt]);
        }
    }
    #undef LD_B
    #undef LD_A
}

// epi1: MODE 0: D1 + gA[src] + gB[dst]; MODE 1: D1 + gA[row] (gA = g_R); SiLU -> fp16 H
template <int MODE>
__device__ __forceinline__ void epi1_phase(char* smc, const int* sidx_s, const int* didx_s,
    const float* gA, const float* gB, float (&d1)[2][4][4],
    int wm, int wn, int lane, int c, uint32_t dstOff, int row0)
{
    #pragma unroll
    for (int mt = 0; mt < 2; mt++) {
        int r1 = wm * 32 + mt * 16 + (lane >> 2);
        int r2 = r1 + 8;
        int si1, di1, si2, di2;
        if (MODE == 0) {
            si1 = sidx_s[r1]; di1 = didx_s[r1];
            si2 = sidx_s[r2]; di2 = didx_s[r2];
        } else {
            si1 = row0 + r1; if (si1 >= NNODE) si1 = NNODE - 1;
            si2 = row0 + r2; if (si2 >= NNODE) si2 = NNODE - 1;
            di1 = di2 = 0;
        }
        #pragma unroll
        for (int nt = 0; nt < 4; nt++) {
            int cpl = wn * 32 + nt * 8 + 2 * (lane & 3);
            int gc = c * 128 + cpl;
            float2 a1 = *(const float2*)(gA + (size_t)si1 * HHID + gc);
            float2 a2 = *(const float2*)(gA + (size_t)si2 * HHID + gc);
            float g10 = a1.x, g11 = a1.y, g20 = a2.x, g21 = a2.y;
            if (MODE == 0) {
                float2 bb1 = *(const float2*)(gB + (size_t)di1 * HHID + gc);
                float2 bb2 = *(const float2*)(gB + (size_t)di2 * HHID + gc);
                g10 += bb1.x; g11 += bb1.y; g20 += bb2.x; g21 += bb2.y;
            }
            __half h00 = __float2half_rn(siluf(d1[mt][nt][0] + g10));
            __half h01 = __float2half_rn(siluf(d1[mt][nt][1] + g11));
            __half h10 = __float2half_rn(siluf(d1[mt][nt][2] + g20));
            __half h11 = __float2half_rn(siluf(d1[mt][nt][3] + g21));
            uint32_t o1 = sw_off(r1, (cpl >> 3)) + (cpl & 7) * 2;
            uint32_t o2 = sw_off(r2, (cpl >> 3)) + (cpl & 7) * 2;
            *(uint32_t*)(smc + dstOff + o1) =
                (uint32_t)__half_as_ushort(h00) | ((uint32_t)__half_as_ushort(h01) << 16);
            *(uint32_t*)(smc + dstOff + o2) =
                (uint32_t)__half_as_ushort(h10) | ((uint32_t)__half_as_ushort(h11) << 16);
        }
    }
}

template <int MODE>
__global__ __launch_bounds__(512, 1) void k_mlp(
    const float* __restrict__ Ain, const void* __restrict__ ei,
    const float* __restrict__ gA, const float* __restrict__ gB,
    const __half* __restrict__ w1f, const __half* __restrict__ w2f,
    const float* __restrict__ b2, const float* __restrict__ gam, const float* __restrict__ bet,
    const float* __restrict__ resid, float* __restrict__ out, float* __restrict__ agg)
{
    extern __shared__ char smc[];
    const uint32_t sb = smem_to_u32(smc);
    const int tid = threadIdx.x;
    const int lane = tid & 31, wid = tid >> 5;
    const int wm = wid >> 2, wn = wid & 3;
    const int row0 = blockIdx.x * 128;

    stage_w(sb, w1f, tid);

    int* sidx_s = (int*)(smc + OFF_SIDX);
    int* didx_s = (int*)(smc + OFF_DIDX);
    float* rc_s = (float*)(smc + OFF_SIDX);

    if (MODE == 0) {
        if (tid < 128) {
            sidx_s[tid] = eidx(ei, (long long)(row0 + tid));
            didx_s[tid] = eidx(ei, (long long)EEDGE + row0 + tid);
        }
    } else {
        if (tid < 128) {
            int rr = row0 + tid; if (rr >= NNODE) rr = NNODE - 1;
            int cval = g_cnt[rr];
            rc_s[tid] = 1.0f / (float)(cval > 1 ? cval : 1);
        }
        __syncthreads();
    }

    // A tile -> single fp16 swizzled
    for (int idx = tid; idx < 128 * 32; idx += 512) {
        int r = idx >> 5, c4 = idx & 31;
        int gr = row0 + r;
        if (MODE == 1 && gr >= NNODE) gr = NNODE - 1;
        float4 v = *(const float4*)(Ain + (size_t)gr * 128 + c4 * 4);
        if (MODE == 1) {
            float s = rc_s[r];
            v.x *= s; v.y *= s; v.z *= s; v.w *= s;
        }
        uint2 ph;
        ph.x = (uint32_t)__half_as_ushort(__float2half_rn(v.x)) |
               ((uint32_t)__half_as_ushort(__float2half_rn(v.y)) << 16);
        ph.y = (uint32_t)__half_as_ushort(__float2half_rn(v.z)) |
               ((uint32_t)__half_as_ushort(__float2half_rn(v.w)) << 16);
        uint32_t off = sw_off(r, c4 >> 1) + (c4 & 1) * 8;
        *(uint2*)(smc + OFF_A + off) = ph;
    }
    CP_WAIT0();
    __syncthreads();

    float d1[2][4][4];
    #pragma unroll
    for (int a = 0; a < 2; a++)
        #pragma unroll
        for (int b = 0; b < 4; b++)
            #pragma unroll
            for (int q = 0; q < 4; q++) d1[a][b][q] = 0.f;

    // G1 c0
    gemm_phase(sb, lane, wm, wn, OFF_A, d1);
    __syncthreads();
    stage_w(sb, w1f + 16384, tid);
    epi1_phase<MODE>(smc, sidx_s, didx_s, gA, gB, d1, wm, wn, lane, 0, OFF_H, row0);
    CP_WAIT0();
    __syncthreads();

    // G1 c1
    #pragma unroll
    for (int a = 0; a < 2; a++)
        #pragma unroll
        for (int b = 0; b < 4; b++)
            #pragma unroll
            for (int q = 0; q < 4; q++) d1[a][b][q] = 0.f;
    gemm_phase(sb, lane, wm, wn, OFF_A, d1);
    __syncthreads();
    stage_w(sb, w2f, tid);
    epi1_phase<MODE>(smc, sidx_s, didx_s, gA, gB, d1, wm, wn, lane, 1, OFF_A, row0);  // H_c1 -> A region
    CP_WAIT0();
    __syncthreads();

    // G2 c0
    float d2[2][4][4];
    #pragma unroll
    for (int a = 0; a < 2; a++)
        #pragma unroll
        for (int b = 0; b < 4; b++)
            #pragma unroll
            for (int q = 0; q < 4; q++) d2[a][b][q] = 0.f;
    gemm_phase(sb, lane, wm, wn, OFF_H, d2);
    __syncthreads();
    stage_w(sb, w2f + 16384, tid);
    CP_WAIT0();
    __syncthreads();

    // G2 c1 (H_c1 lives in A region)
    gemm_phase(sb, lane, wm, wn, OFF_A, d2);

    // ---- epi2: +b2, LayerNorm, residual, store (+ messages for MODE 0) ----
    float b2v[4][2], gmv[4][2], btv[4][2];
    #pragma unroll
    for (int nt = 0; nt < 4; nt++) {
        int col = wn * 32 + nt * 8 + 2 * (lane & 3);
        float2 t;
        t = *(const float2*)(b2 + col);  b2v[nt][0] = t.x; b2v[nt][1] = t.y;
        t = *(const float2*)(gam + col); gmv[nt][0] = t.x; gmv[nt][1] = t.y;
        t = *(const float2*)(bet + col); btv[nt][0] = t.x; btv[nt][1] = t.y;
    }
    float* p1 = (float*)(smc + OFF_P1);
    float* p2 = (float*)(smc + OFF_P2);

    #pragma unroll
    for (int mt = 0; mt < 2; mt++) {
        int r1 = wm * 32 + mt * 16 + (lane >> 2);
        int r2 = r1 + 8;
        float s1a = 0.f, s2a = 0.f, s1b = 0.f, s2b = 0.f;
        #pragma unroll
        for (int nt = 0; nt < 4; nt++) {
            float y0 = d2[mt][nt][0] + b2v[nt][0];
            float y1 = d2[mt][nt][1] + b2v[nt][1];
            float y2 = d2[mt][nt][2] + b2v[nt][0];
            float y3 = d2[mt][nt][3] + b2v[nt][1];
            d2[mt][nt][0] = y0; d2[mt][nt][1] = y1; d2[mt][nt][2] = y2; d2[mt][nt][3] = y3;
            s1a += y0 + y1; s2a += y0 * y0 + y1 * y1;
            s1b += y2 + y3; s2b += y2 * y2 + y3 * y3;
        }
        #pragma unroll
        for (int m = 1; m <= 2; m <<= 1) {
            s1a += __shfl_xor_sync(0xffffffffu, s1a, m);
            s2a += __shfl_xor_sync(0xffffffffu, s2a, m);
            s1b += __shfl_xor_sync(0xffffffffu, s1b, m);
            s2b += __shfl_xor_sync(0xffffffffu, s2b, m);
        }
        if ((lane & 3) == 0) {
            p1[r1 * 4 + wn] = s1a; p2[r1 * 4 + wn] = s2a;
            p1[r2 * 4 + wn] = s1b; p2[r2 * 4 + wn] = s2b;
        }
    }
    __syncthreads();   // all G2c1 reads of A/W regions complete before msg writes

    float* msg = (float*)(smc + OFF_MSG);
    #pragma unroll
    for (int mt = 0; mt < 2; mt++) {
        int r1 = wm * 32 + mt * 16 + (lane >> 2);
        int r2 = r1 + 8;
        float4 q1 = *(float4*)&p1[r1 * 4];
        float4 v1 = *(float4*)&p2[r1 * 4];
        float4 q2 = *(float4*)&p1[r2 * 4];
        float4 v2 = *(float4*)&p2[r2 * 4];
        float mu1 = (q1.x + q1.y + q1.z + q1.w) * (1.0f / 128.0f);
        float mu2 = (q2.x + q2.y + q2.z + q2.w) * (1.0f / 128.0f);
        float rs1 = rsqrtf((v1.x + v1.y + v1.z + v1.w) * (1.0f / 128.0f) - mu1 * mu1 + LNEPS);
        float rs2 = rsqrtf((v2.x + v2.y + v2.z + v2.w) * (1.0f / 128.0f) - mu2 * mu2 + LNEPS);
        bool w1ok = (MODE == 0) || (row0 + r1 < NNODE);
        bool w2ok = (MODE == 0) || (row0 + r2 < NNODE);
        #pragma unroll
        for (int nt = 0; nt < 4; nt++) {
            int col = wn * 32 + nt * 8 + 2 * (lane & 3);
            float pa0 = (d2[mt][nt][0] - mu1) * rs1 * gmv[nt][0] + btv[nt][0];
            float pa1 = (d2[mt][nt][1] - mu1) * rs1 * gmv[nt][1] + btv[nt][1];
            float pb0 = (d2[mt][nt][2] - mu2) * rs2 * gmv[nt][0] + btv[nt][0];
            float pb1 = (d2[mt][nt][3] - mu2) * rs2 * gmv[nt][1] + btv[nt][1];
            if (w1ok) {
                float2 x1 = *(const float2*)(resid + (size_t)(row0 + r1) * 128 + col);
                *(float2*)(out + (size_t)(row0 + r1) * 128 + col) = make_float2(pa0 + x1.x, pa1 + x1.y);
            }
            if (w2ok) {
                float2 x2 = *(const float2*)(resid + (size_t)(row0 + r2) * 128 + col);
                *(float2*)(out + (size_t)(row0 + r2) * 128 + col) = make_float2(pb0 + x2.x, pb1 + x2.y);
            }
            if (MODE == 0) {
                *(float2*)(msg + r1 * 128 + col) = make_float2(pa0, pa1);
                *(float2*)(msg + r2 * 128 + col) = make_float2(pb0, pb1);
            }
        }
    }

    if (MODE == 0) {
        FENCE_ASYNC();
        __syncthreads();
        if (tid < 128) {
            float* gdst = agg + (size_t)didx_s[tid] * 128;
            bulk_reduce_add_f32(gdst, sb + OFF_MSG + (uint32_t)tid * 512, 512);
            asm volatile("cp.async.bulk.commit_group;" ::: "memory");
            asm volatile("cp.async.bulk.wait_group 0;" ::: "memory");
        }
    }
}

// ==================== launcher ====================
extern "C" void kernel_launch(void* const* d_in, const int* in_sizes, int n_in,
                              void* d_out, int out_size) {
    (void)in_sizes; (void)n_in; (void)out_size;
    const float* sender_x   = (const float*)d_in[0];
    const float* receiver_x = (const float*)d_in[1];
    const float* edge_attr  = (const float*)d_in[2];
    const void*  ei         = d_in[3];
    const float* ew1  = (const float*)d_in[4];
    const float* eb1  = (const float*)d_in[5];
    const float* ew2  = (const float*)d_in[6];
    const float* eb2  = (const float*)d_in[7];
    const float* eg   = (const float*)d_in[8];
    const float* ebt  = (const float*)d_in[9];
    const float* nw1  = (const float*)d_in[10];
    const float* nb1  = (const float*)d_in[11];
    const float* nw2  = (const float*)d_in[12];
    const float* nb2  = (const float*)d_in[13];
    const float* ng   = (const float*)d_in[14];
    const float* nbt  = (const float*)d_in[15];
    const float* sw1  = (const float*)d_in[16];
    const float* sb1  = (const float*)d_in[17];
    const float* sw2  = (const float*)d_in[18];
    const float* sb2  = (const float*)d_in[19];
    const float* sg   = (const float*)d_in[20];
    const float* sbt  = (const float*)d_in[21];

    float* out = (float*)d_out;
    float* out_send = out;
    float* out_recv = out + (size_t)NNODE * DD;
    float* out_edge = out + (size_t)2 * NNODE * DD;

    void *pA, *pB, *pR, *pAgg, *pw1f, *pw2f, *pn1f, *pn2f;
    cudaGetSymbolAddress(&pA, g_A);
    cudaGetSymbolAddress(&pB, g_B);
    cudaGetSymbolAddress(&pR, g_R);
    cudaGetSymbolAddress(&pAgg, g_agg);
    cudaGetSymbolAddress(&pw1f, g_w1f);
    cudaGetSymbolAddress(&pw2f, g_w2f);
    cudaGetSymbolAddress(&pn1f, g_nw1f);
    cudaGetSymbolAddress(&pn2f, g_nw2f);

    static cudaStream_t s2 = nullptr;
    static cudaEvent_t evS = nullptr, evP = nullptr, evJ = nullptr;
    if (s2 == nullptr) {
        cudaStreamCreateWithFlags(&s2, cudaStreamNonBlocking);
        cudaEventCreateWithFlags(&evS, cudaEventDisableTiming);
        cudaEventCreateWithFlags(&evP, cudaEventDisableTiming);
        cudaEventCreateWithFlags(&evJ, cudaEventDisableTiming);
    }

    const int SM_PRE = (128 * 68 + 128 * 68) * 4;
    const int SM_FU  = (128 * 68 + 128 * 68 + 64 * 68 + 64) * 4;
    cudaFuncSetAttribute(k_pregemmH, cudaFuncAttributeMaxDynamicSharedMemorySize, SM_PG);
    cudaFuncSetAttribute(k_pregemmR, cudaFuncAttributeMaxDynamicSharedMemorySize, SM_PRE);
    cudaFuncSetAttribute(k_sender,   cudaFuncAttributeMaxDynamicSharedMemorySize, SM_FU);
    cudaFuncSetAttribute(k_mlp<0>,   cudaFuncAttributeMaxDynamicSharedMemorySize, SM_EDGE);
    cudaFuncSetAttribute(k_mlp<1>,   cudaFuncAttributeMaxDynamicSharedMemorySize, SM_EDGE);

    // launch 1: weight prep + cnt zero + dtype detect (main)
    k_prepw<<<157, 256>>>(ew1, ew2, nw1, nw2, ei);
    cudaEventRecord(evS, 0);
    // launch 2: HMMA pregemm A/B on side stream
    cudaStreamWaitEvent(s2, evS, 0);
    k_pregemmH<<<dim3(NNODE / 64, 1, 2), 256, SM_PG, s2>>>(sender_x, receiver_x, eb1);
    // launch 3: zero agg + degree count (main)
    k_initcount<<<(NNODE * DD) / 256, 256>>>(ei);
    cudaEventRecord(evP, s2);
    cudaStreamWaitEvent(0, evP, 0);
    // launch 4 (ncu slot): edge kernel
    k_mlp<0><<<EEDGE / 128, 512, SM_EDGE>>>(
        edge_attr, ei, (const float*)pA, (const float*)pB,
        (const __half*)pw1f, (const __half*)pw2f,
        eb2, eg, ebt, edge_attr, out_edge, (float*)pAgg);
    // side stream overlaps edge: sender MLP + node receiver-half precompute
    k_sender<<<NNODE / 64, 256, SM_FU, s2>>>(sender_x, sw1, sb1, sw2, sb2, sg, sbt, out_send);
    k_pregemmR<<<dim3(NNODE / 64, 4), 256, SM_PRE, s2>>>(receiver_x, nw1, nb1);
    cudaEventRecord(evJ, s2);
    cudaStreamWaitEvent(0, evJ, 0);
    // node MLP (HMMA fp16 single-pass): agg-dependent half, g_R gathered densely
    k_mlp<1><<<(NNODE + 127) / 128, 512, SM_EDGE>>>(
        (const float*)pAgg, nullptr, (const float*)pR, nullptr,
        (const __half*)pn1f, (const __half*)pn2f,
        nb2, ng, nbt, receiver_x, out_recv, nullptr);
}

// round 14
// speedup vs baseline: 1.5967x; 1.0398x over previous
#include <cuda_runtime.h>
#include <cuda_bf16.h>
#include <cuda_fp16.h>
#include <math.h>
#include <cstdint>

#define NNODE 40000
#define EEDGE 640000
#define DD    128
#define HHID  256
#define LNEPS 1e-5f

// ==================== device scratch (allocation-free) ====================
__device__ __align__(128) float g_A[(size_t)NNODE * HHID];   // sender_x @ ew1[0:128]
__device__ __align__(128) float g_B[(size_t)NNODE * HHID];   // receiver_x @ ew1[128:256] + eb1
__device__ __align__(128) float g_R[(size_t)NNODE * HHID];   // receiver_x @ nw1[0:128] + nb1
__device__ __align__(128) float g_agg[(size_t)NNODE * DD];   // scatter-sum of edge messages
__device__ int   g_cnt[NNODE];
__device__ int   g_is64;
// fp16 single-precision weight images for the HMMA MLP kernels (2 chunks [128n][128k], contiguous)
__device__ __align__(16) __half g_w1f[2 * 128 * 128];   // edge W1[256:384]^T
__device__ __align__(16) __half g_w2f[2 * 128 * 128];   // edge W2^T
__device__ __align__(16) __half g_nw1f[2 * 128 * 128];  // node W1[128:256]^T
__device__ __align__(16) __half g_nw2f[2 * 128 * 128];  // node W2^T
// bf16 hi/lo images for the high-precision pregemm (4 chunks [64n][128k])
__device__ __align__(16) __nv_bfloat16 g_wAh[4 * 64 * 128];
__device__ __align__(16) __nv_bfloat16 g_wAl[4 * 64 * 128];
__device__ __align__(16) __nv_bfloat16 g_wBh[4 * 64 * 128];
__device__ __align__(16) __nv_bfloat16 g_wBl[4 * 64 * 128];

// ==================== helpers ====================
__device__ __forceinline__ uint32_t smem_to_u32(const void* p) {
    uint32_t a;
    asm("{ .reg .u64 t; cvta.to.shared.u64 t, %1; cvt.u32.u64 %0, t; }" : "=r"(a) : "l"(p));
    return a;
}
__device__ __forceinline__ int eidx(const void* ei, long long pos) {
    return g_is64 ? (int)((const long long*)ei)[pos] : ((const int*)ei)[pos];
}
__device__ __forceinline__ float siluf(float x) { return x * (1.0f / (1.0f + __expf(-x))); }
__device__ __forceinline__ void split2(float v, unsigned short& h, unsigned short& l) {
    __nv_bfloat16 hb = __float2bfloat16(v);
    __nv_bfloat16 lb = __float2bfloat16(v - __bfloat162float(hb));
    h = __bfloat16_as_ushort(hb);
    l = __bfloat16_as_ushort(lb);
}

#define LDSM_X4(r, ad) \
    asm volatile("ldmatrix.sync.aligned.m8n8.x4.shared.b16 {%0,%1,%2,%3}, [%4];" \
        : "=r"((r)[0]), "=r"((r)[1]), "=r"((r)[2]), "=r"((r)[3]) : "r"(ad))
#define MMA_BF16(d, a, b) \
    asm volatile("mma.sync.aligned.m16n8k16.row.col.f32.bf16.bf16.f32 " \
        "{%0,%1,%2,%3}, {%4,%5,%6,%7}, {%8,%9}, {%0,%1,%2,%3};" \
        : "+f"((d)[0]), "+f"((d)[1]), "+f"((d)[2]), "+f"((d)[3]) \
        : "r"((a)[0]), "r"((a)[1]), "r"((a)[2]), "r"((a)[3]), "r"((b)[0]), "r"((b)[1]))
#define MMA_FP16(d, a, b) \
    asm volatile("mma.sync.aligned.m16n8k16.row.col.f32.f16.f16.f32 " \
        "{%0,%1,%2,%3}, {%4,%5,%6,%7}, {%8,%9}, {%0,%1,%2,%3};" \
        : "+f"((d)[0]), "+f"((d)[1]), "+f"((d)[2]), "+f"((d)[3]) \
        : "r"((a)[0]), "r"((a)[1]), "r"((a)[2]), "r"((a)[3]), "r"((b)[0]), "r"((b)[1]))

__device__ __forceinline__ void bulk_reduce_add_f32(float* gdst, uint32_t ssrc, uint32_t bytes) {
    asm volatile("cp.reduce.async.bulk.global.shared::cta.bulk_group.add.f32 [%0], [%1], %2;"
                 :: "l"(gdst), "r"(ssrc), "r"(bytes) : "memory");
}
#define FENCE_ASYNC() asm volatile("fence.proxy.async.shared::cta;" ::: "memory")
#define CP_ASYNC16(sdst, gsrc) \
    asm volatile("cp.async.cg.shared.global [%0], [%1], 16;" :: "r"(sdst), "l"(gsrc) : "memory")
#define CP_COMMIT() asm volatile("cp.async.commit_group;" ::: "memory")
#define CP_WAIT0()  asm volatile("cp.async.wait_group 0;" ::: "memory")
#define CP_WAIT1()  asm volatile("cp.async.wait_group 1;" ::: "memory")

// swizzled tile: rows of 256B (128 b16); 16B-chunk c at row r lives at (c ^ (r&7))
__device__ __forceinline__ uint32_t sw_off(int r, int chunk) {
    return (uint32_t)(r * 256 + ((chunk ^ (r & 7)) << 4));
}

// ==================== launch 1: weight prep + cnt zero + dtype detect ====================
__global__ void k_prepw(const float* __restrict__ ew1, const float* __restrict__ ew2,
                        const float* __restrict__ nw1, const float* __restrict__ nw2,
                        const void* __restrict__ ei) {
    int i = blockIdx.x * 256 + threadIdx.x;   // grid 157*256 = 40192
    if (i == 0) {
        const long long* p = (const long long*)ei;
        int ok = 1;
        #pragma unroll
        for (int j = 0; j < 32; j++) {
            long long v = p[j];
            if (v < 0 || v >= NNODE) ok = 0;
        }
        g_is64 = ok;
    }
    if (i < NNODE) g_cnt[i] = 0;
    if (i < 32768) {
        {
            int n = i >> 7, k = i & 127;
            int chunk = n >> 7, r = n & 127;
            uint32_t off = (uint32_t)chunk * 32768 + sw_off(r, k >> 3) + (k & 7) * 2;
            *(unsigned short*)((char*)g_w1f + off) =
                __half_as_ushort(__float2half_rn(ew1[(size_t)(256 + k) * HHID + n]));
            *(unsigned short*)((char*)g_nw1f + off) =
                __half_as_ushort(__float2half_rn(nw1[(size_t)(128 + k) * HHID + n]));
        }
        {
            int n = i & 127, k = i >> 7;
            int chunk = k >> 7, kk = k & 127;
            uint32_t off = (uint32_t)chunk * 32768 + sw_off(n, kk >> 3) + (kk & 7) * 2;
            *(unsigned short*)((char*)g_w2f + off) =
                __half_as_ushort(__float2half_rn(ew2[(size_t)k * DD + n]));
            *(unsigned short*)((char*)g_nw2f + off) =
                __half_as_ushort(__float2half_rn(nw2[(size_t)k * DD + n]));
        }
        {
            int n = i >> 7, k = i & 127;
            int chunk = n >> 6, r = n & 63;
            uint32_t off = (uint32_t)chunk * 16384 + sw_off(r, k >> 3) + (k & 7) * 2;
            unsigned short h, l;
            split2(ew1[(size_t)k * HHID + n], h, l);
            *(unsigned short*)((char*)g_wAh + off) = h;
            *(unsigned short*)((char*)g_wAl + off) = l;
            split2(ew1[(size_t)(128 + k) * HHID + n], h, l);
            *(unsigned short*)((char*)g_wBh + off) = h;
            *(unsigned short*)((char*)g_wBl + off) = l;
        }
    }
}

// ==================== launch 3: zero agg + degree count ====================
__global__ void k_initcount(const void* __restrict__ ei) {
    int i = blockIdx.x * 256 + threadIdx.x;
    g_agg[i] = 0.0f;
    if (i < EEDGE) {
        int d = eidx(ei, (long long)EEDGE + i);
        atomicAdd(&g_cnt[d], 1);
    }
}

// ==================== HMMA pregemm (bf16 3-pass, off critical path) ====================
#define PG_A     0
#define PG_W     32768
#define PG_LOSEP 16384
#define SM_PG    65536

__device__ __forceinline__ void stage_w64(uint32_t sb, const __nv_bfloat16* gh,
                                          const __nv_bfloat16* gl, int tid) {
    const char* ph = (const char*)gh;
    const char* pl = (const char*)gl;
    #pragma unroll
    for (int j = 0; j < 4; j++) {
        int i = tid + j * 256;
        CP_ASYNC16(sb + PG_W + i * 16, ph + i * 16);
        CP_ASYNC16(sb + PG_W + PG_LOSEP + i * 16, pl + i * 16);
    }
    CP_COMMIT();
}

__device__ __forceinline__ void gemm64(uint32_t sb, int lane, int wm, int wn,
                                       float (&dd)[2][2][4]) {
    uint32_t bh[2][2][2], bl[2][2][2];
    uint32_t ah[2][2][4], al[2][2][4];

    const int gq = lane >> 3;
    const int rowq = wn * 16 + ((gq >> 1) << 3) + (lane & 7);
    const int rra0 = wm * 32 + (lane & 15);
    const int rra1 = rra0 + 16;
    const int bksel = gq & 1;
    const int aksel = lane >> 4;

    #define LD_B64(buf, ksv)                                                               \
    {                                                                                      \
        int chq = 2 * (ksv) + bksel;                                                       \
        uint32_t adq = sb + PG_W + sw_off(rowq, chq);                                      \
        uint32_t r4[4];                                                                    \
        LDSM_X4(r4, adq);                                                                  \
        bh[buf][0][0] = r4[0]; bh[buf][0][1] = r4[1]; bh[buf][1][0] = r4[2]; bh[buf][1][1] = r4[3]; \
        LDSM_X4(r4, adq + PG_LOSEP);                                                       \
        bl[buf][0][0] = r4[0]; bl[buf][0][1] = r4[1]; bl[buf][1][0] = r4[2]; bl[buf][1][1] = r4[3]; \
    }
    #define LD_A64(buf, ksv)                                                               \
    {                                                                                      \
        int ch = 2 * (ksv) + aksel;                                                        \
        uint32_t ad = sb + PG_A + sw_off(rra0, ch);                                        \
        LDSM_X4(ah[buf][0], ad);                                                           \
        LDSM_X4(al[buf][0], ad + PG_LOSEP);                                                \
        ad = sb + PG_A + sw_off(rra1, ch);                                                 \
        LDSM_X4(ah[buf][1], ad);                                                           \
        LDSM_X4(al[buf][1], ad + PG_LOSEP);                                                \
    }

    LD_B64(0, 0)
    LD_A64(0, 0)
    #pragma unroll
    for (int ks = 0; ks < 8; ks++) {
        const int cur = ks & 1, nxt = cur ^ 1;
        if (ks < 7) {
            LD_B64(nxt, ks + 1)
            LD_A64(nxt, ks + 1)
        }
        #pragma unroll
        for (int nt = 0; nt < 2; nt++) {
            MMA_BF16(dd[0][nt], ah[cur][0], bh[cur][nt]);
            MMA_BF16(dd[1][nt], ah[cur][1], bh[cur][nt]);
        }
        #pragma unroll
        for (int nt = 0; nt < 2; nt++) {
            MMA_BF16(dd[0][nt], ah[cur][0], bl[cur][nt]);
            MMA_BF16(dd[1][nt], ah[cur][1], bl[cur][nt]);
        }
        #pragma unroll
        for (int nt = 0; nt < 2; nt++) {
            MMA_BF16(dd[0][nt], al[cur][0], bh[cur][nt]);
            MMA_BF16(dd[1][nt], al[cur][1], bh[cur][nt]);
        }
    }
    #undef LD_B64
    #undef LD_A64
}

__global__ __launch_bounds__(256, 2) void k_pregemmH(
    const float* __restrict__ sx, const float* __restrict__ rx,
    const float* __restrict__ eb1)
{
    extern __shared__ char smc[];
    const uint32_t sb = smem_to_u32(smc);
    const int tid = threadIdx.x;
    const int lane = tid & 31, wid = tid >> 5;
    const int wm = wid >> 2, wn = wid & 3;
    const int row0 = blockIdx.x * 64;
    const int isB = blockIdx.z;

    const float* X = isB ? rx : sx;
    const __nv_bfloat16* wh = isB ? g_wBh : g_wAh;
    const __nv_bfloat16* wl = isB ? g_wBl : g_wAl;
    float* O = isB ? g_B : g_A;

    stage_w64(sb, wh, wl, tid);

    for (int idx = tid; idx < 64 * 32; idx += 256) {
        int r = idx >> 5, c4 = idx & 31;
        float4 v = *(const float4*)(X + (size_t)(row0 + r) * 128 + c4 * 4);
        unsigned short h0, l0, h1, l1, h2, l2, h3, l3;
        split2(v.x, h0, l0); split2(v.y, h1, l1); split2(v.z, h2, l2); split2(v.w, h3, l3);
        uint2 ph, pl;
        ph.x = (uint32_t)h0 | ((uint32_t)h1 << 16); ph.y = (uint32_t)h2 | ((uint32_t)h3 << 16);
        pl.x = (uint32_t)l0 | ((uint32_t)l1 << 16); pl.y = (uint32_t)l2 | ((uint32_t)l3 << 16);
        uint32_t off = sw_off(r, c4 >> 1) + (c4 & 1) * 8;
        *(uint2*)(smc + PG_A + off) = ph;
        *(uint2*)(smc + PG_A + PG_LOSEP + off) = pl;
    }
    CP_WAIT0();
    __syncthreads();

    #pragma unroll 1
    for (int cc = 0; cc < 4; cc++) {
        float dd[2][2][4];
        #pragma unroll
        for (int a = 0; a < 2; a++)
            #pragma unroll
            for (int b = 0; b < 2; b++)
                #pragma unroll
                for (int q = 0; q < 4; q++) dd[a][b][q] = 0.f;

        gemm64(sb, lane, wm, wn, dd);
        __syncthreads();
        if (cc < 3) stage_w64(sb, wh + (cc + 1) * 8192, wl + (cc + 1) * 8192, tid);

        #pragma unroll
        for (int mt = 0; mt < 2; mt++) {
            int r1 = wm * 32 + mt * 16 + (lane >> 2);
            int r2 = r1 + 8;
            #pragma unroll
            for (int nt = 0; nt < 2; nt++) {
                int col = wn * 16 + nt * 8 + 2 * (lane & 3);
                int gc = cc * 64 + col;
                float b0 = 0.f, b1 = 0.f;
                if (isB) {
                    float2 bb = *(const float2*)(eb1 + gc);
                    b0 = bb.x; b1 = bb.y;
                }
                *(float2*)(O + (size_t)(row0 + r1) * HHID + gc) =
                    make_float2(dd[mt][nt][0] + b0, dd[mt][nt][1] + b1);
                *(float2*)(O + (size_t)(row0 + r2) * HHID + gc) =
                    make_float2(dd[mt][nt][2] + b0, dd[mt][nt][3] + b1);
            }
        }
        if (cc < 3) {
            CP_WAIT0();
            __syncthreads();
        }
    }
}

// ==================== FFMA pregemmR (node receiver-half, overlapped) ====================
#define FMA44(A_, xv, wv)                                                              \
    A_[0][0] += xv.x * wv.x; A_[0][1] += xv.x * wv.y; A_[0][2] += xv.x * wv.z; A_[0][3] += xv.x * wv.w; \
    A_[1][0] += xv.y * wv.x; A_[1][1] += xv.y * wv.y; A_[1][2] += xv.y * wv.z; A_[1][3] += xv.y * wv.w; \
    A_[2][0] += xv.z * wv.x; A_[2][1] += xv.z * wv.y; A_[2][2] += xv.z * wv.z; A_[2][3] += xv.z * wv.w; \
    A_[3][0] += xv.w * wv.x; A_[3][1] += xv.w * wv.y; A_[3][2] += xv.w * wv.z; A_[3][3] += xv.w * wv.w;

#define FMAROW(yy, hx)                                                  \
    yy[0] += hx * w0.x; yy[1] += hx * w0.y; yy[2] += hx * w0.z; yy[3] += hx * w0.w; \
    yy[4] += hx * w1v.x; yy[5] += hx * w1v.y; yy[6] += hx * w1v.z; yy[7] += hx * w1v.w;

__global__ __launch_bounds__(256) void k_pregemmR(
    const float* __restrict__ rx, const float* __restrict__ nw1, const float* __restrict__ nb1)
{
    extern __shared__ float sm[];
    float* Xs = sm;
    float* Ws = sm + 128 * 68;
    int tid = threadIdx.x;
    int row0 = blockIdx.x * 64;
    int h0 = blockIdx.y * 64;

    for (int idx = tid; idx < 64 * 32; idx += 256) {
        int r = idx >> 5, k4 = idx & 31;
        float4 v = *(const float4*)&rx[(size_t)(row0 + r) * 128 + k4 * 4];
        Xs[(k4 * 4 + 0) * 68 + r] = v.x;
        Xs[(k4 * 4 + 1) * 68 + r] = v.y;
        Xs[(k4 * 4 + 2) * 68 + r] = v.z;
        Xs[(k4 * 4 + 3) * 68 + r] = v.w;
    }
    for (int idx = tid; idx < 128 * 16; idx += 256) {
        int k = idx >> 4, c4 = idx & 15;
        *(float4*)&Ws[k * 68 + c4 * 4] = *(const float4*)&nw1[(size_t)k * HHID + h0 + c4 * 4];
    }
    __syncthreads();

    int tx = tid & 15, ty = tid >> 4;
    float acc[4][4] = {};
    #pragma unroll 4
    for (int k = 0; k < 128; k++) {
        float4 xv = *(const float4*)&Xs[k * 68 + ty * 4];
        float4 wv = *(const float4*)&Ws[k * 68 + tx * 4];
        FMA44(acc, xv, wv)
    }
    #pragma unroll
    for (int i = 0; i < 4; i++) {
        float4 o = make_float4(acc[i][0], acc[i][1], acc[i][2], acc[i][3]);
        o.x += nb1[h0 + tx * 4 + 0];
        o.y += nb1[h0 + tx * 4 + 1];
        o.z += nb1[h0 + tx * 4 + 2];
        o.w += nb1[h0 + tx * 4 + 3];
        *(float4*)&g_R[(size_t)(row0 + ty * 4 + i) * HHID + h0 + tx * 4] = o;
    }
}

// ==================== FFMA fused sender (overlapped under edge) ====================
__global__ __launch_bounds__(256) void k_sender(
    const float* __restrict__ Xin,
    const float* __restrict__ w1, const float* __restrict__ b1,
    const float* __restrict__ w2, const float* __restrict__ b2,
    const float* __restrict__ gam, const float* __restrict__ bet,
    float* __restrict__ out)
{
    extern __shared__ float sm[];
    float* Xs = sm;
    float* Ws = Xs + 128 * 68;
    float* Hs = Ws + 128 * 68;

    int tid = threadIdx.x;
    int row0 = blockIdx.x * 64;

    for (int idx = tid; idx < 64 * 32; idx += 256) {
        int r = idx >> 5, k4 = idx & 31;
        float4 v = *(const float4*)&Xin[(size_t)(row0 + r) * 128 + k4 * 4];
        Xs[(k4 * 4 + 0) * 68 + r] = v.x;
        Xs[(k4 * 4 + 1) * 68 + r] = v.y;
        Xs[(k4 * 4 + 2) * 68 + r] = v.z;
        Xs[(k4 * 4 + 3) * 68 + r] = v.w;
    }
    __syncthreads();

    int tx = tid & 15, ty = tid >> 4;
    float y[4][8] = {};

    #pragma unroll 1
    for (int hc = 0; hc < 4; hc++) {
        int h0 = hc * 64;
        for (int idx = tid; idx < 128 * 16; idx += 256) {
            int k = idx >> 4, c4 = idx & 15;
            *(float4*)&Ws[k * 68 + c4 * 4] = *(const float4*)&w1[(size_t)k * HHID + h0 + c4 * 4];
        }
        __syncthreads();

        float h[4][4] = {};
        #pragma unroll 4
        for (int k = 0; k < 128; k++) {
            float4 xv = *(const float4*)&Xs[k * 68 + ty * 4];
            float4 wv = *(const float4*)&Ws[k * 68 + tx * 4];
            FMA44(h, xv, wv)
        }

        float4 bv = *(const float4*)&b1[h0 + tx * 4];
        #pragma unroll
        for (int i = 0; i < 4; i++) {
            h[i][0] += bv.x; h[i][1] += bv.y; h[i][2] += bv.z; h[i][3] += bv.w;
        }

        #pragma unroll
        for (int j = 0; j < 4; j++) {
            float4 hv;
            hv.x = siluf(h[0][j]);
            hv.y = siluf(h[1][j]);
            hv.z = siluf(h[2][j]);
            hv.w = siluf(h[3][j]);
            *(float4*)&Hs[(tx * 4 + j) * 68 + ty * 4] = hv;
        }
        __syncthreads();

        for (int idx = tid; idx < 64 * 32; idx += 256) {
            int k = idx >> 5, c4 = idx & 31;
            *(float4*)&Ws[k * 132 + c4 * 4] = *(const float4*)&w2[(size_t)(h0 + k) * 128 + c4 * 4];
        }
        __syncthreads();

        #pragma unroll 2
        for (int k = 0; k < 64; k++) {
            float4 hv = *(const float4*)&Hs[k * 68 + ty * 4];
            float4 w0 = *(const float4*)&Ws[k * 132 + tx * 8];
            float4 w1v = *(const float4*)&Ws[k * 132 + tx * 8 + 4];
            FMAROW(y[0], hv.x)
            FMAROW(y[1], hv.y)
            FMAROW(y[2], hv.z)
            FMAROW(y[3], hv.w)
        }
        __syncthreads();
    }

    float b2r[8], gr[8], br[8];
    #pragma unroll
    for (int c = 0; c < 8; c++) {
        b2r[c] = b2[tx * 8 + c];
        gr[c] = gam[tx * 8 + c];
        br[c] = bet[tx * 8 + c];
    }
    #pragma unroll
    for (int i = 0; i < 4; i++) {
        #pragma unroll
        for (int c = 0; c < 8; c++) y[i][c] += b2r[c];

        float s1 = 0.f, s2 = 0.f;
        #pragma unroll
        for (int c = 0; c < 8; c++) { float v = y[i][c]; s1 += v; s2 += v * v; }
        #pragma unroll
        for (int m = 8; m >= 1; m >>= 1) {
            s1 += __shfl_xor_sync(0xffffffffu, s1, m);
            s2 += __shfl_xor_sync(0xffffffffu, s2, m);
        }
        float mu = s1 * (1.0f / 128.0f);
        float rs = rsqrtf(s2 * (1.0f / 128.0f) - mu * mu + LNEPS);

        int r = ty * 4 + i;
        float o[8];
        #pragma unroll
        for (int c = 0; c < 8; c++)
            o[c] = (y[i][c] - mu) * rs * gr[c] + br[c] + Xs[(tx * 8 + c) * 68 + r];
        size_t gout = (size_t)(row0 + r) * 128 + tx * 8;
        *(float4*)&out[gout]     = make_float4(o[0], o[1], o[2], o[3]);
        *(float4*)&out[gout + 4] = make_float4(o[4], o[5], o[6], o[7]);
    }
}

// ==================== HMMA MLP kernel (fp16, X resident in SMEM): MODE 0 = edge, 1 = node ====================
#define OFF_SIDX   0
#define OFF_DIDX   512
#define OFF_P1     1024
#define OFF_P2     3072
#define OFF_X32    5120       // 64KB fp32 X tile (attr or agg); MSG overlays in place
#define OFF_MSG    5120
#define OFF_A      70656      // 32KB fp16 A; later H_c1
#define OFF_W      103424     // 64KB fp16 W (both chunks)
#define OFF_H      168960     // 32KB fp16 H c0
#define SM_EDGE    201728

// stage both fp16 W chunks (64KB)
__device__ __forceinline__ void stage_w(uint32_t sb, const __half* g, int tid) {
    const char* p = (const char*)g;
    #pragma unroll
    for (int j = 0; j < 8; j++) {
        int i = tid + j * 512;
        CP_ASYNC16(sb + OFF_W + i * 16, p + i * 16);
    }
    CP_COMMIT();
}

// dd += A(128x128 fp16) @ Wchunk^T; single pass, pipelined fragments
__device__ __forceinline__ void gemm_phase(uint32_t sb, int lane, int wm, int wn,
                                           uint32_t baseA, uint32_t baseW, float (&dd)[2][4][4]) {
    uint32_t bf[2][4][2];
    uint32_t af[2][2][4];

    const int gq = lane >> 3;
    const int rowq0 = wn * 32 + ((gq >> 1) << 3) + (lane & 7);
    const int rowq1 = rowq0 + 16;
    const int rra0 = wm * 32 + (lane & 15);
    const int rra1 = rra0 + 16;
    const int bksel = gq & 1;
    const int aksel = lane >> 4;

    #define LD_B(buf, ksv)                                                                 \
    {                                                                                      \
        int chq = 2 * (ksv) + bksel;                                                       \
        uint32_t adq = sb + baseW + sw_off(rowq0, chq);                                    \
        uint32_t r4[4];                                                                    \
        LDSM_X4(r4, adq);                                                                  \
        bf[buf][0][0] = r4[0]; bf[buf][0][1] = r4[1]; bf[buf][1][0] = r4[2]; bf[buf][1][1] = r4[3]; \
        adq = sb + baseW + sw_off(rowq1, chq);                                             \
        LDSM_X4(r4, adq);                                                                  \
        bf[buf][2][0] = r4[0]; bf[buf][2][1] = r4[1]; bf[buf][3][0] = r4[2]; bf[buf][3][1] = r4[3]; \
    }
    #define LD_A(buf, ksv)                                                                 \
    {                                                                                      \
        int ch = 2 * (ksv) + aksel;                                                        \
        uint32_t ad = sb + baseA + sw_off(rra0, ch);                                       \
        LDSM_X4(af[buf][0], ad);                                                           \
        ad = sb + baseA + sw_off(rra1, ch);                                                \
        LDSM_X4(af[buf][1], ad);                                                           \
    }

    LD_B(0, 0)
    LD_A(0, 0)
    #pragma unroll
    for (int ks = 0; ks < 8; ks++) {
        const int cur = ks & 1, nxt = cur ^ 1;
        if (ks < 7) {
            LD_B(nxt, ks + 1)
            LD_A(nxt, ks + 1)
        }
        #pragma unroll
        for (int nt = 0; nt < 4; nt++) {
            MMA_FP16(dd[0][nt], af[cur][0], bf[cur][nt]);
            MMA_FP16(dd[1][nt], af[cur][1], bf[cur][nt]);
        }
    }
    #undef LD_B
    #undef LD_A
}

// epi1: MODE 0: D1 + gA[src] + gB[dst]; MODE 1: D1 + gA[row] (gA = g_R); SiLU -> fp16 H
template <int MODE>
__device__ __forceinline__ void epi1_phase(char* smc, const int* sidx_s, const int* didx_s,
    const float* gA, const float* gB, float (&d1)[2][4][4],
    int wm, int wn, int lane, int c, uint32_t dstOff, int row0)
{
    #pragma unroll
    for (int mt = 0; mt < 2; mt++) {
        int r1 = wm * 32 + mt * 16 + (lane >> 2);
        int r2 = r1 + 8;
        int si1, di1, si2, di2;
        if (MODE == 0) {
            si1 = sidx_s[r1]; di1 = didx_s[r1];
            si2 = sidx_s[r2]; di2 = didx_s[r2];
        } else {
            si1 = row0 + r1; if (si1 >= NNODE) si1 = NNODE - 1;
            si2 = row0 + r2; if (si2 >= NNODE) si2 = NNODE - 1;
            di1 = di2 = 0;
        }
        #pragma unroll
        for (int nt = 0; nt < 4; nt++) {
            int cpl = wn * 32 + nt * 8 + 2 * (lane & 3);
            int gc = c * 128 + cpl;
            float2 a1 = *(const float2*)(gA + (size_t)si1 * HHID + gc);
            float2 a2 = *(const float2*)(gA + (size_t)si2 * HHID + gc);
            float g10 = a1.x, g11 = a1.y, g20 = a2.x, g21 = a2.y;
            if (MODE == 0) {
                float2 bb1 = *(const float2*)(gB + (size_t)di1 * HHID + gc);
                float2 bb2 = *(const float2*)(gB + (size_t)di2 * HHID + gc);
                g10 += bb1.x; g11 += bb1.y; g20 += bb2.x; g21 += bb2.y;
            }
            __half h00 = __float2half_rn(siluf(d1[mt][nt][0] + g10));
            __half h01 = __float2half_rn(siluf(d1[mt][nt][1] + g11));
            __half h10 = __float2half_rn(siluf(d1[mt][nt][2] + g20));
            __half h11 = __float2half_rn(siluf(d1[mt][nt][3] + g21));
            uint32_t o1 = sw_off(r1, (cpl >> 3)) + (cpl & 7) * 2;
            uint32_t o2 = sw_off(r2, (cpl >> 3)) + (cpl & 7) * 2;
            *(uint32_t*)(smc + dstOff + o1) =
                (uint32_t)__half_as_ushort(h00) | ((uint32_t)__half_as_ushort(h01) << 16);
            *(uint32_t*)(smc + dstOff + o2) =
                (uint32_t)__half_as_ushort(h10) | ((uint32_t)__half_as_ushort(h11) << 16);
        }
    }
}

template <int MODE>
__global__ __launch_bounds__(512, 1) void k_mlp(
    const float* __restrict__ Ain, const void* __restrict__ ei,
    const float* __restrict__ gA, const float* __restrict__ gB,
    const __half* __restrict__ w1f, const __half* __restrict__ w2f,
    const float* __restrict__ b2, const float* __restrict__ gam, const float* __restrict__ bet,
    const float* __restrict__ resid, float* __restrict__ out, float* __restrict__ agg)
{
    extern __shared__ char smc[];
    const uint32_t sb = smem_to_u32(smc);
    const int tid = threadIdx.x;
    const int lane = tid & 31, wid = tid >> 5;
    const int wm = wid >> 2, wn = wid & 3;
    const int row0 = blockIdx.x * 128;

    // stage X tile (64KB fp32) -> group 0
    {
        #pragma unroll
        for (int j = 0; j < 8; j++) {
            int i = tid + j * 512;
            int r = i >> 5;
            int gr = row0 + r;
            if (MODE == 1 && gr >= NNODE) gr = NNODE - 1;
            CP_ASYNC16(sb + OFF_X32 + (uint32_t)i * 16,
                       (const char*)(Ain + (size_t)gr * 128) + (i & 31) * 16);
        }
        CP_COMMIT();
    }
    // stage both W1 chunks (64KB) -> group 1
    stage_w(sb, w1f, tid);

    int* sidx_s = (int*)(smc + OFF_SIDX);
    int* didx_s = (int*)(smc + OFF_DIDX);
    float* rc_s = (float*)(smc + OFF_SIDX);

    if (MODE == 0) {
        if (tid < 128) {
            sidx_s[tid] = eidx(ei, (long long)(row0 + tid));
            didx_s[tid] = eidx(ei, (long long)EEDGE + row0 + tid);
        }
    } else {
        if (tid < 128) {
            int rr = row0 + tid; if (rr >= NNODE) rr = NNODE - 1;
            int cval = g_cnt[rr];
            rc_s[tid] = 1.0f / (float)(cval > 1 ? cval : 1);
        }
    }
    CP_WAIT1();        // X staged (W1 may still be in flight)
    __syncthreads();   // X + rc/idx visible to all

    // convert X (smem) -> fp16 A tile
    for (int idx = tid; idx < 128 * 32; idx += 512) {
        int r = idx >> 5, c4 = idx & 31;
        float4 v = *(const float4*)(smc + OFF_X32 + (uint32_t)r * 512 + c4 * 16);
        if (MODE == 1) {
            float s = rc_s[r];
            v.x *= s; v.y *= s; v.z *= s; v.w *= s;
        }
        uint2 ph;
        ph.x = (uint32_t)__half_as_ushort(__float2half_rn(v.x)) |
               ((uint32_t)__half_as_ushort(__float2half_rn(v.y)) << 16);
        ph.y = (uint32_t)__half_as_ushort(__float2half_rn(v.z)) |
               ((uint32_t)__half_as_ushort(__float2half_rn(v.w)) << 16);
        uint32_t off = sw_off(r, c4 >> 1) + (c4 & 1) * 8;
        *(uint2*)(smc + OFF_A + off) = ph;
    }
    CP_WAIT0();        // W1 staged
    __syncthreads();   // A tile visible

    float d1[2][4][4];
    #pragma unroll
    for (int a = 0; a < 2; a++)
        #pragma unroll
        for (int b = 0; b < 4; b++)
            #pragma unroll
            for (int q = 0; q < 4; q++) d1[a][b][q] = 0.f;

    // G1 c0 + epi1 c0 (no barrier needed: epi writes H, G reads A/W)
    gemm_phase(sb, lane, wm, wn, OFF_A, OFF_W, d1);
    epi1_phase<MODE>(smc, sidx_s, didx_s, gA, gB, d1, wm, wn, lane, 0, OFF_H, row0);

    // G1 c1
    #pragma unroll
    for (int a = 0; a < 2; a++)
        #pragma unroll
        for (int b = 0; b < 4; b++)
            #pragma unroll
            for (int q = 0; q < 4; q++) d1[a][b][q] = 0.f;
    gemm_phase(sb, lane, wm, wn, OFF_A, OFF_W + 32768, d1);
    __syncthreads();          // all A reads + W1 reads done
    stage_w(sb, w2f, tid);    // W2 both chunks (overlaps epi1 c1)
    epi1_phase<MODE>(smc, sidx_s, didx_s, gA, gB, d1, wm, wn, lane, 1, OFF_A, row0);  // H_c1 -> A region
    CP_WAIT0();
    __syncthreads();

    // G2 c0 + c1 back-to-back (no barrier between)
    float d2[2][4][4];
    #pragma unroll
    for (int a = 0; a < 2; a++)
        #pragma unroll
        for (int b = 0; b < 4; b++)
            #pragma unroll
            for (int q = 0; q < 4; q++) d2[a][b][q] = 0.f;
    gemm_phase(sb, lane, wm, wn, OFF_H, OFF_W, d2);
    gemm_phase(sb, lane, wm, wn, OFF_A, OFF_W + 32768, d2);

    // ---- epi2: +b2, LayerNorm, residual, store (+ messages for MODE 0) ----
    float b2v[4][2], gmv[4][2], btv[4][2];
    #pragma unroll
    for (int nt = 0; nt < 4; nt++) {
        int col = wn * 32 + nt * 8 + 2 * (lane & 3);
        float2 t;
        t = *(const float2*)(b2 + col);  b2v[nt][0] = t.x; b2v[nt][1] = t.y;
        t = *(const float2*)(gam + col); gmv[nt][0] = t.x; gmv[nt][1] = t.y;
        t = *(const float2*)(bet + col); btv[nt][0] = t.x; btv[nt][1] = t.y;
    }
    float* p1 = (float*)(smc + OFF_P1);
    float* p2 = (float*)(smc + OFF_P2);

    #pragma unroll
    for (int mt = 0; mt < 2; mt++) {
        int r1 = wm * 32 + mt * 16 + (lane >> 2);
        int r2 = r1 + 8;
        float s1a = 0.f, s2a = 0.f, s1b = 0.f, s2b = 0.f;
        #pragma unroll
        for (int nt = 0; nt < 4; nt++) {
            float y0 = d2[mt][nt][0] + b2v[nt][0];
            float y1 = d2[mt][nt][1] + b2v[nt][1];
            float y2 = d2[mt][nt][2] + b2v[nt][0];
            float y3 = d2[mt][nt][3] + b2v[nt][1];
            d2[mt][nt][0] = y0; d2[mt][nt][1] = y1; d2[mt][nt][2] = y2; d2[mt][nt][3] = y3;
            s1a += y0 + y1; s2a += y0 * y0 + y1 * y1;
            s1b += y2 + y3; s2b += y2 * y2 + y3 * y3;
        }
        #pragma unroll
        for (int m = 1; m <= 2; m <<= 1) {
            s1a += __shfl_xor_sync(0xffffffffu, s1a, m);
            s2a += __shfl_xor_sync(0xffffffffu, s2a, m);
            s1b += __shfl_xor_sync(0xffffffffu, s1b, m);
            s2b += __shfl_xor_sync(0xffffffffu, s2b, m);
        }
        if ((lane & 3) == 0) {
            p1[r1 * 4 + wn] = s1a; p2[r1 * 4 + wn] = s2a;
            p1[r2 * 4 + wn] = s1b; p2[r2 * 4 + wn] = s2b;
        }
    }
    __syncthreads();   // p1/p2 ready; all G2 reads of A/H/W done before msg overwrites X32

    #pragma unroll
    for (int mt = 0; mt < 2; mt++) {
        int r1 = wm * 32 + mt * 16 + (lane >> 2);
        int r2 = r1 + 8;
        float4 q1 = *(float4*)&p1[r1 * 4];
        float4 v1 = *(float4*)&p2[r1 * 4];
        float4 q2 = *(float4*)&p1[r2 * 4];
        float4 v2 = *(float4*)&p2[r2 * 4];
        float mu1 = (q1.x + q1.y + q1.z + q1.w) * (1.0f / 128.0f);
        float mu2 = (q2.x + q2.y + q2.z + q2.w) * (1.0f / 128.0f);
        float rs1 = rsqrtf((v1.x + v1.y + v1.z + v1.w) * (1.0f / 128.0f) - mu1 * mu1 + LNEPS);
        float rs2 = rsqrtf((v2.x + v2.y + v2.z + v2.w) * (1.0f / 128.0f) - mu2 * mu2 + LNEPS);
        bool w1ok = (MODE == 0) || (row0 + r1 < NNODE);
        bool w2ok = (MODE == 0) || (row0 + r2 < NNODE);
        #pragma unroll
        for (int nt = 0; nt < 4; nt++) {
            int col = wn * 32 + nt * 8 + 2 * (lane & 3);
            float pa0 = (d2[mt][nt][0] - mu1) * rs1 * gmv[nt][0] + btv[nt][0];
            float pa1 = (d2[mt][nt][1] - mu1) * rs1 * gmv[nt][1] + btv[nt][1];
            float pb0 = (d2[mt][nt][2] - mu2) * rs2 * gmv[nt][0] + btv[nt][0];
            float pb1 = (d2[mt][nt][3] - mu2) * rs2 * gmv[nt][1] + btv[nt][1];
            if (MODE == 0) {
                // residual from SMEM X copy; then overwrite in place with message
                float* xp1 = (float*)(smc + OFF_X32 + (uint32_t)r1 * 512 + col * 4);
                float* xp2 = (float*)(smc + OFF_X32 + (uint32_t)r2 * 512 + col * 4);
                float2 x1 = *(float2*)xp1;
                float2 x2 = *(float2*)xp2;
                *(float2*)(out + (size_t)(row0 + r1) * 128 + col) = make_float2(pa0 + x1.x, pa1 + x1.y);
                *(float2*)(out + (size_t)(row0 + r2) * 128 + col) = make_float2(pb0 + x2.x, pb1 + x2.y);
                *(float2*)xp1 = make_float2(pa0, pa1);
                *(float2*)xp2 = make_float2(pb0, pb1);
            } else {
                if (w1ok) {
                    float2 x1 = *(const float2*)(resid + (size_t)(row0 + r1) * 128 + col);
                    *(float2*)(out + (size_t)(row0 + r1) * 128 + col) = make_float2(pa0 + x1.x, pa1 + x1.y);
                }
                if (w2ok) {
                    float2 x2 = *(const float2*)(resid + (size_t)(row0 + r2) * 128 + col);
                    *(float2*)(out + (size_t)(row0 + r2) * 128 + col) = make_float2(pb0 + x2.x, pb1 + x2.y);
                }
            }
        }
    }

    if (MODE == 0) {
        FENCE_ASYNC();
        __syncthreads();
        if (tid < 128) {
            float* gdst = agg + (size_t)didx_s[tid] * 128;
            bulk_reduce_add_f32(gdst, sb + OFF_MSG + (uint32_t)tid * 512, 512);
            asm volatile("cp.async.bulk.commit_group;" ::: "memory");
            asm volatile("cp.async.bulk.wait_group 0;" ::: "memory");
        }
    }
}

// ==================== launcher ====================
extern "C" void kernel_launch(void* const* d_in, const int* in_sizes, int n_in,
                              void* d_out, int out_size) {
    (void)in_sizes; (void)n_in; (void)out_size;
    const float* sender_x   = (const float*)d_in[0];
    const float* receiver_x = (const float*)d_in[1];
    const float* edge_attr  = (const float*)d_in[2];
    const void*  ei         = d_in[3];
    const float* ew1  = (const float*)d_in[4];
    const float* eb1  = (const float*)d_in[5];
    const float* ew2  = (const float*)d_in[6];
    const float* eb2  = (const float*)d_in[7];
    const float* eg   = (const float*)d_in[8];
    const float* ebt  = (const float*)d_in[9];
    const float* nw1  = (const float*)d_in[10];
    const float* nb1  = (const float*)d_in[11];
    const float* nw2  = (const float*)d_in[12];
    const float* nb2  = (const float*)d_in[13];
    const float* ng   = (const float*)d_in[14];
    const float* nbt  = (const float*)d_in[15];
    const float* sw1  = (const float*)d_in[16];
    const float* sb1  = (const float*)d_in[17];
    const float* sw2  = (const float*)d_in[18];
    const float* sb2  = (const float*)d_in[19];
    const float* sg   = (const float*)d_in[20];
    const float* sbt  = (const float*)d_in[21];

    float* out = (float*)d_out;
    float* out_send = out;
    float* out_recv = out + (size_t)NNODE * DD;
    float* out_edge = out + (size_t)2 * NNODE * DD;

    void *pA, *pB, *pR, *pAgg, *pw1f, *pw2f, *pn1f, *pn2f;
    cudaGetSymbolAddress(&pA, g_A);
    cudaGetSymbolAddress(&pB, g_B);
    cudaGetSymbolAddress(&pR, g_R);
    cudaGetSymbolAddress(&pAgg, g_agg);
    cudaGetSymbolAddress(&pw1f, g_w1f);
    cudaGetSymbolAddress(&pw2f, g_w2f);
    cudaGetSymbolAddress(&pn1f, g_nw1f);
    cudaGetSymbolAddress(&pn2f, g_nw2f);

    static cudaStream_t s2 = nullptr;
    static cudaEvent_t evS = nullptr, evP = nullptr, evJ = nullptr;
    if (s2 == nullptr) {
        cudaStreamCreateWithFlags(&s2, cudaStreamNonBlocking);
        cudaEventCreateWithFlags(&evS, cudaEventDisableTiming);
        cudaEventCreateWithFlags(&evP, cudaEventDisableTiming);
        cudaEventCreateWithFlags(&evJ, cudaEventDisableTiming);
    }

    const int SM_PRE = (128 * 68 + 128 * 68) * 4;
    const int SM_FU  = (128 * 68 + 128 * 68 + 64 * 68 + 64) * 4;
    cudaFuncSetAttribute(k_pregemmH, cudaFuncAttributeMaxDynamicSharedMemorySize, SM_PG);
    cudaFuncSetAttribute(k_pregemmR, cudaFuncAttributeMaxDynamicSharedMemorySize, SM_PRE);
    cudaFuncSetAttribute(k_sender,   cudaFuncAttributeMaxDynamicSharedMemorySize, SM_FU);
    cudaFuncSetAttribute(k_mlp<0>,   cudaFuncAttributeMaxDynamicSharedMemorySize, SM_EDGE);
    cudaFuncSetAttribute(k_mlp<1>,   cudaFuncAttributeMaxDynamicSharedMemorySize, SM_EDGE);

    // launch 1: weight prep + cnt zero + dtype detect (main)
    k_prepw<<<157, 256>>>(ew1, ew2, nw1, nw2, ei);
    cudaEventRecord(evS, 0);
    // launch 2: HMMA pregemm A/B on side stream
    cudaStreamWaitEvent(s2, evS, 0);
    k_pregemmH<<<dim3(NNODE / 64, 1, 2), 256, SM_PG, s2>>>(sender_x, receiver_x, eb1);
    // launch 3: zero agg + degree count (main)
    k_initcount<<<(NNODE * DD) / 256, 256>>>(ei);
    cudaEventRecord(evP, s2);
    cudaStreamWaitEvent(0, evP, 0);
    // launch 4 (ncu slot): edge kernel
    k_mlp<0><<<EEDGE / 128, 512, SM_EDGE>>>(
        edge_attr, ei, (const float*)pA, (const float*)pB,
        (const __half*)pw1f, (const __half*)pw2f,
        eb2, eg, ebt, edge_attr, out_edge, (float*)pAgg);
    // side stream overlaps edge: sender MLP + node receiver-half precompute
    k_sender<<<NNODE / 64, 256, SM_FU, s2>>>(sender_x, sw1, sb1, sw2, sb2, sg, sbt, out_send);
    k_pregemmR<<<dim3(NNODE / 64, 4), 256, SM_PRE, s2>>>(receiver_x, nw1, nb1);
    cudaEventRecord(evJ, s2);
    cudaStreamWaitEvent(0, evJ, 0);
    // node MLP (HMMA fp16): agg-dependent half, g_R gathered densely
    k_mlp<1><<<(NNODE + 127) / 128, 512, SM_EDGE>>>(
        (const float*)pAgg, nullptr, (const float*)pR, nullptr,
        (const __half*)pn1f, (const __half*)pn2f,
        nb2, ng, nbt, receiver_x, out_recv, nullptr);
}